// round 1
// baseline (speedup 1.0000x reference)
#include <cuda_runtime.h>
#include <math.h>

// ---------------- problem constants ----------------
#define BB    4
#define NSEQ  4096
#define NTOK  16384        // BB*NSEQ
#define DIM   1024
#define DH    256
#define SS    256
#define HIDN  32
#define DFF   4096

// ---------------- scratch (device globals: allowed) ----------------
__device__ float g_pr[NTOK * DH];
__device__ float g_pi[NTOK * DH];
__device__ float g_re[NTOK * SS];
__device__ float g_im[NTOK * SS];
__device__ float g_pinit[NTOK];
__device__ float g_gamma[BB];
__device__ float g_ctx[BB * DIM];
__device__ float g_ctxpart[BB * 32 * DIM];
__device__ float g_MrT[DH * SS];
__device__ float g_MiT[DH * SS];
__device__ float g_av[NTOK * DIM];
__device__ float g_ao[NTOK * DIM];
__device__ float g_h1[NTOK * DIM];
__device__ float g_ff1[NTOK * DFF];
__device__ float g_ff2[NTOK * DIM];

// ---------------- helpers ----------------
__device__ __forceinline__ float block_sum_256(float v) {
    __shared__ float sh[8];
    int lane = threadIdx.x & 31, w = threadIdx.x >> 5;
#pragma unroll
    for (int o = 16; o; o >>= 1) v += __shfl_xor_sync(0xffffffffu, v, o);
    if (lane == 0) sh[w] = v;
    __syncthreads();
    float r = (lane < 8) ? sh[lane] : 0.f;
    if (w == 0) {
#pragma unroll
        for (int o = 4; o; o >>= 1) r += __shfl_xor_sync(0xffffffffu, r, o);
        if (lane == 0) sh[0] = r;
    }
    __syncthreads();
    float out = sh[0];
    __syncthreads();
    return out;
}

__device__ __forceinline__ float gelu_exact(float x) {
    return 0.5f * x * (1.0f + erff(x * 0.7071067811865475f));
}

// ---------------- SGEMM: C = alpha*A@B (+bias) (+old C) (+gelu) ----------------
// A: MxK row-major, B: KxN row-major, C: MxN row-major.
// All of M,N divisible by 128; K divisible by 8 (true for every call here).
template <bool ACC, bool GELU>
__global__ __launch_bounds__(256) void sgemm_kernel(
    const float* __restrict__ A, const float* __restrict__ B,
    const float* __restrict__ bias, float* __restrict__ C,
    int M, int N, int K, float alpha)
{
    constexpr int BM = 128, BN = 128, BK = 8, TM = 8, TN = 8;
    __shared__ float As[BK][BM];
    __shared__ float Bs[BK][BN];

    const int tid = threadIdx.x;
    const int cRow = blockIdx.y, cCol = blockIdx.x;
    const float* Ab = A + (size_t)cRow * BM * K;
    const float* Bbase = B + cCol * BN;
    float* Cb = C + (size_t)cRow * BM * N + cCol * BN;

    const int aRow = tid >> 1;            // 0..127
    const int aCol = (tid & 1) * 4;       // 0 or 4
    const int bRow = tid >> 5;            // 0..7
    const int bCol = (tid & 31) * 4;      // 0..124

    const int tRow = (tid >> 4) * TM;
    const int tCol = (tid & 15) * TN;

    float acc[TM][TN] = {};
    float rA[TM], rB[TN];

    for (int k0 = 0; k0 < K; k0 += BK) {
        float4 a4 = *(const float4*)(Ab + (size_t)aRow * K + k0 + aCol);
        As[aCol + 0][aRow] = a4.x;
        As[aCol + 1][aRow] = a4.y;
        As[aCol + 2][aRow] = a4.z;
        As[aCol + 3][aRow] = a4.w;
        *(float4*)(&Bs[bRow][bCol]) = *(const float4*)(Bbase + (size_t)(k0 + bRow) * N + bCol);
        __syncthreads();
#pragma unroll
        for (int k = 0; k < BK; k++) {
#pragma unroll
            for (int i = 0; i < TM; i++) rA[i] = As[k][tRow + i];
#pragma unroll
            for (int j = 0; j < TN; j++) rB[j] = Bs[k][tCol + j];
#pragma unroll
            for (int i = 0; i < TM; i++)
#pragma unroll
                for (int j = 0; j < TN; j++)
                    acc[i][j] += rA[i] * rB[j];
        }
        __syncthreads();
    }

#pragma unroll
    for (int i = 0; i < TM; i++) {
#pragma unroll
        for (int j = 0; j < TN; j += 4) {
            float4 out;
            float* o = &out.x;
#pragma unroll
            for (int q = 0; q < 4; q++) {
                float v = alpha * acc[i][j + q];
                if (bias) v += bias[cCol * BN + tCol + j + q];
                if (ACC) v += Cb[(size_t)(tRow + i) * N + tCol + j + q];
                if (GELU) v = gelu_exact(v);
                o[q] = v;
            }
            *(float4*)(&Cb[(size_t)(tRow + i) * N + tCol + j]) = out;
        }
    }
}

// ---------------- psi row-normalize (row length DH for pr and pi jointly) ----------------
__global__ void psinorm_kernel(float* __restrict__ pr, float* __restrict__ pi) {
    size_t idx = (size_t)blockIdx.x * DH + threadIdx.x;
    float a = pr[idx], b = pi[idx];
    float tot = block_sum_256(a * a + b * b);
    float nrm = fmaxf(sqrtf(tot), 1e-12f);
    pr[idx] = a / nrm;
    pi[idx] = b / nrm;
}

// ---------------- memory normalize + transpose ----------------
__global__ void memnorm_kernel(const float* __restrict__ mr, const float* __restrict__ mi,
                               float* __restrict__ MrT, float* __restrict__ MiT) {
    int s = blockIdx.x;
    int d = threadIdx.x;
    float a = mr[s * DH + d], b = mi[s * DH + d];
    float tot = block_sum_256(a * a + b * b);
    float nrm = fmaxf(sqrtf(tot), 1e-12f);
    MrT[d * SS + s] = a / nrm;
    MiT[d * SS + s] = b / nrm;
}

// ---------------- gate: sigmoid(silu(LN(x@w1+b1))@w2 + b2) * scale ----------------
__global__ void gate_kernel(const float* __restrict__ x,
                            const float* __restrict__ w1, const float* __restrict__ b1,
                            const float* __restrict__ gain, const float* __restrict__ beta,
                            const float* __restrict__ w2, const float* __restrict__ b2,
                            float* __restrict__ out, float scale)
{
    int row = blockIdx.x;
    const float* xr = x + (size_t)row * DIM;
    __shared__ float part[8][HIDN + 1];
    int tid = threadIdx.x;          // 256
    int j = tid & 31;               // output column
    int t = tid >> 5;               // k-chunk (warp id)
    float s = 0.f;
    int k0 = t * (DIM / 8);
#pragma unroll 4
    for (int i = 0; i < DIM / 8; i++) {
        float xv = xr[k0 + i];                       // broadcast within warp
        s += xv * w1[(k0 + i) * HIDN + j];           // coalesced
    }
    part[t][j] = s;
    __syncthreads();
    if (tid < HIDN) {
        float v = 0.f;
#pragma unroll
        for (int q = 0; q < 8; q++) v += part[q][tid];
        v += b1[tid];
        float m = v;
#pragma unroll
        for (int o = 16; o; o >>= 1) m += __shfl_xor_sync(0xffffffffu, m, o);
        m *= (1.f / 32.f);
        float d = v - m;
        float var = d * d;
#pragma unroll
        for (int o = 16; o; o >>= 1) var += __shfl_xor_sync(0xffffffffu, var, o);
        var *= (1.f / 32.f);
        float tn = d / sqrtf(var + 1e-5f) * gain[tid] + beta[tid];
        float si = tn / (1.f + expf(-tn));           // silu
        float p = si * w2[tid];
#pragma unroll
        for (int o = 16; o; o >>= 1) p += __shfl_xor_sync(0xffffffffu, p, o);
        if (tid == 0) out[row] = scale / (1.f + expf(-(p + b2[0])));
    }
}

// ---------------- ctx = mean over sequence (two-pass, deterministic) ----------------
__global__ void ctx_partial_kernel(const float* __restrict__ h, float* __restrict__ part) {
    int d = blockIdx.x * 256 + threadIdx.x;     // DIM
    int b = blockIdx.y;
    int c = blockIdx.z;                          // 32 chunks of 128 rows
    const float* base = h + (((size_t)b * NSEQ + c * 128) * DIM) + d;
    float s = 0.f;
#pragma unroll 4
    for (int n = 0; n < 128; n++) s += base[(size_t)n * DIM];
    part[(size_t)(b * 32 + c) * DIM + d] = s;
}

__global__ void ctx_final_kernel(const float* __restrict__ part, float* __restrict__ ctx) {
    int i = blockIdx.x * 256 + threadIdx.x;     // BB*DIM
    int b = i >> 10, d = i & 1023;
#pragma unroll
    float s = 0.f;
    for (int c = 0; c < 32; c++) s += part[(size_t)(b * 32 + c) * DIM + d];
    ctx[i] = s * (1.f / (float)NSEQ);
}

// ---------------- attention weights: overlap -> raw -> normalized (in place over g_re) ----------------
__global__ void attn_kernel(float* __restrict__ re, const float* __restrict__ im,
                            const float* __restrict__ pinit, const float* __restrict__ gamma) {
    int row = blockIdx.x;
    int s = threadIdx.x;            // SS = 256
    int b = row >> 12;              // row / NSEQ
    float p = pinit[row] * (1.f - gamma[b]);
    size_t idx = (size_t)row * SS + s;
    float r = re[idx], i = im[idx];
    float raw = (1.f - p) * (r * r + i * i) + p * (1.f / (float)DH);
    float tot = block_sum_256(raw);
    re[idx] = raw / (tot + 1e-8f);
}

// ---------------- residual + LayerNorm: out = LN(a+b)*g + beta ----------------
__global__ void ln_add_kernel(const float* __restrict__ a, const float* __restrict__ bsrc,
                              const float* __restrict__ g, const float* __restrict__ beta,
                              float* __restrict__ out) {
    size_t off = (size_t)blockIdx.x * DIM;
    int tid = threadIdx.x;          // 256, 4 elems each
    float v[4];
    float s = 0.f;
#pragma unroll
    for (int q = 0; q < 4; q++) {
        int i = tid + q * 256;
        v[q] = a[off + i] + bsrc[off + i];
        s += v[q];
    }
    float mu = block_sum_256(s) * (1.f / (float)DIM);
    float s2 = 0.f;
#pragma unroll
    for (int q = 0; q < 4; q++) {
        float d = v[q] - mu;
        s2 += d * d;
    }
    float var = block_sum_256(s2) * (1.f / (float)DIM);
    float inv = 1.f / sqrtf(var + 1e-5f);
#pragma unroll
    for (int q = 0; q < 4; q++) {
        int i = tid + q * 256;
        out[off + i] = (v[q] - mu) * inv * g[i] + beta[i];
    }
}

// ---------------- launch ----------------
static inline float* sym(const void* s) {
    void* p = nullptr;
    cudaGetSymbolAddress(&p, s);
    return (float*)p;
}

extern "C" void kernel_launch(void* const* d_in, const int* in_sizes, int n_in,
                              void* d_out, int out_size) {
    const float* h     = (const float*)d_in[0];
    const float* Wr    = (const float*)d_in[1];
    const float* br    = (const float*)d_in[2];
    const float* Wi    = (const float*)d_in[3];
    const float* bi    = (const float*)d_in[4];
    const float* uw1   = (const float*)d_in[5];
    const float* ub1   = (const float*)d_in[6];
    const float* ug    = (const float*)d_in[7];
    const float* ubeta = (const float*)d_in[8];
    const float* uw2   = (const float*)d_in[9];
    const float* ub2   = (const float*)d_in[10];
    const float* gw1   = (const float*)d_in[11];
    const float* gb1   = (const float*)d_in[12];
    const float* gg    = (const float*)d_in[13];
    const float* gbeta = (const float*)d_in[14];
    const float* gw2   = (const float*)d_in[15];
    const float* gb2   = (const float*)d_in[16];
    const float* m_real= (const float*)d_in[17];
    const float* m_imag= (const float*)d_in[18];
    const float* values= (const float*)d_in[19];
    const float* ow    = (const float*)d_in[20];
    const float* ob    = (const float*)d_in[21];
    const float* n1g   = (const float*)d_in[22];
    const float* n1b   = (const float*)d_in[23];
    const float* n2g   = (const float*)d_in[24];
    const float* n2b   = (const float*)d_in[25];
    const float* fw1   = (const float*)d_in[26];
    const float* fb1   = (const float*)d_in[27];
    const float* fw2   = (const float*)d_in[28];
    const float* fb2   = (const float*)d_in[29];
    float* out = (float*)d_out;

    float* pr   = sym(g_pr);
    float* pi   = sym(g_pi);
    float* re   = sym(g_re);
    float* im   = sym(g_im);
    float* pinit= sym(g_pinit);
    float* gam  = sym(g_gamma);
    float* ctx  = sym(g_ctx);
    float* ctxp = sym(g_ctxpart);
    float* MrT  = sym(g_MrT);
    float* MiT  = sym(g_MiT);
    float* av   = sym(g_av);
    float* ao   = sym(g_ao);
    float* h1   = sym(g_h1);
    float* ff1  = sym(g_ff1);
    float* ff2  = sym(g_ff2);

    dim3 thr(256);

    // 1) complex projection: pr = h@Wr+br, pi = h@Wi+bi   (16384x1024x256)
    {
        dim3 grid(DH / 128, NTOK / 128);
        sgemm_kernel<false, false><<<grid, thr>>>(h, Wr, br, pr, NTOK, DH, DIM, 1.f);
        sgemm_kernel<false, false><<<grid, thr>>>(h, Wi, bi, pi, NTOK, DH, DIM, 1.f);
    }
    // 2) psi normalize
    psinorm_kernel<<<NTOK, DH>>>(pr, pi);
    // 3) uncertainty gate -> p_init (scale 0.95)
    gate_kernel<<<NTOK, 256>>>(h, uw1, ub1, ug, ubeta, uw2, ub2, pinit, 0.95f);
    // 4) ctx mean + gamma gate
    {
        dim3 gridp(DIM / 256, BB, 32);
        ctx_partial_kernel<<<gridp, thr>>>(h, ctxp);
        ctx_final_kernel<<<(BB * DIM) / 256, thr>>>(ctxp, ctx);
        gate_kernel<<<BB, 256>>>(ctx, gw1, gb1, gg, gbeta, gw2, gb2, gam, 1.0f);
    }
    // 5) memory normalize + transpose
    memnorm_kernel<<<SS, DH>>>(m_real, m_imag, MrT, MiT);
    // 6) re = pr@MrT + pi@MiT ; im = pr@MiT - pi@MrT   (16384x256x256 each)
    {
        dim3 grid(SS / 128, NTOK / 128);
        sgemm_kernel<false, false><<<grid, thr>>>(pr, MrT, nullptr, re, NTOK, SS, DH, 1.f);
        sgemm_kernel<true,  false><<<grid, thr>>>(pi, MiT, nullptr, re, NTOK, SS, DH, 1.f);
        sgemm_kernel<false, false><<<grid, thr>>>(pr, MiT, nullptr, im, NTOK, SS, DH, 1.f);
        sgemm_kernel<true,  false><<<grid, thr>>>(pi, MrT, nullptr, im, NTOK, SS, DH, -1.f);
    }
    // 7) attention weights (in place into re)
    attn_kernel<<<NTOK, SS>>>(re, im, pinit, gam);
    // 8) av = attn@values ; ao = av@ow + ob
    {
        dim3 grid1(DIM / 128, NTOK / 128);
        sgemm_kernel<false, false><<<grid1, thr>>>(re, values, nullptr, av, NTOK, DIM, SS, 1.f);
        sgemm_kernel<false, false><<<grid1, thr>>>(av, ow, ob, ao, NTOK, DIM, DIM, 1.f);
    }
    // 9) h1 = LN(h + ao)
    ln_add_kernel<<<NTOK, 256>>>(h, ao, n1g, n1b, h1);
    // 10) FFN: ff1 = gelu(h1@fw1+fb1) ; ff2 = ff1@fw2 + fb2
    {
        dim3 gridA(DFF / 128, NTOK / 128);
        sgemm_kernel<false, true><<<gridA, thr>>>(h1, fw1, fb1, ff1, NTOK, DFF, DIM, 1.f);
        dim3 gridB(DIM / 128, NTOK / 128);
        sgemm_kernel<false, false><<<gridB, thr>>>(ff1, fw2, fb2, ff2, NTOK, DIM, DFF, 1.f);
    }
    // 11) out = LN(h1 + ff2)
    ln_add_kernel<<<NTOK, 256>>>(h1, ff2, n2g, n2b, out);
}

// round 3
// speedup vs baseline: 3.5587x; 3.5587x over previous
#include <cuda_runtime.h>
#include <math.h>
#include <stdint.h>

// ---------------- problem constants ----------------
#define BB    4
#define NSEQ  4096
#define NTOK  16384        // BB*NSEQ
#define DIM   1024
#define DH    256
#define SS    256
#define HIDN  32
#define DFF   4096

// ---------------- scratch (device globals: allowed) ----------------
__device__ float g_h32[NTOK * DIM];       // rna(h)
__device__ float g_psi[NTOK * 512];       // [pr | pi] packed, normalized+rounded
__device__ float g_reim[NTOK * 512];      // [re | im] packed
__device__ float g_attn[NTOK * SS];
__device__ float g_t1[NTOK * HIDN];
__device__ float g_pinit[NTOK];
__device__ float g_gamma[BB];
__device__ float g_ctx[BB * DIM];
__device__ float g_ctxpart[BB * 32 * DIM];
__device__ float g_av[NTOK * DIM];
__device__ float g_ao[NTOK * DIM];
__device__ float g_h1[NTOK * DIM];
__device__ float g_h1r[NTOK * DIM];
__device__ float g_ff1[NTOK * DFF];
__device__ float g_ff2[NTOK * DIM];
// packed / transposed weights (B operands stored [N, K], K contiguous)
__device__ float g_WT[512 * DIM];         // rows 0-255 = Wr^T, 256-511 = Wi^T
__device__ float g_bc[512];               // [br | bi]
__device__ float g_Mpack[512 * 512];      // rows 0-255: [Mr|Mi], rows 256-511: [Mi|-Mr]
__device__ float g_uw1T[HIDN * DIM];
__device__ float g_valT[DIM * SS];
__device__ float g_owT[DIM * DIM];
__device__ float g_fw1T[DFF * DIM];
__device__ float g_fw2T[DIM * DFF];

// ---------------- small helpers ----------------
__device__ __forceinline__ float rna_tf32(float x) {
    uint32_t u;
    asm("cvt.rna.tf32.f32 %0, %1;" : "=r"(u) : "f"(x));
    return __uint_as_float(u);
}

__device__ __forceinline__ float gelu_exact(float x) {
    return 0.5f * x * (1.0f + erff(x * 0.7071067811865475f));
}

__device__ __forceinline__ float block_sum_256(float v) {
    __shared__ float sh[8];
    int lane = threadIdx.x & 31, w = threadIdx.x >> 5;
#pragma unroll
    for (int o = 16; o; o >>= 1) v += __shfl_xor_sync(0xffffffffu, v, o);
    if (lane == 0) sh[w] = v;
    __syncthreads();
    float r = (lane < 8) ? sh[lane] : 0.f;
    if (w == 0) {
#pragma unroll
        for (int o = 4; o; o >>= 1) r += __shfl_xor_sync(0xffffffffu, r, o);
        if (lane == 0) sh[0] = r;
    }
    __syncthreads();
    float out = sh[0];
    __syncthreads();
    return out;
}

__device__ __forceinline__ uint32_t smem_u32(const void* p) {
    return (uint32_t)__cvta_generic_to_shared(p);
}
__device__ __forceinline__ void cp16(uint32_t dst, const void* src) {
    asm volatile("cp.async.cg.shared.global [%0], [%1], 16;" :: "r"(dst), "l"(src));
}
__device__ __forceinline__ void cp_commit() { asm volatile("cp.async.commit_group;"); }
template <int N>
__device__ __forceinline__ void cp_wait() { asm volatile("cp.async.wait_group %0;" :: "n"(N)); }

// ---------------- tf32 mma.sync GEMM ----------------
// C[128*gy + :, BN*gx + :] = A @ B^T (+bias) (+gelu) (+rna)
// A: [M, K] row-major fp32 (tf32-rounded values)
// B: [Nrows, K] row-major fp32 (tf32-rounded values)
// Block tile 128 x BN, 256 threads, BK = 32, 3-stage cp.async pipeline.
// SMEM rows padded to stride 36 floats -> conflict-free fragment loads.

template <int BN>
__device__ __forceinline__ void load_slab(char* smem, int stage,
                                          const float* gA, const float* gB,
                                          int k0, int K, int tid) {
    constexpr int LD = 36;
    constexpr int STAGE_BYTES = (128 + BN) * LD * 4;
    uint32_t base = smem_u32(smem) + stage * STAGE_BYTES;
#pragma unroll
    for (int i = 0; i < 4; i++) {                 // A: 128 rows x 32 floats
        int idx = tid + i * 256;
        int row = idx >> 3, seg = idx & 7;
        cp16(base + (uint32_t)(row * LD + seg * 4) * 4,
             gA + (size_t)row * K + k0 + seg * 4);
    }
    uint32_t bbase = base + 128 * LD * 4;
#pragma unroll
    for (int i = 0; i < BN / 32; i++) {           // B: BN rows x 32 floats
        int idx = tid + i * 256;
        int row = idx >> 3, seg = idx & 7;
        cp16(bbase + (uint32_t)(row * LD + seg * 4) * 4,
             gB + (size_t)row * K + k0 + seg * 4);
    }
}

template <int BN, bool GELU, bool RND>
__global__ __launch_bounds__(256) void tgemm(
    const float* __restrict__ A, const float* __restrict__ B,
    const float* __restrict__ bias, float* __restrict__ C,
    int K, int Ntot)
{
    extern __shared__ char smem[];
    constexpr int LD = 36;
    constexpr int STAGE_BYTES = (128 + BN) * LD * 4;
    constexpr int WN = BN / 32;        // warps across n (4 or 1)
    constexpr int WM = 8 / WN;         // warps across m (2 or 8)
    constexpr int MI = (128 / WM) / 16; // m16 atoms per warp (4 or 1)

    const int tid = threadIdx.x, wid = tid >> 5, lane = tid & 31;
    const int warp_m = (wid % WM) * (128 / WM);
    const int warp_n = (wid / WM) * 32;
    const int g = lane >> 2;           // group id
    const int tg = lane & 3;           // thread in group

    const float* gA = A + (size_t)blockIdx.y * 128 * K;
    const float* gB = B + (size_t)blockIdx.x * BN * K;
    const int NS = K >> 5;

    float acc[MI][4][4] = {};

    load_slab<BN>(smem, 0, gA, gB, 0, K, tid);  cp_commit();
    load_slab<BN>(smem, 1, gA, gB, 32, K, tid); cp_commit();

    for (int ks = 0; ks < NS; ks++) {
        if (ks + 2 < NS) {
            load_slab<BN>(smem, (ks + 2) % 3, gA, gB, (ks + 2) * 32, K, tid);
            cp_commit();
        }
        int rem = NS - 1 - ks;
        if (rem >= 2) cp_wait<2>();
        else if (rem == 1) cp_wait<1>();
        else cp_wait<0>();
        __syncthreads();

        const float* As = (const float*)(smem + (size_t)(ks % 3) * STAGE_BYTES);
        const float* Bs = As + 128 * LD;

#pragma unroll
        for (int kk = 0; kk < 4; kk++) {
            int k0 = kk * 8 + tg;
            uint32_t a[MI][4], b[4][2];
#pragma unroll
            for (int mi = 0; mi < MI; mi++) {
                int r = warp_m + mi * 16 + g;
                a[mi][0] = __float_as_uint(As[r * LD + k0]);
                a[mi][1] = __float_as_uint(As[(r + 8) * LD + k0]);
                a[mi][2] = __float_as_uint(As[r * LD + k0 + 4]);
                a[mi][3] = __float_as_uint(As[(r + 8) * LD + k0 + 4]);
            }
#pragma unroll
            for (int ni = 0; ni < 4; ni++) {
                int rn = warp_n + ni * 8 + g;
                b[ni][0] = __float_as_uint(Bs[rn * LD + k0]);
                b[ni][1] = __float_as_uint(Bs[rn * LD + k0 + 4]);
            }
#pragma unroll
            for (int mi = 0; mi < MI; mi++)
#pragma unroll
                for (int ni = 0; ni < 4; ni++)
                    asm volatile(
                        "mma.sync.aligned.m16n8k8.row.col.f32.tf32.tf32.f32 "
                        "{%0,%1,%2,%3}, {%4,%5,%6,%7}, {%8,%9}, {%0,%1,%2,%3};"
                        : "+f"(acc[mi][ni][0]), "+f"(acc[mi][ni][1]),
                          "+f"(acc[mi][ni][2]), "+f"(acc[mi][ni][3])
                        : "r"(a[mi][0]), "r"(a[mi][1]), "r"(a[mi][2]), "r"(a[mi][3]),
                          "r"(b[ni][0]), "r"(b[ni][1]));
        }
        __syncthreads();
    }

    // epilogue
#pragma unroll
    for (int mi = 0; mi < MI; mi++) {
        int r0 = blockIdx.y * 128 + warp_m + mi * 16 + g;
#pragma unroll
        for (int ni = 0; ni < 4; ni++) {
            int col = blockIdx.x * BN + warp_n + ni * 8 + 2 * tg;
            float bx = 0.f, by = 0.f;
            if (bias) { bx = bias[col]; by = bias[col + 1]; }
#pragma unroll
            for (int half = 0; half < 2; half++) {
                int row = r0 + half * 8;
                float vx = acc[mi][ni][half * 2 + 0] + bx;
                float vy = acc[mi][ni][half * 2 + 1] + by;
                if (GELU) { vx = gelu_exact(vx); vy = gelu_exact(vy); }
                if (RND)  { vx = rna_tf32(vx);   vy = rna_tf32(vy); }
                float2 v = make_float2(vx, vy);
                *(float2*)(C + (size_t)row * Ntot + col) = v;
            }
        }
    }
}

// ---------------- elementwise / small kernels ----------------
__global__ void round_copy_kernel(const float* __restrict__ in, float* __restrict__ out) {
    int i = blockIdx.x * 256 + threadIdx.x;
    float4 v = ((const float4*)in)[i];
    v.x = rna_tf32(v.x); v.y = rna_tf32(v.y);
    v.z = rna_tf32(v.z); v.w = rna_tf32(v.w);
    ((float4*)out)[i] = v;
}

// transpose with rna rounding: out[C, R] = rna(in[R, C]^T)
__global__ void transpose_rna_kernel(const float* __restrict__ in, float* __restrict__ out,
                                     int R, int C) {
    __shared__ float t[32][33];
    int c0 = blockIdx.x * 32, r0 = blockIdx.y * 32;
    int x = threadIdx.x, y = threadIdx.y;  // 32 x 8
#pragma unroll
    for (int dy = 0; dy < 32; dy += 8)
        t[y + dy][x] = in[(size_t)(r0 + y + dy) * C + c0 + x];
    __syncthreads();
#pragma unroll
    for (int dy = 0; dy < 32; dy += 8)
        out[(size_t)(c0 + y + dy) * R + r0 + x] = rna_tf32(t[x][y + dy]);
}

__global__ void pack_bias_kernel(const float* __restrict__ br, const float* __restrict__ bi,
                                 float* __restrict__ bc) {
    int i = threadIdx.x;   // 256
    bc[i] = br[i];
    bc[256 + i] = bi[i];
}

// normalize packed psi rows of 512 ([pr|pi]); round to tf32
__global__ void psinorm_kernel(float* __restrict__ psi) {
    size_t base = (size_t)blockIdx.x * 512;
    int tid = threadIdx.x;   // 256
    float a = psi[base + tid], b = psi[base + 256 + tid];
    float tot = block_sum_256(a * a + b * b);
    float nrm = fmaxf(sqrtf(tot), 1e-12f);
    psi[base + tid] = rna_tf32(a / nrm);
    psi[base + 256 + tid] = rna_tf32(b / nrm);
}

// memory normalize -> packed B operand [512 rows x 512 K]
// rows 0..255   (for re):  [ Mr_s | Mi_s ]
// rows 256..511 (for im):  [ Mi_s | -Mr_s ]
__global__ void memnorm_kernel(const float* __restrict__ mr, const float* __restrict__ mi,
                               float* __restrict__ Mp) {
    int s = blockIdx.x;    // SS
    int d = threadIdx.x;   // DH = 256
    float a = mr[s * DH + d], b = mi[s * DH + d];
    float tot = block_sum_256(a * a + b * b);
    float nrm = fmaxf(sqrtf(tot), 1e-12f);
    float ra = rna_tf32(a / nrm), rb = rna_tf32(b / nrm);
    Mp[(size_t)s * 512 + d] = ra;
    Mp[(size_t)s * 512 + 256 + d] = rb;
    Mp[(size_t)(256 + s) * 512 + d] = rb;
    Mp[(size_t)(256 + s) * 512 + 256 + d] = -ra;
}

// gamma gate (BB=4 rows): fully fused
__global__ void gate_kernel(const float* __restrict__ x,
                            const float* __restrict__ w1, const float* __restrict__ b1,
                            const float* __restrict__ gain, const float* __restrict__ beta,
                            const float* __restrict__ w2, const float* __restrict__ b2,
                            float* __restrict__ out, float scale)
{
    int row = blockIdx.x;
    const float* xr = x + (size_t)row * DIM;
    __shared__ float part[8][HIDN + 1];
    int tid = threadIdx.x;
    int j = tid & 31;
    int t = tid >> 5;
    float s = 0.f;
    int k0 = t * (DIM / 8);
#pragma unroll 4
    for (int i = 0; i < DIM / 8; i++) {
        float xv = xr[k0 + i];
        s += xv * w1[(k0 + i) * HIDN + j];
    }
    part[t][j] = s;
    __syncthreads();
    if (tid < HIDN) {
        float v = 0.f;
#pragma unroll
        for (int q = 0; q < 8; q++) v += part[q][tid];
        v += b1[tid];
        float m = v;
#pragma unroll
        for (int o = 16; o; o >>= 1) m += __shfl_xor_sync(0xffffffffu, m, o);
        m *= (1.f / 32.f);
        float d = v - m;
        float var = d * d;
#pragma unroll
        for (int o = 16; o; o >>= 1) var += __shfl_xor_sync(0xffffffffu, var, o);
        var *= (1.f / 32.f);
        float tn = d / sqrtf(var + 1e-5f) * gain[tid] + beta[tid];
        float si = tn / (1.f + expf(-tn));
        float p = si * w2[tid];
#pragma unroll
        for (int o = 16; o; o >>= 1) p += __shfl_xor_sync(0xffffffffu, p, o);
        if (tid == 0) out[row] = scale / (1.f + expf(-(p + b2[0])));
    }
}

// finish uncertainty gate from t1 = h@uw1 + ub1
__global__ void gate_finish_kernel(const float* __restrict__ t1,
                                   const float* __restrict__ gain, const float* __restrict__ beta,
                                   const float* __restrict__ w2, const float* __restrict__ b2,
                                   float* __restrict__ out, float scale)
{
    int row = blockIdx.x * 8 + (threadIdx.x >> 5);
    int j = threadIdx.x & 31;
    float v = t1[row * HIDN + j];
    float m = v;
#pragma unroll
    for (int o = 16; o; o >>= 1) m += __shfl_xor_sync(0xffffffffu, m, o);
    m *= (1.f / 32.f);
    float d = v - m;
    float var = d * d;
#pragma unroll
    for (int o = 16; o; o >>= 1) var += __shfl_xor_sync(0xffffffffu, var, o);
    var *= (1.f / 32.f);
    float tn = d / sqrtf(var + 1e-5f) * gain[j] + beta[j];
    float si = tn / (1.f + expf(-tn));
    float p = si * w2[j];
#pragma unroll
    for (int o = 16; o; o >>= 1) p += __shfl_xor_sync(0xffffffffu, p, o);
    if (j == 0) out[row] = scale / (1.f + expf(-(p + b2[0])));
}

__global__ void ctx_partial_kernel(const float* __restrict__ h, float* __restrict__ part) {
    int d = blockIdx.x * 256 + threadIdx.x;
    int b = blockIdx.y;
    int c = blockIdx.z;
    const float* base = h + (((size_t)b * NSEQ + c * 128) * DIM) + d;
    float s = 0.f;
#pragma unroll 4
    for (int n = 0; n < 128; n++) s += base[(size_t)n * DIM];
    part[(size_t)(b * 32 + c) * DIM + d] = s;
}

__global__ void ctx_final_kernel(const float* __restrict__ part, float* __restrict__ ctx) {
    int i = blockIdx.x * 256 + threadIdx.x;
    int b = i >> 10, d = i & 1023;
    float s = 0.f;
#pragma unroll
    for (int c = 0; c < 32; c++) s += part[(size_t)(b * 32 + c) * DIM + d];
    ctx[i] = s * (1.f / (float)NSEQ);
}

// attention weights from packed reim
__global__ void attn_kernel(const float* __restrict__ reim, float* __restrict__ attn,
                            const float* __restrict__ pinit, const float* __restrict__ gamma) {
    int row = blockIdx.x;
    int s = threadIdx.x;   // SS
    int b = row >> 12;
    float p = pinit[row] * (1.f - gamma[b]);
    size_t base = (size_t)row * 512;
    float r = reim[base + s], i = reim[base + 256 + s];
    float raw = (1.f - p) * (r * r + i * i) + p * (1.f / (float)DH);
    float tot = block_sum_256(raw);
    attn[(size_t)row * SS + s] = rna_tf32(raw / (tot + 1e-8f));
}

template <bool RC>
__global__ void ln_add_kernel(const float* __restrict__ a, const float* __restrict__ bsrc,
                              const float* __restrict__ g, const float* __restrict__ beta,
                              float* __restrict__ out, float* __restrict__ outr) {
    size_t off = (size_t)blockIdx.x * DIM;
    int tid = threadIdx.x;
    float v[4];
    float s = 0.f;
#pragma unroll
    for (int q = 0; q < 4; q++) {
        int i = tid + q * 256;
        v[q] = a[off + i] + bsrc[off + i];
        s += v[q];
    }
    float mu = block_sum_256(s) * (1.f / (float)DIM);
    float s2 = 0.f;
#pragma unroll
    for (int q = 0; q < 4; q++) {
        float d = v[q] - mu;
        s2 += d * d;
    }
    float var = block_sum_256(s2) * (1.f / (float)DIM);
    float inv = 1.f / sqrtf(var + 1e-5f);
#pragma unroll
    for (int q = 0; q < 4; q++) {
        int i = tid + q * 256;
        float o = (v[q] - mu) * inv * g[i] + beta[i];
        out[off + i] = o;
        if (RC) outr[off + i] = rna_tf32(o);
    }
}

// ---------------- launch ----------------
static inline float* sym(const void* s) {
    void* p = nullptr;
    cudaGetSymbolAddress(&p, s);
    return (float*)p;
}

extern "C" void kernel_launch(void* const* d_in, const int* in_sizes, int n_in,
                              void* d_out, int out_size) {
    const float* h     = (const float*)d_in[0];
    const float* Wr    = (const float*)d_in[1];
    const float* br    = (const float*)d_in[2];
    const float* Wi    = (const float*)d_in[3];
    const float* bi    = (const float*)d_in[4];
    const float* uw1   = (const float*)d_in[5];
    const float* ub1   = (const float*)d_in[6];
    const float* ug    = (const float*)d_in[7];
    const float* ubeta = (const float*)d_in[8];
    const float* uw2   = (const float*)d_in[9];
    const float* ub2   = (const float*)d_in[10];
    const float* gw1   = (const float*)d_in[11];
    const float* gb1   = (const float*)d_in[12];
    const float* gg    = (const float*)d_in[13];
    const float* gbeta = (const float*)d_in[14];
    const float* gw2   = (const float*)d_in[15];
    const float* gb2   = (const float*)d_in[16];
    const float* m_real= (const float*)d_in[17];
    const float* m_imag= (const float*)d_in[18];
    const float* values= (const float*)d_in[19];
    const float* ow    = (const float*)d_in[20];
    const float* ob    = (const float*)d_in[21];
    const float* n1g   = (const float*)d_in[22];
    const float* n1b   = (const float*)d_in[23];
    const float* n2g   = (const float*)d_in[24];
    const float* n2b   = (const float*)d_in[25];
    const float* fw1   = (const float*)d_in[26];
    const float* fb1   = (const float*)d_in[27];
    const float* fw2   = (const float*)d_in[28];
    const float* fb2   = (const float*)d_in[29];
    float* out = (float*)d_out;

    float* h32  = sym(g_h32);
    float* psi  = sym(g_psi);
    float* reim = sym(g_reim);
    float* attn = sym(g_attn);
    float* t1   = sym(g_t1);
    float* pinit= sym(g_pinit);
    float* gam  = sym(g_gamma);
    float* ctx  = sym(g_ctx);
    float* ctxp = sym(g_ctxpart);
    float* av   = sym(g_av);
    float* ao   = sym(g_ao);
    float* h1   = sym(g_h1);
    float* h1r  = sym(g_h1r);
    float* ff1  = sym(g_ff1);
    float* ff2  = sym(g_ff2);
    float* WT   = sym(g_WT);
    float* bc   = sym(g_bc);
    float* Mp   = sym(g_Mpack);
    float* uw1T = sym(g_uw1T);
    float* valT = sym(g_valT);
    float* owT  = sym(g_owT);
    float* fw1T = sym(g_fw1T);
    float* fw2T = sym(g_fw2T);

    const int sm128 = (128 + 128) * 36 * 4 * 3;   // 110592
    const int sm32  = (128 + 32) * 36 * 4 * 3;    // 69120
    cudaFuncSetAttribute(tgemm<128, false, false>, cudaFuncAttributeMaxDynamicSharedMemorySize, sm128);
    cudaFuncSetAttribute(tgemm<128, false, true >, cudaFuncAttributeMaxDynamicSharedMemorySize, sm128);
    cudaFuncSetAttribute(tgemm<128, true,  true >, cudaFuncAttributeMaxDynamicSharedMemorySize, sm128);
    cudaFuncSetAttribute(tgemm<32,  false, false>, cudaFuncAttributeMaxDynamicSharedMemorySize, sm32);

    dim3 thr(256);
    dim3 t328(32, 8);

    // 0) rounded copy of h
    round_copy_kernel<<<NTOK * DIM / 1024, thr>>>(h, h32);

    // 1) weight transposes (+rna) into [N, K] layouts
    transpose_rna_kernel<<<dim3(DH / 32, DIM / 32),  t328>>>(Wr, WT, DIM, DH);
    transpose_rna_kernel<<<dim3(DH / 32, DIM / 32),  t328>>>(Wi, WT + 256 * DIM, DIM, DH);
    pack_bias_kernel<<<1, 256>>>(br, bi, bc);
    transpose_rna_kernel<<<dim3(HIDN / 32, DIM / 32),t328>>>(uw1,    uw1T, DIM, HIDN);
    transpose_rna_kernel<<<dim3(DIM / 32, SS / 32),  t328>>>(values, valT, SS,  DIM);
    transpose_rna_kernel<<<dim3(DIM / 32, DIM / 32), t328>>>(ow,     owT,  DIM, DIM);
    transpose_rna_kernel<<<dim3(DFF / 32, DIM / 32), t328>>>(fw1,    fw1T, DIM, DFF);
    transpose_rna_kernel<<<dim3(DIM / 32, DFF / 32), t328>>>(fw2,    fw2T, DFF, DIM);

    // 2) memory normalize -> packed B operand
    memnorm_kernel<<<SS, DH>>>(m_real, m_imag, Mp);

    // 3) psi = h @ [Wr|Wi] + [br|bi]   (16384 x 512 x 1024), then normalize
    tgemm<128, false, false><<<dim3(4, 128), thr, sm128>>>(h32, WT, bc, psi, DIM, 512);
    psinorm_kernel<<<NTOK, 256>>>(psi);

    // 4) uncertainty gate
    tgemm<32, false, false><<<dim3(1, 128), thr, sm32>>>(h32, uw1T, ub1, t1, DIM, HIDN);
    gate_finish_kernel<<<NTOK / 8, 256>>>(t1, ug, ubeta, uw2, ub2, pinit, 0.95f);

    // 5) ctx mean + gamma gate
    ctx_partial_kernel<<<dim3(DIM / 256, BB, 32), thr>>>(h, ctxp);
    ctx_final_kernel<<<(BB * DIM) / 256, thr>>>(ctxp, ctx);
    gate_kernel<<<BB, 256>>>(ctx, gw1, gb1, gg, gbeta, gw2, gb2, gam, 1.0f);

    // 6) reim = psi @ Mpack^T   (16384 x 512 x 512)
    tgemm<128, false, false><<<dim3(4, 128), thr, sm128>>>(psi, Mp, nullptr, reim, 512, 512);

    // 7) attention weights
    attn_kernel<<<NTOK, SS>>>(reim, attn, pinit, gam);

    // 8) av = attn @ values (rounded) ; ao = av @ ow + ob
    tgemm<128, false, true ><<<dim3(8, 128), thr, sm128>>>(attn, valT, nullptr, av, SS, DIM);
    tgemm<128, false, false><<<dim3(8, 128), thr, sm128>>>(av, owT, ob, ao, DIM, DIM);

    // 9) h1 = LN(h + ao), plus rounded copy
    ln_add_kernel<true><<<NTOK, 256>>>(h, ao, n1g, n1b, h1, h1r);

    // 10) FFN
    tgemm<128, true,  true ><<<dim3(32, 128), thr, sm128>>>(h1r, fw1T, fb1, ff1, DIM, DFF);
    tgemm<128, false, false><<<dim3(8, 128), thr, sm128>>>(ff1, fw2T, fb2, ff2, DFF, DIM);

    // 11) out = LN(h1 + ff2)
    ln_add_kernel<false><<<NTOK, 256>>>(h1, ff2, n2g, n2b, out, nullptr);
}

// round 4
// speedup vs baseline: 3.5888x; 1.0084x over previous
#include <cuda_runtime.h>
#include <math.h>
#include <stdint.h>

// ---------------- problem constants ----------------
#define BB    4
#define NSEQ  4096
#define NTOK  16384        // BB*NSEQ
#define DIM   1024
#define DH    256
#define SS    256
#define HIDN  32
#define DFF   4096

// ---------------- scratch (device globals: allowed) ----------------
__device__ float g_h32[NTOK * DIM];       // rna(h)
__device__ float g_psi[NTOK * 512];       // [pr | pi] packed, normalized+rounded
__device__ float g_reim[NTOK * 512];      // [re | im] packed
__device__ float g_attn[NTOK * SS];
__device__ float g_t1[NTOK * HIDN];
__device__ float g_pinit[NTOK];
__device__ float g_gamma[BB];
__device__ float g_ctx[BB * DIM];
__device__ float g_ctxpart[BB * 32 * DIM];
__device__ float g_ao[NTOK * DIM];
__device__ float g_h1[NTOK * DIM];
__device__ float g_h1r[NTOK * DIM];
__device__ float g_ff1[NTOK * DFF];
__device__ float g_ff2[NTOK * DIM];
// packed / transposed weights (B operands stored [N, K], K contiguous)
__device__ float g_WT[512 * DIM];         // rows 0-255 = Wr^T, 256-511 = Wi^T
__device__ float g_bc[512];               // [br | bi]
__device__ float g_Mpack[512 * 512];      // rows 0-255: [Mr|Mi], rows 256-511: [Mi|-Mr]
__device__ float g_uw1T[HIDN * DIM];
__device__ float g_val32[SS * DIM];       // rna(values)
__device__ float g_owT[DIM * DIM];
__device__ float g_VOT[DIM * SS];         // (values @ ow)^T, rounded
__device__ float g_fw1T[DFF * DIM];
__device__ float g_fw2T[DIM * DFF];

// ---------------- small helpers ----------------
__device__ __forceinline__ float rna_tf32(float x) {
    uint32_t u;
    asm("cvt.rna.tf32.f32 %0, %1;" : "=r"(u) : "f"(x));
    return __uint_as_float(u);
}

__device__ __forceinline__ float gelu_exact(float x) {
    return 0.5f * x * (1.0f + erff(x * 0.7071067811865475f));
}

__device__ __forceinline__ float block_sum_256(float v) {
    __shared__ float sh[8];
    int lane = threadIdx.x & 31, w = threadIdx.x >> 5;
#pragma unroll
    for (int o = 16; o; o >>= 1) v += __shfl_xor_sync(0xffffffffu, v, o);
    if (lane == 0) sh[w] = v;
    __syncthreads();
    float r = (lane < 8) ? sh[lane] : 0.f;
    if (w == 0) {
#pragma unroll
        for (int o = 4; o; o >>= 1) r += __shfl_xor_sync(0xffffffffu, r, o);
        if (lane == 0) sh[0] = r;
    }
    __syncthreads();
    float out = sh[0];
    __syncthreads();
    return out;
}

__device__ __forceinline__ uint32_t smem_u32(const void* p) {
    return (uint32_t)__cvta_generic_to_shared(p);
}
__device__ __forceinline__ void cp16(uint32_t dst, const void* src) {
    asm volatile("cp.async.cg.shared.global [%0], [%1], 16;" :: "r"(dst), "l"(src));
}
__device__ __forceinline__ void cp_commit() { asm volatile("cp.async.commit_group;"); }
template <int N>
__device__ __forceinline__ void cp_wait() { asm volatile("cp.async.wait_group %0;" :: "n"(N)); }

#define MMA_TF32(d, a0, a1, a2, a3, b0, b1) \
    asm volatile( \
        "mma.sync.aligned.m16n8k8.row.col.f32.tf32.tf32.f32 " \
        "{%0,%1,%2,%3}, {%4,%5,%6,%7}, {%8,%9}, {%0,%1,%2,%3};" \
        : "+f"((d)[0]), "+f"((d)[1]), "+f"((d)[2]), "+f"((d)[3]) \
        : "r"(a0), "r"(a1), "r"(a2), "r"(a3), "r"(b0), "r"(b1))

// ============================================================
// BIG GEMM: 128 x 256 CTA tile, 8 warps (2 x 4), warp tile 64 x 64
// C = A @ B^T (+bias) (+gelu) (+rna);  A:[M,K], B:[N,K] row-major (tf32 vals)
// BK = 32, 3-stage cp.async pipeline, LD = 36 floats (conflict-free).
// ============================================================
__device__ __forceinline__ void load_slab_big(char* smem, int stage,
                                              const float* gA, const float* gB,
                                              int k0, int Ka, int Kb, int tid) {
    constexpr int LD = 36;
    constexpr int STAGE_BYTES = (128 + 256) * LD * 4;
    uint32_t base = smem_u32(smem) + stage * STAGE_BYTES;
#pragma unroll
    for (int i = 0; i < 4; i++) {                 // A: 128 rows x 32 floats
        int idx = tid + i * 256;
        int row = idx >> 3, seg = idx & 7;
        cp16(base + (uint32_t)(row * LD + seg * 4) * 4,
             gA + (size_t)row * Ka + k0 + seg * 4);
    }
    uint32_t bbase = base + 128 * LD * 4;
#pragma unroll
    for (int i = 0; i < 8; i++) {                 // B: 256 rows x 32 floats
        int idx = tid + i * 256;
        int row = idx >> 3, seg = idx & 7;
        cp16(bbase + (uint32_t)(row * LD + seg * 4) * 4,
             gB + (size_t)row * Kb + k0 + seg * 4);
    }
}

template <bool GELU, bool RND>
__global__ __launch_bounds__(256, 1) void tgemm_big(
    const float* __restrict__ A, const float* __restrict__ B,
    const float* __restrict__ bias, float* __restrict__ C,
    int K, int Ntot)
{
    extern __shared__ char smem[];
    constexpr int LD = 36;
    constexpr int STAGE_BYTES = (128 + 256) * LD * 4;

    const int tid = threadIdx.x, wid = tid >> 5, lane = tid & 31;
    const int warp_m = (wid & 1) * 64;
    const int warp_n = (wid >> 1) * 64;
    const int g = lane >> 2;
    const int tg = lane & 3;

    const float* gA = A + (size_t)blockIdx.y * 128 * K;
    const float* gB = B + (size_t)blockIdx.x * 256 * K;
    const int NS = K >> 5;

    float acc[4][8][4] = {};

    load_slab_big(smem, 0, gA, gB, 0, K, K, tid);  cp_commit();
    load_slab_big(smem, 1, gA, gB, 32, K, K, tid); cp_commit();

    for (int ks = 0; ks < NS; ks++) {
        if (ks + 2 < NS) {
            load_slab_big(smem, (ks + 2) % 3, gA, gB, (ks + 2) * 32, K, K, tid);
            cp_commit();
        }
        int rem = NS - 1 - ks;
        if (rem >= 2) cp_wait<2>();
        else if (rem == 1) cp_wait<1>();
        else cp_wait<0>();
        __syncthreads();

        const float* As = (const float*)(smem + (size_t)(ks % 3) * STAGE_BYTES);
        const float* Bs = As + 128 * LD;

#pragma unroll
        for (int kk = 0; kk < 4; kk++) {
            int k0 = kk * 8 + tg;
            uint32_t a[4][4], b[8][2];
#pragma unroll
            for (int mi = 0; mi < 4; mi++) {
                int r = warp_m + mi * 16 + g;
                a[mi][0] = __float_as_uint(As[r * LD + k0]);
                a[mi][1] = __float_as_uint(As[(r + 8) * LD + k0]);
                a[mi][2] = __float_as_uint(As[r * LD + k0 + 4]);
                a[mi][3] = __float_as_uint(As[(r + 8) * LD + k0 + 4]);
            }
#pragma unroll
            for (int ni = 0; ni < 8; ni++) {
                int rn = warp_n + ni * 8 + g;
                b[ni][0] = __float_as_uint(Bs[rn * LD + k0]);
                b[ni][1] = __float_as_uint(Bs[rn * LD + k0 + 4]);
            }
#pragma unroll
            for (int mi = 0; mi < 4; mi++)
#pragma unroll
                for (int ni = 0; ni < 8; ni++)
                    MMA_TF32(acc[mi][ni], a[mi][0], a[mi][1], a[mi][2], a[mi][3],
                             b[ni][0], b[ni][1]);
        }
        __syncthreads();
    }

    // epilogue
#pragma unroll
    for (int mi = 0; mi < 4; mi++) {
        int r0 = blockIdx.y * 128 + warp_m + mi * 16 + g;
#pragma unroll
        for (int ni = 0; ni < 8; ni++) {
            int col = blockIdx.x * 256 + warp_n + ni * 8 + 2 * tg;
            float bx = 0.f, by = 0.f;
            if (bias) { bx = bias[col]; by = bias[col + 1]; }
#pragma unroll
            for (int half = 0; half < 2; half++) {
                int row = r0 + half * 8;
                float vx = acc[mi][ni][half * 2 + 0] + bx;
                float vy = acc[mi][ni][half * 2 + 1] + by;
                if (GELU) { vx = gelu_exact(vx); vy = gelu_exact(vy); }
                if (RND)  { vx = rna_tf32(vx);   vy = rna_tf32(vy); }
                *(float2*)(C + (size_t)row * Ntot + col) = make_float2(vx, vy);
            }
        }
    }
}

// ============================================================
// SMALL GEMM (BN = 32): for the gate projection (N = 32)
// 8 warps stacked on m, warp tile 16 x 32.
// ============================================================
__device__ __forceinline__ void load_slab_32(char* smem, int stage,
                                             const float* gA, const float* gB,
                                             int k0, int K, int tid) {
    constexpr int LD = 36;
    constexpr int STAGE_BYTES = (128 + 32) * LD * 4;
    uint32_t base = smem_u32(smem) + stage * STAGE_BYTES;
#pragma unroll
    for (int i = 0; i < 4; i++) {
        int idx = tid + i * 256;
        int row = idx >> 3, seg = idx & 7;
        cp16(base + (uint32_t)(row * LD + seg * 4) * 4,
             gA + (size_t)row * K + k0 + seg * 4);
    }
    uint32_t bbase = base + 128 * LD * 4;
    {
        int idx = tid;
        int row = idx >> 3, seg = idx & 7;
        if (row < 32)
            cp16(bbase + (uint32_t)(row * LD + seg * 4) * 4,
                 gB + (size_t)row * K + k0 + seg * 4);
    }
}

__global__ __launch_bounds__(256) void tgemm32(
    const float* __restrict__ A, const float* __restrict__ B,
    const float* __restrict__ bias, float* __restrict__ C,
    int K, int Ntot)
{
    extern __shared__ char smem[];
    constexpr int LD = 36;
    constexpr int STAGE_BYTES = (128 + 32) * LD * 4;

    const int tid = threadIdx.x, wid = tid >> 5, lane = tid & 31;
    const int warp_m = wid * 16;
    const int g = lane >> 2, tg = lane & 3;

    const float* gA = A + (size_t)blockIdx.y * 128 * K;
    const float* gB = B;
    const int NS = K >> 5;

    float acc[4][4] = {};

    load_slab_32(smem, 0, gA, gB, 0, K, tid);  cp_commit();
    load_slab_32(smem, 1, gA, gB, 32, K, tid); cp_commit();

    for (int ks = 0; ks < NS; ks++) {
        if (ks + 2 < NS) {
            load_slab_32(smem, (ks + 2) % 3, gA, gB, (ks + 2) * 32, K, tid);
            cp_commit();
        }
        int rem = NS - 1 - ks;
        if (rem >= 2) cp_wait<2>();
        else if (rem == 1) cp_wait<1>();
        else cp_wait<0>();
        __syncthreads();

        const float* As = (const float*)(smem + (size_t)(ks % 3) * STAGE_BYTES);
        const float* Bs = As + 128 * LD;

#pragma unroll
        for (int kk = 0; kk < 4; kk++) {
            int k0 = kk * 8 + tg;
            uint32_t a[4], b[4][2];
            int r = warp_m + g;
            a[0] = __float_as_uint(As[r * LD + k0]);
            a[1] = __float_as_uint(As[(r + 8) * LD + k0]);
            a[2] = __float_as_uint(As[r * LD + k0 + 4]);
            a[3] = __float_as_uint(As[(r + 8) * LD + k0 + 4]);
#pragma unroll
            for (int ni = 0; ni < 4; ni++) {
                int rn = ni * 8 + g;
                b[ni][0] = __float_as_uint(Bs[rn * LD + k0]);
                b[ni][1] = __float_as_uint(Bs[rn * LD + k0 + 4]);
            }
#pragma unroll
            for (int ni = 0; ni < 4; ni++)
                MMA_TF32(acc[ni], a[0], a[1], a[2], a[3], b[ni][0], b[ni][1]);
        }
        __syncthreads();
    }

#pragma unroll
    for (int ni = 0; ni < 4; ni++) {
        int col = ni * 8 + 2 * tg;
        float bx = bias ? bias[col] : 0.f;
        float by = bias ? bias[col + 1] : 0.f;
        int r0 = blockIdx.y * 128 + warp_m + g;
#pragma unroll
        for (int half = 0; half < 2; half++) {
            int row = r0 + half * 8;
            float vx = acc[ni][half * 2 + 0] + bx;
            float vy = acc[ni][half * 2 + 1] + by;
            *(float2*)(C + (size_t)row * Ntot + col) = make_float2(vx, vy);
        }
    }
}

// ---------------- elementwise / small kernels ----------------
__global__ void round_copy_kernel(const float* __restrict__ in, float* __restrict__ out) {
    int i = blockIdx.x * 256 + threadIdx.x;
    float4 v = ((const float4*)in)[i];
    v.x = rna_tf32(v.x); v.y = rna_tf32(v.y);
    v.z = rna_tf32(v.z); v.w = rna_tf32(v.w);
    ((float4*)out)[i] = v;
}

__global__ void transpose_rna_kernel(const float* __restrict__ in, float* __restrict__ out,
                                     int R, int C) {
    __shared__ float t[32][33];
    int c0 = blockIdx.x * 32, r0 = blockIdx.y * 32;
    int x = threadIdx.x, y = threadIdx.y;  // 32 x 8
#pragma unroll
    for (int dy = 0; dy < 32; dy += 8)
        t[y + dy][x] = in[(size_t)(r0 + y + dy) * C + c0 + x];
    __syncthreads();
#pragma unroll
    for (int dy = 0; dy < 32; dy += 8)
        out[(size_t)(c0 + y + dy) * R + r0 + x] = rna_tf32(t[x][y + dy]);
}

__global__ void pack_bias_kernel(const float* __restrict__ br, const float* __restrict__ bi,
                                 float* __restrict__ bc) {
    int i = threadIdx.x;
    bc[i] = br[i];
    bc[256 + i] = bi[i];
}

__global__ void psinorm_kernel(float* __restrict__ psi) {
    size_t base = (size_t)blockIdx.x * 512;
    int tid = threadIdx.x;   // 256
    float a = psi[base + tid], b = psi[base + 256 + tid];
    float tot = block_sum_256(a * a + b * b);
    float nrm = fmaxf(sqrtf(tot), 1e-12f);
    psi[base + tid] = rna_tf32(a / nrm);
    psi[base + 256 + tid] = rna_tf32(b / nrm);
}

// memory normalize -> packed B operand [512 x 512]
__global__ void memnorm_kernel(const float* __restrict__ mr, const float* __restrict__ mi,
                               float* __restrict__ Mp) {
    int s = blockIdx.x;    // SS
    int d = threadIdx.x;   // DH
    float a = mr[s * DH + d], b = mi[s * DH + d];
    float tot = block_sum_256(a * a + b * b);
    float nrm = fmaxf(sqrtf(tot), 1e-12f);
    float ra = rna_tf32(a / nrm), rb = rna_tf32(b / nrm);
    Mp[(size_t)s * 512 + d] = ra;
    Mp[(size_t)s * 512 + 256 + d] = rb;
    Mp[(size_t)(256 + s) * 512 + d] = rb;
    Mp[(size_t)(256 + s) * 512 + 256 + d] = -ra;
}

__global__ void gate_kernel(const float* __restrict__ x,
                            const float* __restrict__ w1, const float* __restrict__ b1,
                            const float* __restrict__ gain, const float* __restrict__ beta,
                            const float* __restrict__ w2, const float* __restrict__ b2,
                            float* __restrict__ out, float scale)
{
    int row = blockIdx.x;
    const float* xr = x + (size_t)row * DIM;
    __shared__ float part[8][HIDN + 1];
    int tid = threadIdx.x;
    int j = tid & 31;
    int t = tid >> 5;
    float s = 0.f;
    int k0 = t * (DIM / 8);
#pragma unroll 4
    for (int i = 0; i < DIM / 8; i++) {
        float xv = xr[k0 + i];
        s += xv * w1[(k0 + i) * HIDN + j];
    }
    part[t][j] = s;
    __syncthreads();
    if (tid < HIDN) {
        float v = 0.f;
#pragma unroll
        for (int q = 0; q < 8; q++) v += part[q][tid];
        v += b1[tid];
        float m = v;
#pragma unroll
        for (int o = 16; o; o >>= 1) m += __shfl_xor_sync(0xffffffffu, m, o);
        m *= (1.f / 32.f);
        float d = v - m;
        float var = d * d;
#pragma unroll
        for (int o = 16; o; o >>= 1) var += __shfl_xor_sync(0xffffffffu, var, o);
        var *= (1.f / 32.f);
        float tn = d / sqrtf(var + 1e-5f) * gain[tid] + beta[tid];
        float si = tn / (1.f + expf(-tn));
        float p = si * w2[tid];
#pragma unroll
        for (int o = 16; o; o >>= 1) p += __shfl_xor_sync(0xffffffffu, p, o);
        if (tid == 0) out[row] = scale / (1.f + expf(-(p + b2[0])));
    }
}

__global__ void gate_finish_kernel(const float* __restrict__ t1,
                                   const float* __restrict__ gain, const float* __restrict__ beta,
                                   const float* __restrict__ w2, const float* __restrict__ b2,
                                   float* __restrict__ out, float scale)
{
    int row = blockIdx.x * 8 + (threadIdx.x >> 5);
    int j = threadIdx.x & 31;
    float v = t1[row * HIDN + j];
    float m = v;
#pragma unroll
    for (int o = 16; o; o >>= 1) m += __shfl_xor_sync(0xffffffffu, m, o);
    m *= (1.f / 32.f);
    float d = v - m;
    float var = d * d;
#pragma unroll
    for (int o = 16; o; o >>= 1) var += __shfl_xor_sync(0xffffffffu, var, o);
    var *= (1.f / 32.f);
    float tn = d / sqrtf(var + 1e-5f) * gain[j] + beta[j];
    float si = tn / (1.f + expf(-tn));
    float p = si * w2[j];
#pragma unroll
    for (int o = 16; o; o >>= 1) p += __shfl_xor_sync(0xffffffffu, p, o);
    if (j == 0) out[row] = scale / (1.f + expf(-(p + b2[0])));
}

__global__ void ctx_partial_kernel(const float* __restrict__ h, float* __restrict__ part) {
    int d = blockIdx.x * 256 + threadIdx.x;
    int b = blockIdx.y;
    int c = blockIdx.z;
    const float* base = h + (((size_t)b * NSEQ + c * 128) * DIM) + d;
    float s = 0.f;
#pragma unroll 4
    for (int n = 0; n < 128; n++) s += base[(size_t)n * DIM];
    part[(size_t)(b * 32 + c) * DIM + d] = s;
}

__global__ void ctx_final_kernel(const float* __restrict__ part, float* __restrict__ ctx) {
    int i = blockIdx.x * 256 + threadIdx.x;
    int b = i >> 10, d = i & 1023;
    float s = 0.f;
#pragma unroll
    for (int c = 0; c < 32; c++) s += part[(size_t)(b * 32 + c) * DIM + d];
    ctx[i] = s * (1.f / (float)NSEQ);
}

__global__ void attn_kernel(const float* __restrict__ reim, float* __restrict__ attn,
                            const float* __restrict__ pinit, const float* __restrict__ gamma) {
    int row = blockIdx.x;
    int s = threadIdx.x;
    int b = row >> 12;
    float p = pinit[row] * (1.f - gamma[b]);
    size_t base = (size_t)row * 512;
    float r = reim[base + s], i = reim[base + 256 + s];
    float raw = (1.f - p) * (r * r + i * i) + p * (1.f / (float)DH);
    float tot = block_sum_256(raw);
    attn[(size_t)row * SS + s] = rna_tf32(raw / (tot + 1e-8f));
}

template <bool RC>
__global__ void ln_add_kernel(const float* __restrict__ a, const float* __restrict__ bsrc,
                              const float* __restrict__ g, const float* __restrict__ beta,
                              float* __restrict__ out, float* __restrict__ outr) {
    size_t off = (size_t)blockIdx.x * DIM;
    int tid = threadIdx.x;
    float v[4];
    float s = 0.f;
#pragma unroll
    for (int q = 0; q < 4; q++) {
        int i = tid + q * 256;
        v[q] = a[off + i] + bsrc[off + i];
        s += v[q];
    }
    float mu = block_sum_256(s) * (1.f / (float)DIM);
    float s2 = 0.f;
#pragma unroll
    for (int q = 0; q < 4; q++) {
        float d = v[q] - mu;
        s2 += d * d;
    }
    float var = block_sum_256(s2) * (1.f / (float)DIM);
    float inv = 1.f / sqrtf(var + 1e-5f);
#pragma unroll
    for (int q = 0; q < 4; q++) {
        int i = tid + q * 256;
        float o = (v[q] - mu) * inv * g[i] + beta[i];
        out[off + i] = o;
        if (RC) outr[off + i] = rna_tf32(o);
    }
}

// ---------------- launch ----------------
static inline float* sym(const void* s) {
    void* p = nullptr;
    cudaGetSymbolAddress(&p, s);
    return (float*)p;
}

extern "C" void kernel_launch(void* const* d_in, const int* in_sizes, int n_in,
                              void* d_out, int out_size) {
    const float* h     = (const float*)d_in[0];
    const float* Wr    = (const float*)d_in[1];
    const float* br    = (const float*)d_in[2];
    const float* Wi    = (const float*)d_in[3];
    const float* bi    = (const float*)d_in[4];
    const float* uw1   = (const float*)d_in[5];
    const float* ub1   = (const float*)d_in[6];
    const float* ug    = (const float*)d_in[7];
    const float* ubeta = (const float*)d_in[8];
    const float* uw2   = (const float*)d_in[9];
    const float* ub2   = (const float*)d_in[10];
    const float* gw1   = (const float*)d_in[11];
    const float* gb1   = (const float*)d_in[12];
    const float* gg    = (const float*)d_in[13];
    const float* gbeta = (const float*)d_in[14];
    const float* gw2   = (const float*)d_in[15];
    const float* gb2   = (const float*)d_in[16];
    const float* m_real= (const float*)d_in[17];
    const float* m_imag= (const float*)d_in[18];
    const float* values= (const float*)d_in[19];
    const float* ow    = (const float*)d_in[20];
    const float* ob    = (const float*)d_in[21];
    const float* n1g   = (const float*)d_in[22];
    const float* n1b   = (const float*)d_in[23];
    const float* n2g   = (const float*)d_in[24];
    const float* n2b   = (const float*)d_in[25];
    const float* fw1   = (const float*)d_in[26];
    const float* fb1   = (const float*)d_in[27];
    const float* fw2   = (const float*)d_in[28];
    const float* fb2   = (const float*)d_in[29];
    float* out = (float*)d_out;

    float* h32  = sym(g_h32);
    float* psi  = sym(g_psi);
    float* reim = sym(g_reim);
    float* attn = sym(g_attn);
    float* t1   = sym(g_t1);
    float* pinit= sym(g_pinit);
    float* gam  = sym(g_gamma);
    float* ctx  = sym(g_ctx);
    float* ctxp = sym(g_ctxpart);
    float* ao   = sym(g_ao);
    float* h1   = sym(g_h1);
    float* h1r  = sym(g_h1r);
    float* ff1  = sym(g_ff1);
    float* ff2  = sym(g_ff2);
    float* WT   = sym(g_WT);
    float* bc   = sym(g_bc);
    float* Mp   = sym(g_Mpack);
    float* uw1T = sym(g_uw1T);
    float* val32= sym(g_val32);
    float* owT  = sym(g_owT);
    float* VOT  = sym(g_VOT);
    float* fw1T = sym(g_fw1T);
    float* fw2T = sym(g_fw2T);

    const int smBIG = (128 + 256) * 36 * 4 * 3;   // 165888
    const int sm32  = (128 + 32) * 36 * 4 * 3;    // 69120
    cudaFuncSetAttribute(tgemm_big<false, false>, cudaFuncAttributeMaxDynamicSharedMemorySize, smBIG);
    cudaFuncSetAttribute(tgemm_big<false, true >, cudaFuncAttributeMaxDynamicSharedMemorySize, smBIG);
    cudaFuncSetAttribute(tgemm_big<true,  true >, cudaFuncAttributeMaxDynamicSharedMemorySize, smBIG);
    cudaFuncSetAttribute(tgemm32, cudaFuncAttributeMaxDynamicSharedMemorySize, sm32);

    dim3 thr(256);
    dim3 t328(32, 8);

    // 0) rounded copies
    round_copy_kernel<<<NTOK * DIM / 1024, thr>>>(h, h32);
    round_copy_kernel<<<SS * DIM / 1024, thr>>>(values, val32);

    // 1) weight transposes (+rna)
    transpose_rna_kernel<<<dim3(DH / 32, DIM / 32),  t328>>>(Wr, WT, DIM, DH);
    transpose_rna_kernel<<<dim3(DH / 32, DIM / 32),  t328>>>(Wi, WT + 256 * DIM, DIM, DH);
    pack_bias_kernel<<<1, 256>>>(br, bi, bc);
    transpose_rna_kernel<<<dim3(HIDN / 32, DIM / 32),t328>>>(uw1, uw1T, DIM, HIDN);
    transpose_rna_kernel<<<dim3(DIM / 32, DIM / 32), t328>>>(ow,  owT,  DIM, DIM);
    transpose_rna_kernel<<<dim3(DFF / 32, DIM / 32), t328>>>(fw1, fw1T, DIM, DFF);
    transpose_rna_kernel<<<dim3(DIM / 32, DFF / 32), t328>>>(fw2, fw2T, DFF, DIM);

    // 2) memory normalize -> packed B operand
    memnorm_kernel<<<SS, DH>>>(m_real, m_imag, Mp);

    // 2b) VOT = owT @ values^T  -> [D=1024 rows, S=256 cols], rounded
    //     VOT[d, s] = sum_e ow[e, d] * values[s, e]
    tgemm_big<false, true ><<<dim3(1, 8), thr, smBIG>>>(owT, val32, nullptr, VOT, DIM, SS);

    // 3) psi = h @ [Wr|Wi] + [br|bi]  (16384 x 512 x 1024), then normalize
    tgemm_big<false, false><<<dim3(2, 128), thr, smBIG>>>(h32, WT, bc, psi, DIM, 512);
    psinorm_kernel<<<NTOK, 256>>>(psi);

    // 4) uncertainty gate
    tgemm32<<<dim3(1, 128), thr, sm32>>>(h32, uw1T, ub1, t1, DIM, HIDN);
    gate_finish_kernel<<<NTOK / 8, 256>>>(t1, ug, ubeta, uw2, ub2, pinit, 0.95f);

    // 5) ctx mean + gamma gate
    ctx_partial_kernel<<<dim3(DIM / 256, BB, 32), thr>>>(h, ctxp);
    ctx_final_kernel<<<(BB * DIM) / 256, thr>>>(ctxp, ctx);
    gate_kernel<<<BB, 256>>>(ctx, gw1, gb1, gg, gbeta, gw2, gb2, gam, 1.0f);

    // 6) reim = psi @ Mpack^T  (16384 x 512 x 512)
    tgemm_big<false, false><<<dim3(2, 128), thr, smBIG>>>(psi, Mp, nullptr, reim, 512, 512);

    // 7) attention weights
    attn_kernel<<<NTOK, SS>>>(reim, attn, pinit, gam);

    // 8) ao = attn @ VOT^T + ob   (16384 x 1024 x 256)
    tgemm_big<false, false><<<dim3(4, 128), thr, smBIG>>>(attn, VOT, ob, ao, SS, DIM);

    // 9) h1 = LN(h + ao) (+ rounded copy)
    ln_add_kernel<true><<<NTOK, 256>>>(h, ao, n1g, n1b, h1, h1r);

    // 10) FFN
    tgemm_big<true,  true ><<<dim3(16, 128), thr, smBIG>>>(h1r, fw1T, fb1, ff1, DIM, DFF);
    tgemm_big<false, false><<<dim3(4, 128), thr, smBIG>>>(ff1, fw2T, fb2, ff2, DFF, DIM);

    // 11) out = LN(h1 + ff2)
    ln_add_kernel<false><<<NTOK, 256>>>(h1, ff2, n2g, n2b, out, nullptr);
}

// round 5
// speedup vs baseline: 3.7840x; 1.0544x over previous
#include <cuda_runtime.h>
#include <math.h>
#include <stdint.h>

// ---------------- problem constants ----------------
#define BB    4
#define NSEQ  4096
#define NTOK  16384        // BB*NSEQ
#define DIM   1024
#define DH    256
#define SS    256
#define HIDN  32
#define DFF   4096

// ---------------- scratch (device globals: allowed) ----------------
__device__ float g_h32[NTOK * DIM];       // rna(h)
__device__ float g_psi[NTOK * 512];       // [pr | pi] packed, normalized+rounded
__device__ float g_reim[NTOK * 512];      // [re | im] packed
__device__ float g_attn[NTOK * SS];
__device__ float g_t1[NTOK * HIDN];
__device__ float g_pinit[NTOK];
__device__ float g_gamma[BB];
__device__ float g_ctx[BB * DIM];
__device__ float g_ctxpart[BB * 32 * DIM];
__device__ float g_ao[NTOK * DIM];
__device__ float g_h1[NTOK * DIM];
__device__ float g_h1r[NTOK * DIM];
__device__ float g_ff1[NTOK * DFF];
__device__ float g_ff2[NTOK * DIM];
// packed / transposed weights (B operands stored [N, K], K contiguous)
__device__ float g_WT[512 * DIM];         // rows 0-255 = Wr^T, 256-511 = Wi^T
__device__ float g_bc[512];               // [br | bi]
__device__ float g_Mpack[512 * 512];      // rows 0-255: [Mr|Mi], rows 256-511: [Mi|-Mr]
__device__ float g_uw1T[HIDN * DIM];
__device__ float g_val32[SS * DIM];       // rna(values)
__device__ float g_owT[DIM * DIM];
__device__ float g_VOT[DIM * SS];         // (values @ ow)^T, rounded
__device__ float g_fw1T[DFF * DIM];
__device__ float g_fw2T[DIM * DFF];

// ---------------- small helpers ----------------
__device__ __forceinline__ float rna_tf32(float x) {
    uint32_t u;
    asm("cvt.rna.tf32.f32 %0, %1;" : "=r"(u) : "f"(x));
    return __uint_as_float(u);
}

__device__ __forceinline__ float gelu_exact(float x) {
    return 0.5f * x * (1.0f + erff(x * 0.7071067811865475f));
}

__device__ __forceinline__ float block_sum_256(float v) {
    __shared__ float sh[8];
    int lane = threadIdx.x & 31, w = threadIdx.x >> 5;
#pragma unroll
    for (int o = 16; o; o >>= 1) v += __shfl_xor_sync(0xffffffffu, v, o);
    if (lane == 0) sh[w] = v;
    __syncthreads();
    float r = (lane < 8) ? sh[lane] : 0.f;
    if (w == 0) {
#pragma unroll
        for (int o = 4; o; o >>= 1) r += __shfl_xor_sync(0xffffffffu, r, o);
        if (lane == 0) sh[0] = r;
    }
    __syncthreads();
    float out = sh[0];
    __syncthreads();
    return out;
}

__device__ __forceinline__ uint32_t smem_u32(const void* p) {
    return (uint32_t)__cvta_generic_to_shared(p);
}
__device__ __forceinline__ void cp16(uint32_t dst, const void* src) {
    asm volatile("cp.async.cg.shared.global [%0], [%1], 16;" :: "r"(dst), "l"(src));
}
__device__ __forceinline__ void cp_commit() { asm volatile("cp.async.commit_group;"); }
template <int N>
__device__ __forceinline__ void cp_wait() { asm volatile("cp.async.wait_group %0;" :: "n"(N)); }

#define MMA_TF32(d, a0, a1, a2, a3, b0, b1) \
    asm volatile( \
        "mma.sync.aligned.m16n8k8.row.col.f32.tf32.tf32.f32 " \
        "{%0,%1,%2,%3}, {%4,%5,%6,%7}, {%8,%9}, {%0,%1,%2,%3};" \
        : "+f"((d)[0]), "+f"((d)[1]), "+f"((d)[2]), "+f"((d)[3]) \
        : "r"(a0), "r"(a1), "r"(a2), "r"(a3), "r"(b0), "r"(b1))

// ============================================================
// BIG GEMM: 128 x 256 CTA tile, 8 warps (2 x 4), warp tile 64 x 64
// C = A @ B^T (+bias) (+gelu) (+rna);  A:[M,K], B:[N,K] row-major (tf32 vals)
// BK = 32, 3-stage cp.async pipeline.
// SMEM: 32 floats (8 x 16B chunks) per row; chunk swizzle p = c ^ ((row&1)<<2)
//   -> conflict-free for 16B cp.async writes AND LDS.128 fragment reads.
// k-permutation: mma position (tg, j, slot) <-> logical col 16w + 4*tg + 2j + slot.
//   A and B use the same bijection, so the k8 dot products are exact.
// ============================================================
__device__ __forceinline__ void load_slab_big(char* smem, int stage,
                                              const float* gA, const float* gB,
                                              int k0, int Ka, int Kb, int tid) {
    constexpr int STAGE_BYTES = (128 + 256) * 128;
    uint32_t base = smem_u32(smem) + stage * STAGE_BYTES;
#pragma unroll
    for (int i = 0; i < 4; i++) {                 // A: 128 rows x 8 chunks
        int idx = tid + i * 256;
        int row = idx >> 3, c = idx & 7;
        int p = c ^ ((row & 1) << 2);
        cp16(base + (uint32_t)(row * 128 + p * 16),
             gA + (size_t)row * Ka + k0 + c * 4);
    }
    uint32_t bbase = base + 128 * 128;
#pragma unroll
    for (int i = 0; i < 8; i++) {                 // B: 256 rows x 8 chunks
        int idx = tid + i * 256;
        int row = idx >> 3, c = idx & 7;
        int p = c ^ ((row & 1) << 2);
        cp16(bbase + (uint32_t)(row * 128 + p * 16),
             gB + (size_t)row * Kb + k0 + c * 4);
    }
}

template <bool GELU, bool RND>
__global__ __launch_bounds__(256, 1) void tgemm_big(
    const float* __restrict__ A, const float* __restrict__ B,
    const float* __restrict__ bias, float* __restrict__ C,
    int K, int Ntot)
{
    extern __shared__ char smem[];
    constexpr int STAGE_BYTES = (128 + 256) * 128;

    const int tid = threadIdx.x, wid = tid >> 5, lane = tid & 31;
    const int warp_m = (wid & 1) * 64;
    const int warp_n = (wid >> 1) * 64;
    const int g = lane >> 2;
    const int tg = lane & 3;

    const float* gA = A + (size_t)blockIdx.y * 128 * K;
    const float* gB = B + (size_t)blockIdx.x * 256 * K;
    const int NS = K >> 5;

    float acc[4][8][4] = {};

    load_slab_big(smem, 0, gA, gB, 0, K, K, tid);  cp_commit();
    load_slab_big(smem, 1, gA, gB, 32, K, K, tid); cp_commit();

    for (int ks = 0; ks < NS; ks++) {
        if (ks + 2 < NS) {
            load_slab_big(smem, (ks + 2) % 3, gA, gB, (ks + 2) * 32, K, K, tid);
            cp_commit();
        }
        int rem = NS - 1 - ks;
        if (rem >= 2) cp_wait<2>();
        else if (rem == 1) cp_wait<1>();
        else cp_wait<0>();
        __syncthreads();

        const float* As = (const float*)(smem + (size_t)(ks % 3) * STAGE_BYTES);
        const float* Bs = As + 128 * 32;

#pragma unroll
        for (int w = 0; w < 2; w++) {
            // physical chunk for this thread: (4w + tg) ^ ((row&1)<<2).
            // row bases are even, so parity is decided by g&1 (A: row=base+g; the
            // +8 half keeps parity).
            float4 a4[4][2];
#pragma unroll
            for (int mi = 0; mi < 4; mi++) {
#pragma unroll
                for (int half = 0; half < 2; half++) {
                    int r = warp_m + mi * 16 + half * 8 + g;
                    int p = (4 * w + tg) ^ ((r & 1) << 2);
                    a4[mi][half] = *(const float4*)(As + r * 32 + p * 4);
                }
            }
            float4 b4[8];
#pragma unroll
            for (int ni = 0; ni < 8; ni++) {
                int r = warp_n + ni * 8 + g;
                int p = (4 * w + tg) ^ ((r & 1) << 2);
                b4[ni] = *(const float4*)(Bs + r * 32 + p * 4);
            }
#pragma unroll
            for (int mi = 0; mi < 4; mi++) {
#pragma unroll
                for (int ni = 0; ni < 8; ni++) {
                    MMA_TF32(acc[mi][ni],
                             __float_as_uint(a4[mi][0].x), __float_as_uint(a4[mi][1].x),
                             __float_as_uint(a4[mi][0].y), __float_as_uint(a4[mi][1].y),
                             __float_as_uint(b4[ni].x),    __float_as_uint(b4[ni].y));
                    MMA_TF32(acc[mi][ni],
                             __float_as_uint(a4[mi][0].z), __float_as_uint(a4[mi][1].z),
                             __float_as_uint(a4[mi][0].w), __float_as_uint(a4[mi][1].w),
                             __float_as_uint(b4[ni].z),    __float_as_uint(b4[ni].w));
                }
            }
        }
        __syncthreads();
    }

    // epilogue
#pragma unroll
    for (int mi = 0; mi < 4; mi++) {
        int r0 = blockIdx.y * 128 + warp_m + mi * 16 + g;
#pragma unroll
        for (int ni = 0; ni < 8; ni++) {
            int col = blockIdx.x * 256 + warp_n + ni * 8 + 2 * tg;
            float bx = 0.f, by = 0.f;
            if (bias) { bx = bias[col]; by = bias[col + 1]; }
#pragma unroll
            for (int half = 0; half < 2; half++) {
                int row = r0 + half * 8;
                float vx = acc[mi][ni][half * 2 + 0] + bx;
                float vy = acc[mi][ni][half * 2 + 1] + by;
                if (GELU) { vx = gelu_exact(vx); vy = gelu_exact(vy); }
                if (RND)  { vx = rna_tf32(vx);   vy = rna_tf32(vy); }
                *(float2*)(C + (size_t)row * Ntot + col) = make_float2(vx, vy);
            }
        }
    }
}

// ============================================================
// SMALL GEMM (BN = 32) for the gate projection (N = 32)
// (unchanged from round 4: LD=36 scalar-LDS version; minor cost)
// ============================================================
__device__ __forceinline__ void load_slab_32(char* smem, int stage,
                                             const float* gA, const float* gB,
                                             int k0, int K, int tid) {
    constexpr int LD = 36;
    constexpr int STAGE_BYTES = (128 + 32) * LD * 4;
    uint32_t base = smem_u32(smem) + stage * STAGE_BYTES;
#pragma unroll
    for (int i = 0; i < 4; i++) {
        int idx = tid + i * 256;
        int row = idx >> 3, seg = idx & 7;
        cp16(base + (uint32_t)(row * LD + seg * 4) * 4,
             gA + (size_t)row * K + k0 + seg * 4);
    }
    uint32_t bbase = base + 128 * LD * 4;
    {
        int idx = tid;
        int row = idx >> 3, seg = idx & 7;
        if (row < 32)
            cp16(bbase + (uint32_t)(row * LD + seg * 4) * 4,
                 gB + (size_t)row * K + k0 + seg * 4);
    }
}

__global__ __launch_bounds__(256) void tgemm32(
    const float* __restrict__ A, const float* __restrict__ B,
    const float* __restrict__ bias, float* __restrict__ C,
    int K, int Ntot)
{
    extern __shared__ char smem[];
    constexpr int LD = 36;
    constexpr int STAGE_BYTES = (128 + 32) * LD * 4;

    const int tid = threadIdx.x, wid = tid >> 5, lane = tid & 31;
    const int warp_m = wid * 16;
    const int g = lane >> 2, tg = lane & 3;

    const float* gA = A + (size_t)blockIdx.y * 128 * K;
    const float* gB = B;
    const int NS = K >> 5;

    float acc[4][4] = {};

    load_slab_32(smem, 0, gA, gB, 0, K, tid);  cp_commit();
    load_slab_32(smem, 1, gA, gB, 32, K, tid); cp_commit();

    for (int ks = 0; ks < NS; ks++) {
        if (ks + 2 < NS) {
            load_slab_32(smem, (ks + 2) % 3, gA, gB, (ks + 2) * 32, K, tid);
            cp_commit();
        }
        int rem = NS - 1 - ks;
        if (rem >= 2) cp_wait<2>();
        else if (rem == 1) cp_wait<1>();
        else cp_wait<0>();
        __syncthreads();

        const float* As = (const float*)(smem + (size_t)(ks % 3) * STAGE_BYTES);
        const float* Bs = As + 128 * LD;

#pragma unroll
        for (int kk = 0; kk < 4; kk++) {
            int k0 = kk * 8 + tg;
            uint32_t a[4], b[4][2];
            int r = warp_m + g;
            a[0] = __float_as_uint(As[r * LD + k0]);
            a[1] = __float_as_uint(As[(r + 8) * LD + k0]);
            a[2] = __float_as_uint(As[r * LD + k0 + 4]);
            a[3] = __float_as_uint(As[(r + 8) * LD + k0 + 4]);
#pragma unroll
            for (int ni = 0; ni < 4; ni++) {
                int rn = ni * 8 + g;
                b[ni][0] = __float_as_uint(Bs[rn * LD + k0]);
                b[ni][1] = __float_as_uint(Bs[rn * LD + k0 + 4]);
            }
#pragma unroll
            for (int ni = 0; ni < 4; ni++)
                MMA_TF32(acc[ni], a[0], a[1], a[2], a[3], b[ni][0], b[ni][1]);
        }
        __syncthreads();
    }

#pragma unroll
    for (int ni = 0; ni < 4; ni++) {
        int col = ni * 8 + 2 * tg;
        float bx = bias ? bias[col] : 0.f;
        float by = bias ? bias[col + 1] : 0.f;
        int r0 = blockIdx.y * 128 + warp_m + g;
#pragma unroll
        for (int half = 0; half < 2; half++) {
            int row = r0 + half * 8;
            float vx = acc[ni][half * 2 + 0] + bx;
            float vy = acc[ni][half * 2 + 1] + by;
            *(float2*)(C + (size_t)row * Ntot + col) = make_float2(vx, vy);
        }
    }
}

// ---------------- elementwise / small kernels ----------------
__global__ void round_copy_kernel(const float* __restrict__ in, float* __restrict__ out) {
    int i = blockIdx.x * 256 + threadIdx.x;
    float4 v = ((const float4*)in)[i];
    v.x = rna_tf32(v.x); v.y = rna_tf32(v.y);
    v.z = rna_tf32(v.z); v.w = rna_tf32(v.w);
    ((float4*)out)[i] = v;
}

__global__ void transpose_rna_kernel(const float* __restrict__ in, float* __restrict__ out,
                                     int R, int C) {
    __shared__ float t[32][33];
    int c0 = blockIdx.x * 32, r0 = blockIdx.y * 32;
    int x = threadIdx.x, y = threadIdx.y;  // 32 x 8
#pragma unroll
    for (int dy = 0; dy < 32; dy += 8)
        t[y + dy][x] = in[(size_t)(r0 + y + dy) * C + c0 + x];
    __syncthreads();
#pragma unroll
    for (int dy = 0; dy < 32; dy += 8)
        out[(size_t)(c0 + y + dy) * R + r0 + x] = rna_tf32(t[x][y + dy]);
}

__global__ void pack_bias_kernel(const float* __restrict__ br, const float* __restrict__ bi,
                                 float* __restrict__ bc) {
    int i = threadIdx.x;
    bc[i] = br[i];
    bc[256 + i] = bi[i];
}

__global__ void psinorm_kernel(float* __restrict__ psi) {
    size_t base = (size_t)blockIdx.x * 512;
    int tid = threadIdx.x;   // 256
    float a = psi[base + tid], b = psi[base + 256 + tid];
    float tot = block_sum_256(a * a + b * b);
    float nrm = fmaxf(sqrtf(tot), 1e-12f);
    psi[base + tid] = rna_tf32(a / nrm);
    psi[base + 256 + tid] = rna_tf32(b / nrm);
}

// memory normalize -> packed B operand [512 x 512]
__global__ void memnorm_kernel(const float* __restrict__ mr, const float* __restrict__ mi,
                               float* __restrict__ Mp) {
    int s = blockIdx.x;    // SS
    int d = threadIdx.x;   // DH
    float a = mr[s * DH + d], b = mi[s * DH + d];
    float tot = block_sum_256(a * a + b * b);
    float nrm = fmaxf(sqrtf(tot), 1e-12f);
    float ra = rna_tf32(a / nrm), rb = rna_tf32(b / nrm);
    Mp[(size_t)s * 512 + d] = ra;
    Mp[(size_t)s * 512 + 256 + d] = rb;
    Mp[(size_t)(256 + s) * 512 + d] = rb;
    Mp[(size_t)(256 + s) * 512 + 256 + d] = -ra;
}

__global__ void gate_kernel(const float* __restrict__ x,
                            const float* __restrict__ w1, const float* __restrict__ b1,
                            const float* __restrict__ gain, const float* __restrict__ beta,
                            const float* __restrict__ w2, const float* __restrict__ b2,
                            float* __restrict__ out, float scale)
{
    int row = blockIdx.x;
    const float* xr = x + (size_t)row * DIM;
    __shared__ float part[8][HIDN + 1];
    int tid = threadIdx.x;
    int j = tid & 31;
    int t = tid >> 5;
    float s = 0.f;
    int k0 = t * (DIM / 8);
#pragma unroll 4
    for (int i = 0; i < DIM / 8; i++) {
        float xv = xr[k0 + i];
        s += xv * w1[(k0 + i) * HIDN + j];
    }
    part[t][j] = s;
    __syncthreads();
    if (tid < HIDN) {
        float v = 0.f;
#pragma unroll
        for (int q = 0; q < 8; q++) v += part[q][tid];
        v += b1[tid];
        float m = v;
#pragma unroll
        for (int o = 16; o; o >>= 1) m += __shfl_xor_sync(0xffffffffu, m, o);
        m *= (1.f / 32.f);
        float d = v - m;
        float var = d * d;
#pragma unroll
        for (int o = 16; o; o >>= 1) var += __shfl_xor_sync(0xffffffffu, var, o);
        var *= (1.f / 32.f);
        float tn = d / sqrtf(var + 1e-5f) * gain[tid] + beta[tid];
        float si = tn / (1.f + expf(-tn));
        float p = si * w2[tid];
#pragma unroll
        for (int o = 16; o; o >>= 1) p += __shfl_xor_sync(0xffffffffu, p, o);
        if (tid == 0) out[row] = scale / (1.f + expf(-(p + b2[0])));
    }
}

__global__ void gate_finish_kernel(const float* __restrict__ t1,
                                   const float* __restrict__ gain, const float* __restrict__ beta,
                                   const float* __restrict__ w2, const float* __restrict__ b2,
                                   float* __restrict__ out, float scale)
{
    int row = blockIdx.x * 8 + (threadIdx.x >> 5);
    int j = threadIdx.x & 31;
    float v = t1[row * HIDN + j];
    float m = v;
#pragma unroll
    for (int o = 16; o; o >>= 1) m += __shfl_xor_sync(0xffffffffu, m, o);
    m *= (1.f / 32.f);
    float d = v - m;
    float var = d * d;
#pragma unroll
    for (int o = 16; o; o >>= 1) var += __shfl_xor_sync(0xffffffffu, var, o);
    var *= (1.f / 32.f);
    float tn = d / sqrtf(var + 1e-5f) * gain[j] + beta[j];
    float si = tn / (1.f + expf(-tn));
    float p = si * w2[j];
#pragma unroll
    for (int o = 16; o; o >>= 1) p += __shfl_xor_sync(0xffffffffu, p, o);
    if (j == 0) out[row] = scale / (1.f + expf(-(p + b2[0])));
}

__global__ void ctx_partial_kernel(const float* __restrict__ h, float* __restrict__ part) {
    int d = blockIdx.x * 256 + threadIdx.x;
    int b = blockIdx.y;
    int c = blockIdx.z;
    const float* base = h + (((size_t)b * NSEQ + c * 128) * DIM) + d;
    float s = 0.f;
#pragma unroll 4
    for (int n = 0; n < 128; n++) s += base[(size_t)n * DIM];
    part[(size_t)(b * 32 + c) * DIM + d] = s;
}

__global__ void ctx_final_kernel(const float* __restrict__ part, float* __restrict__ ctx) {
    int i = blockIdx.x * 256 + threadIdx.x;
    int b = i >> 10, d = i & 1023;
    float s = 0.f;
#pragma unroll
    for (int c = 0; c < 32; c++) s += part[(size_t)(b * 32 + c) * DIM + d];
    ctx[i] = s * (1.f / (float)NSEQ);
}

__global__ void attn_kernel(const float* __restrict__ reim, float* __restrict__ attn,
                            const float* __restrict__ pinit, const float* __restrict__ gamma) {
    int row = blockIdx.x;
    int s = threadIdx.x;
    int b = row >> 12;
    float p = pinit[row] * (1.f - gamma[b]);
    size_t base = (size_t)row * 512;
    float r = reim[base + s], i = reim[base + 256 + s];
    float raw = (1.f - p) * (r * r + i * i) + p * (1.f / (float)DH);
    float tot = block_sum_256(raw);
    attn[(size_t)row * SS + s] = rna_tf32(raw / (tot + 1e-8f));
}

template <bool RC>
__global__ void ln_add_kernel(const float* __restrict__ a, const float* __restrict__ bsrc,
                              const float* __restrict__ g, const float* __restrict__ beta,
                              float* __restrict__ out, float* __restrict__ outr) {
    size_t off = (size_t)blockIdx.x * DIM;
    int tid = threadIdx.x;
    float v[4];
    float s = 0.f;
#pragma unroll
    for (int q = 0; q < 4; q++) {
        int i = tid + q * 256;
        v[q] = a[off + i] + bsrc[off + i];
        s += v[q];
    }
    float mu = block_sum_256(s) * (1.f / (float)DIM);
    float s2 = 0.f;
#pragma unroll
    for (int q = 0; q < 4; q++) {
        float d = v[q] - mu;
        s2 += d * d;
    }
    float var = block_sum_256(s2) * (1.f / (float)DIM);
    float inv = 1.f / sqrtf(var + 1e-5f);
#pragma unroll
    for (int q = 0; q < 4; q++) {
        int i = tid + q * 256;
        float o = (v[q] - mu) * inv * g[i] + beta[i];
        out[off + i] = o;
        if (RC) outr[off + i] = rna_tf32(o);
    }
}

// ---------------- launch ----------------
static inline float* sym(const void* s) {
    void* p = nullptr;
    cudaGetSymbolAddress(&p, s);
    return (float*)p;
}

extern "C" void kernel_launch(void* const* d_in, const int* in_sizes, int n_in,
                              void* d_out, int out_size) {
    const float* h     = (const float*)d_in[0];
    const float* Wr    = (const float*)d_in[1];
    const float* br    = (const float*)d_in[2];
    const float* Wi    = (const float*)d_in[3];
    const float* bi    = (const float*)d_in[4];
    const float* uw1   = (const float*)d_in[5];
    const float* ub1   = (const float*)d_in[6];
    const float* ug    = (const float*)d_in[7];
    const float* ubeta = (const float*)d_in[8];
    const float* uw2   = (const float*)d_in[9];
    const float* ub2   = (const float*)d_in[10];
    const float* gw1   = (const float*)d_in[11];
    const float* gb1   = (const float*)d_in[12];
    const float* gg    = (const float*)d_in[13];
    const float* gbeta = (const float*)d_in[14];
    const float* gw2   = (const float*)d_in[15];
    const float* gb2   = (const float*)d_in[16];
    const float* m_real= (const float*)d_in[17];
    const float* m_imag= (const float*)d_in[18];
    const float* values= (const float*)d_in[19];
    const float* ow    = (const float*)d_in[20];
    const float* ob    = (const float*)d_in[21];
    const float* n1g   = (const float*)d_in[22];
    const float* n1b   = (const float*)d_in[23];
    const float* n2g   = (const float*)d_in[24];
    const float* n2b   = (const float*)d_in[25];
    const float* fw1   = (const float*)d_in[26];
    const float* fb1   = (const float*)d_in[27];
    const float* fw2   = (const float*)d_in[28];
    const float* fb2   = (const float*)d_in[29];
    float* out = (float*)d_out;

    float* h32  = sym(g_h32);
    float* psi  = sym(g_psi);
    float* reim = sym(g_reim);
    float* attn = sym(g_attn);
    float* t1   = sym(g_t1);
    float* pinit= sym(g_pinit);
    float* gam  = sym(g_gamma);
    float* ctx  = sym(g_ctx);
    float* ctxp = sym(g_ctxpart);
    float* ao   = sym(g_ao);
    float* h1   = sym(g_h1);
    float* h1r  = sym(g_h1r);
    float* ff1  = sym(g_ff1);
    float* ff2  = sym(g_ff2);
    float* WT   = sym(g_WT);
    float* bc   = sym(g_bc);
    float* Mp   = sym(g_Mpack);
    float* uw1T = sym(g_uw1T);
    float* val32= sym(g_val32);
    float* owT  = sym(g_owT);
    float* VOT  = sym(g_VOT);
    float* fw1T = sym(g_fw1T);
    float* fw2T = sym(g_fw2T);

    const int smBIG = (128 + 256) * 128 * 3;      // 147456
    const int sm32  = (128 + 32) * 36 * 4 * 3;    // 69120
    cudaFuncSetAttribute(tgemm_big<false, false>, cudaFuncAttributeMaxDynamicSharedMemorySize, smBIG);
    cudaFuncSetAttribute(tgemm_big<false, true >, cudaFuncAttributeMaxDynamicSharedMemorySize, smBIG);
    cudaFuncSetAttribute(tgemm_big<true,  true >, cudaFuncAttributeMaxDynamicSharedMemorySize, smBIG);
    cudaFuncSetAttribute(tgemm32, cudaFuncAttributeMaxDynamicSharedMemorySize, sm32);

    dim3 thr(256);
    dim3 t328(32, 8);

    // 0) rounded copies
    round_copy_kernel<<<NTOK * DIM / 1024, thr>>>(h, h32);
    round_copy_kernel<<<SS * DIM / 1024, thr>>>(values, val32);

    // 1) weight transposes (+rna)
    transpose_rna_kernel<<<dim3(DH / 32, DIM / 32),  t328>>>(Wr, WT, DIM, DH);
    transpose_rna_kernel<<<dim3(DH / 32, DIM / 32),  t328>>>(Wi, WT + 256 * DIM, DIM, DH);
    pack_bias_kernel<<<1, 256>>>(br, bi, bc);
    transpose_rna_kernel<<<dim3(HIDN / 32, DIM / 32),t328>>>(uw1, uw1T, DIM, HIDN);
    transpose_rna_kernel<<<dim3(DIM / 32, DIM / 32), t328>>>(ow,  owT,  DIM, DIM);
    transpose_rna_kernel<<<dim3(DFF / 32, DIM / 32), t328>>>(fw1, fw1T, DIM, DFF);
    transpose_rna_kernel<<<dim3(DIM / 32, DFF / 32), t328>>>(fw2, fw2T, DFF, DIM);

    // 2) memory normalize -> packed B operand
    memnorm_kernel<<<SS, DH>>>(m_real, m_imag, Mp);

    // 2b) VOT = owT @ values^T  -> [1024, 256], rounded
    tgemm_big<false, true ><<<dim3(1, 8), thr, smBIG>>>(owT, val32, nullptr, VOT, DIM, SS);

    // 3) psi = h @ [Wr|Wi] + [br|bi]  (16384 x 512 x 1024), then normalize
    tgemm_big<false, false><<<dim3(2, 128), thr, smBIG>>>(h32, WT, bc, psi, DIM, 512);
    psinorm_kernel<<<NTOK, 256>>>(psi);

    // 4) uncertainty gate
    tgemm32<<<dim3(1, 128), thr, sm32>>>(h32, uw1T, ub1, t1, DIM, HIDN);
    gate_finish_kernel<<<NTOK / 8, 256>>>(t1, ug, ubeta, uw2, ub2, pinit, 0.95f);

    // 5) ctx mean + gamma gate
    ctx_partial_kernel<<<dim3(DIM / 256, BB, 32), thr>>>(h, ctxp);
    ctx_final_kernel<<<(BB * DIM) / 256, thr>>>(ctxp, ctx);
    gate_kernel<<<BB, 256>>>(ctx, gw1, gb1, gg, gbeta, gw2, gb2, gam, 1.0f);

    // 6) reim = psi @ Mpack^T  (16384 x 512 x 512)
    tgemm_big<false, false><<<dim3(2, 128), thr, smBIG>>>(psi, Mp, nullptr, reim, 512, 512);

    // 7) attention weights
    attn_kernel<<<NTOK, SS>>>(reim, attn, pinit, gam);

    // 8) ao = attn @ VOT^T + ob   (16384 x 1024 x 256)
    tgemm_big<false, false><<<dim3(4, 128), thr, smBIG>>>(attn, VOT, ob, ao, SS, DIM);

    // 9) h1 = LN(h + ao) (+ rounded copy)
    ln_add_kernel<true><<<NTOK, 256>>>(h, ao, n1g, n1b, h1, h1r);

    // 10) FFN
    tgemm_big<true,  true ><<<dim3(16, 128), thr, smBIG>>>(h1r, fw1T, fb1, ff1, DIM, DFF);
    tgemm_big<false, false><<<dim3(4, 128), thr, smBIG>>>(ff1, fw2T, fb2, ff2, DFF, DIM);

    // 11) out = LN(h1 + ff2)
    ln_add_kernel<false><<<NTOK, 256>>>(h1, ff2, n2g, n2b, out, nullptr);
}

// round 6
// speedup vs baseline: 5.3380x; 1.4107x over previous
#include <cuda_runtime.h>
#include <cuda_fp16.h>
#include <math.h>
#include <stdint.h>

// ---------------- problem constants ----------------
#define BB    4
#define NSEQ  4096
#define NTOK  16384        // BB*NSEQ
#define DIM   1024
#define DH    256
#define SS    256
#define HIDN  32
#define DFF   4096

// ---------------- scratch (device globals: allowed) ----------------
// fp32 intermediates
__device__ float g_psi[NTOK * 512];       // [pr | pi] pre-norm
__device__ float g_reim[NTOK * 512];      // [re | im]
__device__ float g_t1[NTOK * HIDN];
__device__ float g_pinit[NTOK];
__device__ float g_gamma[BB];
__device__ float g_ctx[BB * DIM];
__device__ float g_ctxpart[BB * 32 * DIM];
__device__ float g_ao[NTOK * DIM];
__device__ float g_h1[NTOK * DIM];
__device__ float g_ff2[NTOK * DIM];
// fp16 k-permuted GEMM operands
__device__ __half g_h16[NTOK * DIM];
__device__ __half g_psi16[NTOK * 512];
__device__ __half g_attn16[NTOK * SS];
__device__ __half g_h1r16[NTOK * DIM];
__device__ __half g_ff116[NTOK * DFF];
__device__ __half g_WT16[512 * DIM];      // rows 0-255 Wr^T, 256-511 Wi^T
__device__ __half g_uw1T16[HIDN * DIM];
__device__ __half g_Mp16[512 * 512];      // [Mr|Mi] ; [Mi|-Mr]
__device__ __half g_owT16[DIM * DIM];
__device__ __half g_val16[SS * DIM];
__device__ __half g_VOT16[DIM * SS];      // (values@ow)^T
__device__ __half g_fw1T16[DFF * DIM];
__device__ __half g_fw2T16[DIM * DFF];
__device__ float g_bc[512];               // [br | bi]

// ---------------- helpers ----------------
// k-permutation within 32-element blocks: logical k = 16w + 8h + 2t + j
//   -> phys = 8t + 4w + 2h + j.  Same bijection for A and B => exact dot products.
__device__ __forceinline__ int kperm(int k) {
    int r = k & 31;
    int t = (r >> 1) & 3, w = r >> 4, hh = (r >> 3) & 1, j = r & 1;
    return (k & ~31) | (t << 3) | (w << 2) | (hh << 1) | j;
}

__device__ __forceinline__ float gelu_exact(float x) {
    return 0.5f * x * (1.0f + erff(x * 0.7071067811865475f));
}

__device__ __forceinline__ float block_sum_256(float v) {
    __shared__ float sh[8];
    int lane = threadIdx.x & 31, w = threadIdx.x >> 5;
#pragma unroll
    for (int o = 16; o; o >>= 1) v += __shfl_xor_sync(0xffffffffu, v, o);
    if (lane == 0) sh[w] = v;
    __syncthreads();
    float r = (lane < 8) ? sh[lane] : 0.f;
    if (w == 0) {
#pragma unroll
        for (int o = 4; o; o >>= 1) r += __shfl_xor_sync(0xffffffffu, r, o);
        if (lane == 0) sh[0] = r;
    }
    __syncthreads();
    float out = sh[0];
    __syncthreads();
    return out;
}

__device__ __forceinline__ uint32_t smem_u32(const void* p) {
    return (uint32_t)__cvta_generic_to_shared(p);
}
__device__ __forceinline__ void cp16(uint32_t dst, const void* src) {
    asm volatile("cp.async.cg.shared.global [%0], [%1], 16;" :: "r"(dst), "l"(src));
}
__device__ __forceinline__ void cp_commit() { asm volatile("cp.async.commit_group;"); }
template <int N>
__device__ __forceinline__ void cp_wait() { asm volatile("cp.async.wait_group %0;" :: "n"(N)); }

#define MMA_F16(d, a0, a1, a2, a3, b0, b1) \
    asm volatile( \
        "mma.sync.aligned.m16n8k16.row.col.f32.f16.f16.f32 " \
        "{%0,%1,%2,%3}, {%4,%5,%6,%7}, {%8,%9}, {%0,%1,%2,%3};" \
        : "+f"((d)[0]), "+f"((d)[1]), "+f"((d)[2]), "+f"((d)[3]) \
        : "r"(a0), "r"(a1), "r"(a2), "r"(a3), "r"(b0), "r"(b1))

// ============================================================
// BIG fp16 GEMM: 128 x 256 CTA tile, 8 warps, warp tile 64 x 64.
// A:[M,K], B:[N,K] __half, k-permuted. BK=32 (two k16 steps), 3-stage cp.async.
// SMEM rows = 32 halfs = 64 B -> naturally conflict-free for cp16 and LDS.128.
// Each thread's uint4 = its 8 fragment halfs for BOTH k16 steps.
// ============================================================
__device__ __forceinline__ void load_slab_h(char* smem, int stage,
                                            const __half* gA, const __half* gB,
                                            int k0, int K, int tid) {
    constexpr int STAGE = (128 + 256) * 64;
    uint32_t base = smem_u32(smem) + stage * STAGE;
#pragma unroll
    for (int i = 0; i < 2; i++) {                 // A: 128 rows x 4 chunks
        int idx = tid + i * 256;
        int row = idx >> 2, c = idx & 3;
        cp16(base + (uint32_t)(row * 64 + c * 16),
             gA + (size_t)row * K + k0 + c * 8);
    }
    uint32_t bb = base + 128 * 64;
#pragma unroll
    for (int i = 0; i < 4; i++) {                 // B: 256 rows x 4 chunks
        int idx = tid + i * 256;
        int row = idx >> 2, c = idx & 3;
        cp16(bb + (uint32_t)(row * 64 + c * 16),
             gB + (size_t)row * K + k0 + c * 8);
    }
}

template <bool GELU, bool OUTH>
__global__ __launch_bounds__(256, 1) void hgemm_big(
    const __half* __restrict__ A, const __half* __restrict__ B,
    const float* __restrict__ bias, void* __restrict__ Cv,
    int K, int Ntot)
{
    extern __shared__ char smem[];
    constexpr int STAGE = (128 + 256) * 64;

    const int tid = threadIdx.x, wid = tid >> 5, lane = tid & 31;
    const int warp_m = (wid & 1) * 64;
    const int warp_n = (wid >> 1) * 64;
    const int g = lane >> 2, tg = lane & 3;

    const __half* gA = A + (size_t)blockIdx.y * 128 * K;
    const __half* gB = B + (size_t)blockIdx.x * 256 * K;
    const int NS = K >> 5;

    float acc[4][8][4] = {};

    load_slab_h(smem, 0, gA, gB, 0, K, tid);  cp_commit();
    load_slab_h(smem, 1, gA, gB, 32, K, tid); cp_commit();

    for (int ks = 0; ks < NS; ks++) {
        if (ks + 2 < NS) {
            load_slab_h(smem, (ks + 2) % 3, gA, gB, (ks + 2) * 32, K, tid);
            cp_commit();
        }
        int rem = NS - 1 - ks;
        if (rem >= 2) cp_wait<2>();
        else if (rem == 1) cp_wait<1>();
        else cp_wait<0>();
        __syncthreads();

        const __half* As = (const __half*)(smem + (size_t)(ks % 3) * STAGE);
        const __half* Bs = As + 128 * 32;

        uint4 aq[4][2];
#pragma unroll
        for (int mi = 0; mi < 4; mi++) {
            aq[mi][0] = *(const uint4*)(As + (warp_m + mi * 16 + g) * 32 + 8 * tg);
            aq[mi][1] = *(const uint4*)(As + (warp_m + mi * 16 + 8 + g) * 32 + 8 * tg);
        }
        uint4 bq[8];
#pragma unroll
        for (int ni = 0; ni < 8; ni++)
            bq[ni] = *(const uint4*)(Bs + (warp_n + ni * 8 + g) * 32 + 8 * tg);

#pragma unroll
        for (int mi = 0; mi < 4; mi++) {
#pragma unroll
            for (int ni = 0; ni < 8; ni++) {
                MMA_F16(acc[mi][ni], aq[mi][0].x, aq[mi][1].x, aq[mi][0].y, aq[mi][1].y,
                        bq[ni].x, bq[ni].y);
                MMA_F16(acc[mi][ni], aq[mi][0].z, aq[mi][1].z, aq[mi][0].w, aq[mi][1].w,
                        bq[ni].z, bq[ni].w);
            }
        }
        __syncthreads();
    }

    // epilogue
#pragma unroll
    for (int mi = 0; mi < 4; mi++) {
        int r0 = blockIdx.y * 128 + warp_m + mi * 16 + g;
#pragma unroll
        for (int ni = 0; ni < 8; ni++) {
            int col = blockIdx.x * 256 + warp_n + ni * 8 + 2 * tg;
            float bx = 0.f, by = 0.f;
            if (bias) { bx = bias[col]; by = bias[col + 1]; }
#pragma unroll
            for (int half = 0; half < 2; half++) {
                int row = r0 + half * 8;
                float vx = acc[mi][ni][half * 2 + 0] + bx;
                float vy = acc[mi][ni][half * 2 + 1] + by;
                if (GELU) { vx = gelu_exact(vx); vy = gelu_exact(vy); }
                if (OUTH) {
                    __half2 hv = __floats2half2_rn(vx, vy);
                    *(__half2*)((__half*)Cv + (size_t)row * Ntot + kperm(col)) = hv;
                } else {
                    *(float2*)((float*)Cv + (size_t)row * Ntot + col) = make_float2(vx, vy);
                }
            }
        }
    }
}

// ============================================================
// SMALL fp16 GEMM (N = 32): gate projection. 8 warps on m, warp tile 16x32.
// ============================================================
__device__ __forceinline__ void load_slab_h32(char* smem, int stage,
                                              const __half* gA, const __half* gB,
                                              int k0, int K, int tid) {
    constexpr int STAGE = (128 + 32) * 64;
    uint32_t base = smem_u32(smem) + stage * STAGE;
#pragma unroll
    for (int i = 0; i < 2; i++) {
        int idx = tid + i * 256;
        int row = idx >> 2, c = idx & 3;
        cp16(base + (uint32_t)(row * 64 + c * 16),
             gA + (size_t)row * K + k0 + c * 8);
    }
    uint32_t bb = base + 128 * 64;
    if (tid < 128) {
        int row = tid >> 2, c = tid & 3;
        cp16(bb + (uint32_t)(row * 64 + c * 16),
             gB + (size_t)row * K + k0 + c * 8);
    }
}

__global__ __launch_bounds__(256) void hgemm32(
    const __half* __restrict__ A, const __half* __restrict__ B,
    const float* __restrict__ bias, float* __restrict__ C,
    int K, int Ntot)
{
    extern __shared__ char smem[];
    constexpr int STAGE = (128 + 32) * 64;

    const int tid = threadIdx.x, wid = tid >> 5, lane = tid & 31;
    const int warp_m = wid * 16;
    const int g = lane >> 2, tg = lane & 3;

    const __half* gA = A + (size_t)blockIdx.y * 128 * K;
    const __half* gB = B;
    const int NS = K >> 5;

    float acc[4][4] = {};

    load_slab_h32(smem, 0, gA, gB, 0, K, tid);  cp_commit();
    load_slab_h32(smem, 1, gA, gB, 32, K, tid); cp_commit();

    for (int ks = 0; ks < NS; ks++) {
        if (ks + 2 < NS) {
            load_slab_h32(smem, (ks + 2) % 3, gA, gB, (ks + 2) * 32, K, tid);
            cp_commit();
        }
        int rem = NS - 1 - ks;
        if (rem >= 2) cp_wait<2>();
        else if (rem == 1) cp_wait<1>();
        else cp_wait<0>();
        __syncthreads();

        const __half* As = (const __half*)(smem + (size_t)(ks % 3) * STAGE);
        const __half* Bs = As + 128 * 32;

        uint4 alo = *(const uint4*)(As + (warp_m + g) * 32 + 8 * tg);
        uint4 ahi = *(const uint4*)(As + (warp_m + 8 + g) * 32 + 8 * tg);
        uint4 bq[4];
#pragma unroll
        for (int ni = 0; ni < 4; ni++)
            bq[ni] = *(const uint4*)(Bs + (ni * 8 + g) * 32 + 8 * tg);
#pragma unroll
        for (int ni = 0; ni < 4; ni++) {
            MMA_F16(acc[ni], alo.x, ahi.x, alo.y, ahi.y, bq[ni].x, bq[ni].y);
            MMA_F16(acc[ni], alo.z, ahi.z, alo.w, ahi.w, bq[ni].z, bq[ni].w);
        }
        __syncthreads();
    }

#pragma unroll
    for (int ni = 0; ni < 4; ni++) {
        int col = ni * 8 + 2 * tg;
        float bx = bias ? bias[col] : 0.f;
        float by = bias ? bias[col + 1] : 0.f;
        int r0 = blockIdx.y * 128 + warp_m + g;
#pragma unroll
        for (int half = 0; half < 2; half++) {
            int row = r0 + half * 8;
            *(float2*)(C + (size_t)row * Ntot + col) =
                make_float2(acc[ni][half * 2 + 0] + bx, acc[ni][half * 2 + 1] + by);
        }
    }
}

// ---------------- operand-prep / elementwise kernels ----------------
// fp32 -> fp16 k-permuted (flat; row lengths are multiples of 32)
__global__ void cvt16_kernel(const float* __restrict__ in, __half* __restrict__ out) {
    int i = (blockIdx.x * 256 + threadIdx.x) * 4;
    float4 v = *(const float4*)(in + i);
    int p0 = kperm(i);           // pair (i, i+1)
    int p1 = p0 + 8;             // pair (i+2, i+3): t -> t+1 => phys +8
    *(__half2*)(out + p0) = __floats2half2_rn(v.x, v.y);
    *(__half2*)(out + p1) = __floats2half2_rn(v.z, v.w);
}

// fp32 [R,C] -> fp16 [C,R] transposed + k-permuted on the R (new-k) dim
__global__ void transpose16_kernel(const float* __restrict__ in, __half* __restrict__ out,
                                   int R, int C) {
    __shared__ float t[32][33];
    int c0 = blockIdx.x * 32, r0 = blockIdx.y * 32;
    int x = threadIdx.x, y = threadIdx.y;  // 32 x 8
#pragma unroll
    for (int dy = 0; dy < 32; dy += 8)
        t[y + dy][x] = in[(size_t)(r0 + y + dy) * C + c0 + x];
    __syncthreads();
#pragma unroll
    for (int dy = 0; dy < 32; dy += 8)
        out[(size_t)(c0 + y + dy) * R + kperm(r0 + x)] = __float2half_rn(t[x][y + dy]);
}

__global__ void pack_bias_kernel(const float* __restrict__ br, const float* __restrict__ bi,
                                 float* __restrict__ bc) {
    int i = threadIdx.x;
    bc[i] = br[i];
    bc[256 + i] = bi[i];
}

// normalize packed psi rows (512 = [pr|pi]) -> fp16 permuted
__global__ void psinorm_kernel(const float* __restrict__ psi, __half* __restrict__ psi16) {
    size_t base = (size_t)blockIdx.x * 512;
    int tid = threadIdx.x;   // 256
    float a = psi[base + tid], b = psi[base + 256 + tid];
    float tot = block_sum_256(a * a + b * b);
    float inv = 1.f / fmaxf(sqrtf(tot), 1e-12f);
    psi16[base + kperm(tid)] = __float2half_rn(a * inv);
    psi16[base + kperm(256 + tid)] = __float2half_rn(b * inv);
}

// memory normalize -> packed fp16 B operand [512 x 512]
__global__ void memnorm_kernel(const float* __restrict__ mr, const float* __restrict__ mi,
                               __half* __restrict__ Mp) {
    int s = blockIdx.x;    // SS
    int d = threadIdx.x;   // DH
    float a = mr[s * DH + d], b = mi[s * DH + d];
    float tot = block_sum_256(a * a + b * b);
    float inv = 1.f / fmaxf(sqrtf(tot), 1e-12f);
    float ra = a * inv, rb = b * inv;
    Mp[(size_t)s * 512 + kperm(d)] = __float2half_rn(ra);
    Mp[(size_t)s * 512 + kperm(256 + d)] = __float2half_rn(rb);
    Mp[(size_t)(256 + s) * 512 + kperm(d)] = __float2half_rn(rb);
    Mp[(size_t)(256 + s) * 512 + kperm(256 + d)] = __float2half_rn(-ra);
}

// gamma gate (BB=4 rows): fully fused fp32
__global__ void gate_kernel(const float* __restrict__ x,
                            const float* __restrict__ w1, const float* __restrict__ b1,
                            const float* __restrict__ gain, const float* __restrict__ beta,
                            const float* __restrict__ w2, const float* __restrict__ b2,
                            float* __restrict__ out, float scale)
{
    int row = blockIdx.x;
    const float* xr = x + (size_t)row * DIM;
    __shared__ float part[8][HIDN + 1];
    int tid = threadIdx.x;
    int j = tid & 31;
    int t = tid >> 5;
    float s = 0.f;
    int k0 = t * (DIM / 8);
#pragma unroll 4
    for (int i = 0; i < DIM / 8; i++) {
        float xv = xr[k0 + i];
        s += xv * w1[(k0 + i) * HIDN + j];
    }
    part[t][j] = s;
    __syncthreads();
    if (tid < HIDN) {
        float v = 0.f;
#pragma unroll
        for (int q = 0; q < 8; q++) v += part[q][tid];
        v += b1[tid];
        float m = v;
#pragma unroll
        for (int o = 16; o; o >>= 1) m += __shfl_xor_sync(0xffffffffu, m, o);
        m *= (1.f / 32.f);
        float d = v - m;
        float var = d * d;
#pragma unroll
        for (int o = 16; o; o >>= 1) var += __shfl_xor_sync(0xffffffffu, var, o);
        var *= (1.f / 32.f);
        float tn = d / sqrtf(var + 1e-5f) * gain[tid] + beta[tid];
        float si = tn / (1.f + expf(-tn));
        float p = si * w2[tid];
#pragma unroll
        for (int o = 16; o; o >>= 1) p += __shfl_xor_sync(0xffffffffu, p, o);
        if (tid == 0) out[row] = scale / (1.f + expf(-(p + b2[0])));
    }
}

__global__ void gate_finish_kernel(const float* __restrict__ t1,
                                   const float* __restrict__ gain, const float* __restrict__ beta,
                                   const float* __restrict__ w2, const float* __restrict__ b2,
                                   float* __restrict__ out, float scale)
{
    int row = blockIdx.x * 8 + (threadIdx.x >> 5);
    int j = threadIdx.x & 31;
    float v = t1[row * HIDN + j];
    float m = v;
#pragma unroll
    for (int o = 16; o; o >>= 1) m += __shfl_xor_sync(0xffffffffu, m, o);
    m *= (1.f / 32.f);
    float d = v - m;
    float var = d * d;
#pragma unroll
    for (int o = 16; o; o >>= 1) var += __shfl_xor_sync(0xffffffffu, var, o);
    var *= (1.f / 32.f);
    float tn = d / sqrtf(var + 1e-5f) * gain[j] + beta[j];
    float si = tn / (1.f + expf(-tn));
    float p = si * w2[j];
#pragma unroll
    for (int o = 16; o; o >>= 1) p += __shfl_xor_sync(0xffffffffu, p, o);
    if (j == 0) out[row] = scale / (1.f + expf(-(p + b2[0])));
}

__global__ void ctx_partial_kernel(const float* __restrict__ h, float* __restrict__ part) {
    int d = blockIdx.x * 256 + threadIdx.x;
    int b = blockIdx.y;
    int c = blockIdx.z;
    const float* base = h + (((size_t)b * NSEQ + c * 128) * DIM) + d;
    float s = 0.f;
#pragma unroll 4
    for (int n = 0; n < 128; n++) s += base[(size_t)n * DIM];
    part[(size_t)(b * 32 + c) * DIM + d] = s;
}

__global__ void ctx_final_kernel(const float* __restrict__ part, float* __restrict__ ctx) {
    int i = blockIdx.x * 256 + threadIdx.x;
    int b = i >> 10, d = i & 1023;
    float s = 0.f;
#pragma unroll
    for (int c = 0; c < 32; c++) s += part[(size_t)(b * 32 + c) * DIM + d];
    ctx[i] = s * (1.f / (float)NSEQ);
}

// attention weights -> fp16 permuted
__global__ void attn_kernel(const float* __restrict__ reim, __half* __restrict__ attn16,
                            const float* __restrict__ pinit, const float* __restrict__ gamma) {
    int row = blockIdx.x;
    int s = threadIdx.x;
    int b = row >> 12;
    float p = pinit[row] * (1.f - gamma[b]);
    size_t base = (size_t)row * 512;
    float r = reim[base + s], i = reim[base + 256 + s];
    float raw = (1.f - p) * (r * r + i * i) + p * (1.f / (float)DH);
    float tot = block_sum_256(raw);
    attn16[(size_t)row * SS + kperm(s)] = __float2half_rn(raw / (tot + 1e-8f));
}

template <bool RC>
__global__ void ln_add_kernel(const float* __restrict__ a, const float* __restrict__ bsrc,
                              const float* __restrict__ g, const float* __restrict__ beta,
                              float* __restrict__ out, __half* __restrict__ outr) {
    size_t off = (size_t)blockIdx.x * DIM;
    int tid = threadIdx.x;
    float v[4];
    float s = 0.f;
#pragma unroll
    for (int q = 0; q < 4; q++) {
        int i = tid + q * 256;
        v[q] = a[off + i] + bsrc[off + i];
        s += v[q];
    }
    float mu = block_sum_256(s) * (1.f / (float)DIM);
    float s2 = 0.f;
#pragma unroll
    for (int q = 0; q < 4; q++) {
        float d = v[q] - mu;
        s2 += d * d;
    }
    float var = block_sum_256(s2) * (1.f / (float)DIM);
    float inv = 1.f / sqrtf(var + 1e-5f);
#pragma unroll
    for (int q = 0; q < 4; q++) {
        int i = tid + q * 256;
        float o = (v[q] - mu) * inv * g[i] + beta[i];
        out[off + i] = o;
        if (RC) outr[off + kperm(i)] = __float2half_rn(o);
    }
}

// ---------------- launch ----------------
static inline void* symv(const void* s) {
    void* p = nullptr;
    cudaGetSymbolAddress(&p, s);
    return p;
}

extern "C" void kernel_launch(void* const* d_in, const int* in_sizes, int n_in,
                              void* d_out, int out_size) {
    const float* h     = (const float*)d_in[0];
    const float* Wr    = (const float*)d_in[1];
    const float* br    = (const float*)d_in[2];
    const float* Wi    = (const float*)d_in[3];
    const float* bi    = (const float*)d_in[4];
    const float* uw1   = (const float*)d_in[5];
    const float* ub1   = (const float*)d_in[6];
    const float* ug    = (const float*)d_in[7];
    const float* ubeta = (const float*)d_in[8];
    const float* uw2   = (const float*)d_in[9];
    const float* ub2   = (const float*)d_in[10];
    const float* gw1   = (const float*)d_in[11];
    const float* gb1   = (const float*)d_in[12];
    const float* gg    = (const float*)d_in[13];
    const float* gbeta = (const float*)d_in[14];
    const float* gw2   = (const float*)d_in[15];
    const float* gb2   = (const float*)d_in[16];
    const float* m_real= (const float*)d_in[17];
    const float* m_imag= (const float*)d_in[18];
    const float* values= (const float*)d_in[19];
    const float* ow    = (const float*)d_in[20];
    const float* ob    = (const float*)d_in[21];
    const float* n1g   = (const float*)d_in[22];
    const float* n1b   = (const float*)d_in[23];
    const float* n2g   = (const float*)d_in[24];
    const float* n2b   = (const float*)d_in[25];
    const float* fw1   = (const float*)d_in[26];
    const float* fb1   = (const float*)d_in[27];
    const float* fw2   = (const float*)d_in[28];
    const float* fb2   = (const float*)d_in[29];
    float* out = (float*)d_out;

    float* psi   = (float*)symv(g_psi);
    float* reim  = (float*)symv(g_reim);
    float* t1    = (float*)symv(g_t1);
    float* pinit = (float*)symv(g_pinit);
    float* gam   = (float*)symv(g_gamma);
    float* ctx   = (float*)symv(g_ctx);
    float* ctxp  = (float*)symv(g_ctxpart);
    float* ao    = (float*)symv(g_ao);
    float* h1    = (float*)symv(g_h1);
    float* ff2   = (float*)symv(g_ff2);
    float* bc    = (float*)symv(g_bc);
    __half* h16    = (__half*)symv(g_h16);
    __half* psi16  = (__half*)symv(g_psi16);
    __half* attn16 = (__half*)symv(g_attn16);
    __half* h1r16  = (__half*)symv(g_h1r16);
    __half* ff116  = (__half*)symv(g_ff116);
    __half* WT16   = (__half*)symv(g_WT16);
    __half* uw1T16 = (__half*)symv(g_uw1T16);
    __half* Mp16   = (__half*)symv(g_Mp16);
    __half* owT16  = (__half*)symv(g_owT16);
    __half* val16  = (__half*)symv(g_val16);
    __half* VOT16  = (__half*)symv(g_VOT16);
    __half* fw1T16 = (__half*)symv(g_fw1T16);
    __half* fw2T16 = (__half*)symv(g_fw2T16);

    const int smBIG = (128 + 256) * 64 * 3;   // 73728
    const int sm32  = (128 + 32) * 64 * 3;    // 30720
    cudaFuncSetAttribute(hgemm_big<false, false>, cudaFuncAttributeMaxDynamicSharedMemorySize, smBIG);
    cudaFuncSetAttribute(hgemm_big<false, true >, cudaFuncAttributeMaxDynamicSharedMemorySize, smBIG);
    cudaFuncSetAttribute(hgemm_big<true,  true >, cudaFuncAttributeMaxDynamicSharedMemorySize, smBIG);
    cudaFuncSetAttribute(hgemm32, cudaFuncAttributeMaxDynamicSharedMemorySize, sm32);

    dim3 thr(256);
    dim3 t328(32, 8);

    // 0) fp16-permuted conversions of activations / values
    cvt16_kernel<<<NTOK * DIM / 1024, thr>>>(h, h16);
    cvt16_kernel<<<SS * DIM / 1024, thr>>>(values, val16);

    // 1) weight transposes -> fp16 permuted [N, K]
    transpose16_kernel<<<dim3(DH / 32, DIM / 32),  t328>>>(Wr, WT16, DIM, DH);
    transpose16_kernel<<<dim3(DH / 32, DIM / 32),  t328>>>(Wi, WT16 + 256 * DIM, DIM, DH);
    pack_bias_kernel<<<1, 256>>>(br, bi, bc);
    transpose16_kernel<<<dim3(HIDN / 32, DIM / 32),t328>>>(uw1, uw1T16, DIM, HIDN);
    transpose16_kernel<<<dim3(DIM / 32, DIM / 32), t328>>>(ow,  owT16,  DIM, DIM);
    transpose16_kernel<<<dim3(DFF / 32, DIM / 32), t328>>>(fw1, fw1T16, DIM, DFF);
    transpose16_kernel<<<dim3(DIM / 32, DFF / 32), t328>>>(fw2, fw2T16, DFF, DIM);

    // 2) memory normalize -> packed fp16 B operand
    memnorm_kernel<<<SS, DH>>>(m_real, m_imag, Mp16);

    // 2b) VOT = owT @ values^T -> [1024, 256] fp16 permuted
    hgemm_big<false, true ><<<dim3(1, 8), thr, smBIG>>>(owT16, val16, nullptr, VOT16, DIM, SS);

    // 3) psi = h @ [Wr|Wi] + [br|bi], then normalize -> psi16
    hgemm_big<false, false><<<dim3(2, 128), thr, smBIG>>>(h16, WT16, bc, psi, DIM, 512);
    psinorm_kernel<<<NTOK, 256>>>(psi, psi16);

    // 4) uncertainty gate
    hgemm32<<<dim3(1, 128), thr, sm32>>>(h16, uw1T16, ub1, t1, DIM, HIDN);
    gate_finish_kernel<<<NTOK / 8, 256>>>(t1, ug, ubeta, uw2, ub2, pinit, 0.95f);

    // 5) ctx mean + gamma gate
    ctx_partial_kernel<<<dim3(DIM / 256, BB, 32), thr>>>(h, ctxp);
    ctx_final_kernel<<<(BB * DIM) / 256, thr>>>(ctxp, ctx);
    gate_kernel<<<BB, 256>>>(ctx, gw1, gb1, gg, gbeta, gw2, gb2, gam, 1.0f);

    // 6) reim = psi @ Mpack^T  (16384 x 512 x 512)
    hgemm_big<false, false><<<dim3(2, 128), thr, smBIG>>>(psi16, Mp16, nullptr, reim, 512, 512);

    // 7) attention weights -> fp16 permuted
    attn_kernel<<<NTOK, SS>>>(reim, attn16, pinit, gam);

    // 8) ao = attn @ VOT^T + ob   (16384 x 1024 x 256)
    hgemm_big<false, false><<<dim3(4, 128), thr, smBIG>>>(attn16, VOT16, ob, ao, SS, DIM);

    // 9) h1 = LN(h + ao) (+ fp16 permuted copy)
    ln_add_kernel<true><<<NTOK, 256>>>(h, ao, n1g, n1b, h1, h1r16);

    // 10) FFN
    hgemm_big<true,  true ><<<dim3(16, 128), thr, smBIG>>>(h1r16, fw1T16, fb1, ff116, DIM, DFF);
    hgemm_big<false, false><<<dim3(4, 128), thr, smBIG>>>(ff116, fw2T16, fb2, ff2, DFF, DIM);

    // 11) out = LN(h1 + ff2)
    ln_add_kernel<false><<<NTOK, 256>>>(h1, ff2, n2g, n2b, out, nullptr);
}

// round 7
// speedup vs baseline: 5.4727x; 1.0252x over previous
#include <cuda_runtime.h>
#include <cuda_fp16.h>
#include <math.h>
#include <stdint.h>

// ---------------- problem constants ----------------
#define BB    4
#define NSEQ  4096
#define NTOK  16384        // BB*NSEQ
#define DIM   1024
#define DH    256
#define SS    256
#define HIDN  32
#define DFF   4096

// ---------------- scratch (device globals: allowed) ----------------
__device__ float g_t1[NTOK * HIDN];
__device__ float g_pinit[NTOK];
__device__ float g_gamma[BB];
__device__ float g_ctx[BB * DIM];
__device__ float g_ctxpart[BB * 32 * DIM];
__device__ float g_rowss[NTOK];           // per-row sum of squares of psi
__device__ float g_ao[NTOK * DIM];
__device__ float g_h1[NTOK * DIM];
__device__ float g_ff2[NTOK * DIM];
__device__ float g_bc[512];               // [br | bi]
// fp16 k-permuted GEMM operands
__device__ __half g_h16[NTOK * DIM];
__device__ __half g_psi16[NTOK * 512];    // unnormalized [pr|pi]
__device__ __half g_reim16[NTOK * 512];   // [re|im] (x ||psi||)
__device__ __half g_attn16[NTOK * SS];
__device__ __half g_h1r16[NTOK * DIM];
__device__ __half g_ff116[NTOK * DFF];
__device__ __half g_WT16[512 * DIM];      // rows 0-255 Wr^T, 256-511 Wi^T
__device__ __half g_uw1T16[HIDN * DIM];
__device__ __half g_Mp16[512 * 512];      // [Mr|Mi] ; [Mi|-Mr]
__device__ __half g_owT16[DIM * DIM];
__device__ __half g_val16[SS * DIM];
__device__ __half g_VOT16[DIM * SS];      // (values@ow)^T
__device__ __half g_fw1T16[DFF * DIM];
__device__ __half g_fw2T16[DIM * DFF];

// ---------------- helpers ----------------
// k-permutation within 32-element blocks (same bijection for A and B)
__device__ __forceinline__ int kperm(int k) {
    int r = k & 31;
    int t = (r >> 1) & 3, w = r >> 4, hh = (r >> 3) & 1, j = r & 1;
    return (k & ~31) | (t << 3) | (w << 2) | (hh << 1) | j;
}

__device__ __forceinline__ float gelu_exact(float x) {
    return 0.5f * x * (1.0f + erff(x * 0.7071067811865475f));
}

__device__ __forceinline__ float block_sum_256(float v) {
    __shared__ float sh[8];
    int lane = threadIdx.x & 31, w = threadIdx.x >> 5;
#pragma unroll
    for (int o = 16; o; o >>= 1) v += __shfl_xor_sync(0xffffffffu, v, o);
    if (lane == 0) sh[w] = v;
    __syncthreads();
    float r = (lane < 8) ? sh[lane] : 0.f;
    if (w == 0) {
#pragma unroll
        for (int o = 4; o; o >>= 1) r += __shfl_xor_sync(0xffffffffu, r, o);
        if (lane == 0) sh[0] = r;
    }
    __syncthreads();
    float out = sh[0];
    __syncthreads();
    return out;
}

__device__ __forceinline__ uint32_t smem_u32(const void* p) {
    return (uint32_t)__cvta_generic_to_shared(p);
}
__device__ __forceinline__ void cp16(uint32_t dst, const void* src) {
    asm volatile("cp.async.cg.shared.global [%0], [%1], 16;" :: "r"(dst), "l"(src));
}
__device__ __forceinline__ void cp_commit() { asm volatile("cp.async.commit_group;"); }
template <int N>
__device__ __forceinline__ void cp_wait() { asm volatile("cp.async.wait_group %0;" :: "n"(N)); }

#define MMA_F16(d, a0, a1, a2, a3, b0, b1) \
    asm volatile( \
        "mma.sync.aligned.m16n8k16.row.col.f32.f16.f16.f32 " \
        "{%0,%1,%2,%3}, {%4,%5,%6,%7}, {%8,%9}, {%0,%1,%2,%3};" \
        : "+f"((d)[0]), "+f"((d)[1]), "+f"((d)[2]), "+f"((d)[3]) \
        : "r"(a0), "r"(a1), "r"(a2), "r"(a3), "r"(b0), "r"(b1))

// ============================================================
// BIG fp16 GEMM: 128 x 256 CTA tile, 8 warps, warp tile 64 x 64.
// Optional: GELU, fp16 kperm'd output (OUTH), per-row sumsq (SUMSQ).
// ============================================================
__device__ __forceinline__ void load_slab_h(char* smem, int stage,
                                            const __half* gA, const __half* gB,
                                            int k0, int K, int tid) {
    constexpr int STAGE = (128 + 256) * 64;
    uint32_t base = smem_u32(smem) + stage * STAGE;
#pragma unroll
    for (int i = 0; i < 2; i++) {                 // A: 128 rows x 4 chunks
        int idx = tid + i * 256;
        int row = idx >> 2, c = idx & 3;
        cp16(base + (uint32_t)(row * 64 + c * 16),
             gA + (size_t)row * K + k0 + c * 8);
    }
    uint32_t bb = base + 128 * 64;
#pragma unroll
    for (int i = 0; i < 4; i++) {                 // B: 256 rows x 4 chunks
        int idx = tid + i * 256;
        int row = idx >> 2, c = idx & 3;
        cp16(bb + (uint32_t)(row * 64 + c * 16),
             gB + (size_t)row * K + k0 + c * 8);
    }
}

template <bool GELU, bool OUTH, bool SUMSQ>
__global__ __launch_bounds__(256, 1) void hgemm_big(
    const __half* __restrict__ A, const __half* __restrict__ B,
    const float* __restrict__ bias, void* __restrict__ Cv,
    float* __restrict__ rowss, int K, int Ntot)
{
    extern __shared__ char smem[];
    constexpr int STAGE = (128 + 256) * 64;

    const int tid = threadIdx.x, wid = tid >> 5, lane = tid & 31;
    const int warp_m = (wid & 1) * 64;
    const int warp_n = (wid >> 1) * 64;
    const int g = lane >> 2, tg = lane & 3;

    const __half* gA = A + (size_t)blockIdx.y * 128 * K;
    const __half* gB = B + (size_t)blockIdx.x * 256 * K;
    const int NS = K >> 5;

    float acc[4][8][4] = {};

    load_slab_h(smem, 0, gA, gB, 0, K, tid);  cp_commit();
    load_slab_h(smem, 1, gA, gB, 32, K, tid); cp_commit();

    for (int ks = 0; ks < NS; ks++) {
        if (ks + 2 < NS) {
            load_slab_h(smem, (ks + 2) % 3, gA, gB, (ks + 2) * 32, K, tid);
            cp_commit();
        }
        int rem = NS - 1 - ks;
        if (rem >= 2) cp_wait<2>();
        else if (rem == 1) cp_wait<1>();
        else cp_wait<0>();
        __syncthreads();

        const __half* As = (const __half*)(smem + (size_t)(ks % 3) * STAGE);
        const __half* Bs = As + 128 * 32;

        uint4 aq[4][2];
#pragma unroll
        for (int mi = 0; mi < 4; mi++) {
            aq[mi][0] = *(const uint4*)(As + (warp_m + mi * 16 + g) * 32 + 8 * tg);
            aq[mi][1] = *(const uint4*)(As + (warp_m + mi * 16 + 8 + g) * 32 + 8 * tg);
        }
        uint4 bq[8];
#pragma unroll
        for (int ni = 0; ni < 8; ni++)
            bq[ni] = *(const uint4*)(Bs + (warp_n + ni * 8 + g) * 32 + 8 * tg);

#pragma unroll
        for (int mi = 0; mi < 4; mi++) {
#pragma unroll
            for (int ni = 0; ni < 8; ni++) {
                MMA_F16(acc[mi][ni], aq[mi][0].x, aq[mi][1].x, aq[mi][0].y, aq[mi][1].y,
                        bq[ni].x, bq[ni].y);
                MMA_F16(acc[mi][ni], aq[mi][0].z, aq[mi][1].z, aq[mi][0].w, aq[mi][1].w,
                        bq[ni].z, bq[ni].w);
            }
        }
        __syncthreads();
    }

    float ss[4][2];
    if (SUMSQ) {
#pragma unroll
        for (int mi = 0; mi < 4; mi++) { ss[mi][0] = 0.f; ss[mi][1] = 0.f; }
    }

    // epilogue
#pragma unroll
    for (int mi = 0; mi < 4; mi++) {
        int r0 = blockIdx.y * 128 + warp_m + mi * 16 + g;
#pragma unroll
        for (int ni = 0; ni < 8; ni++) {
            int col = blockIdx.x * 256 + warp_n + ni * 8 + 2 * tg;
            float bx = 0.f, by = 0.f;
            if (bias) { bx = bias[col]; by = bias[col + 1]; }
#pragma unroll
            for (int half = 0; half < 2; half++) {
                int row = r0 + half * 8;
                float vx = acc[mi][ni][half * 2 + 0] + bx;
                float vy = acc[mi][ni][half * 2 + 1] + by;
                if (GELU) { vx = gelu_exact(vx); vy = gelu_exact(vy); }
                if (SUMSQ) ss[mi][half] += vx * vx + vy * vy;
                if (OUTH) {
                    __half2 hv = __floats2half2_rn(vx, vy);
                    *(__half2*)((__half*)Cv + (size_t)row * Ntot + kperm(col)) = hv;
                } else {
                    *(float2*)((float*)Cv + (size_t)row * Ntot + col) = make_float2(vx, vy);
                }
            }
        }
    }

    if (SUMSQ) {
        // reduce over tg (lanes 4g..4g+3), then across the 4 n-warps via smem,
        // then ONE atomicAdd per row per CTA (2 CTAs/row total -> deterministic).
        float* red = (float*)smem;   // [128][4]
#pragma unroll
        for (int mi = 0; mi < 4; mi++) {
#pragma unroll
            for (int half = 0; half < 2; half++) {
                float v = ss[mi][half];
                v += __shfl_xor_sync(0xffffffffu, v, 1);
                v += __shfl_xor_sync(0xffffffffu, v, 2);
                if (tg == 0) {
                    int rl = warp_m + mi * 16 + half * 8 + g;
                    red[rl * 4 + (wid >> 1)] = v;
                }
            }
        }
        __syncthreads();
        if (tid < 128) {
            float tot = red[tid * 4] + red[tid * 4 + 1] + red[tid * 4 + 2] + red[tid * 4 + 3];
            atomicAdd(&rowss[blockIdx.y * 128 + tid], tot);
        }
    }
}

// ============================================================
// SMALL fp16 GEMM (N = 32): gate projection.
// ============================================================
__device__ __forceinline__ void load_slab_h32(char* smem, int stage,
                                              const __half* gA, const __half* gB,
                                              int k0, int K, int tid) {
    constexpr int STAGE = (128 + 32) * 64;
    uint32_t base = smem_u32(smem) + stage * STAGE;
#pragma unroll
    for (int i = 0; i < 2; i++) {
        int idx = tid + i * 256;
        int row = idx >> 2, c = idx & 3;
        cp16(base + (uint32_t)(row * 64 + c * 16),
             gA + (size_t)row * K + k0 + c * 8);
    }
    uint32_t bb = base + 128 * 64;
    if (tid < 128) {
        int row = tid >> 2, c = tid & 3;
        cp16(bb + (uint32_t)(row * 64 + c * 16),
             gB + (size_t)row * K + k0 + c * 8);
    }
}

__global__ __launch_bounds__(256) void hgemm32(
    const __half* __restrict__ A, const __half* __restrict__ B,
    const float* __restrict__ bias, float* __restrict__ C,
    int K, int Ntot)
{
    extern __shared__ char smem[];
    constexpr int STAGE = (128 + 32) * 64;

    const int tid = threadIdx.x, wid = tid >> 5, lane = tid & 31;
    const int warp_m = wid * 16;
    const int g = lane >> 2, tg = lane & 3;

    const __half* gA = A + (size_t)blockIdx.y * 128 * K;
    const __half* gB = B;
    const int NS = K >> 5;

    float acc[4][4] = {};

    load_slab_h32(smem, 0, gA, gB, 0, K, tid);  cp_commit();
    load_slab_h32(smem, 1, gA, gB, 32, K, tid); cp_commit();

    for (int ks = 0; ks < NS; ks++) {
        if (ks + 2 < NS) {
            load_slab_h32(smem, (ks + 2) % 3, gA, gB, (ks + 2) * 32, K, tid);
            cp_commit();
        }
        int rem = NS - 1 - ks;
        if (rem >= 2) cp_wait<2>();
        else if (rem == 1) cp_wait<1>();
        else cp_wait<0>();
        __syncthreads();

        const __half* As = (const __half*)(smem + (size_t)(ks % 3) * STAGE);
        const __half* Bs = As + 128 * 32;

        uint4 alo = *(const uint4*)(As + (warp_m + g) * 32 + 8 * tg);
        uint4 ahi = *(const uint4*)(As + (warp_m + 8 + g) * 32 + 8 * tg);
        uint4 bq[4];
#pragma unroll
        for (int ni = 0; ni < 4; ni++)
            bq[ni] = *(const uint4*)(Bs + (ni * 8 + g) * 32 + 8 * tg);
#pragma unroll
        for (int ni = 0; ni < 4; ni++) {
            MMA_F16(acc[ni], alo.x, ahi.x, alo.y, ahi.y, bq[ni].x, bq[ni].y);
            MMA_F16(acc[ni], alo.z, ahi.z, alo.w, ahi.w, bq[ni].z, bq[ni].w);
        }
        __syncthreads();
    }

#pragma unroll
    for (int ni = 0; ni < 4; ni++) {
        int col = ni * 8 + 2 * tg;
        float bx = bias ? bias[col] : 0.f;
        float by = bias ? bias[col + 1] : 0.f;
        int r0 = blockIdx.y * 128 + warp_m + g;
#pragma unroll
        for (int half = 0; half < 2; half++) {
            int row = r0 + half * 8;
            *(float2*)(C + (size_t)row * Ntot + col) =
                make_float2(acc[ni][half * 2 + 0] + bx, acc[ni][half * 2 + 1] + by);
        }
    }
}

// ============================================================
// PREP megakernel: all weight transposes + conversions + memnorm + bias pack
//                  + zeroing of rowss, in ONE launch (job table by block range).
// All blocks 256 threads.
// ============================================================
__device__ __forceinline__ void transpose_tile(const float* in, __half* out,
                                               int R, int C, int lb, int tid) {
    __shared__ float t[32][33];
    int nbx = C >> 5;
    int bx = lb % nbx, by = lb / nbx;
    int c0 = bx * 32, r0 = by * 32;
    int x = tid & 31, y = tid >> 5;  // 32 x 8
#pragma unroll
    for (int dy = 0; dy < 32; dy += 8)
        t[y + dy][x] = in[(size_t)(r0 + y + dy) * C + c0 + x];
    __syncthreads();
#pragma unroll
    for (int dy = 0; dy < 32; dy += 8)
        out[(size_t)(c0 + y + dy) * R + kperm(r0 + x)] = __float2half_rn(t[x][y + dy]);
}

__global__ void prep_kernel(
    const float* __restrict__ Wr, const float* __restrict__ Wi,
    const float* __restrict__ uw1, const float* __restrict__ ow,
    const float* __restrict__ fw1, const float* __restrict__ fw2,
    const float* __restrict__ values,
    const float* __restrict__ mr, const float* __restrict__ mi,
    const float* __restrict__ br, const float* __restrict__ bi,
    __half* __restrict__ WT16, __half* __restrict__ uw1T16,
    __half* __restrict__ owT16, __half* __restrict__ fw1T16,
    __half* __restrict__ fw2T16, __half* __restrict__ val16,
    __half* __restrict__ Mp16, float* __restrict__ bc,
    float* __restrict__ rowss)
{
    int b = blockIdx.x, tid = threadIdx.x;
    // job ranges
    if (b < 16) {                                   // zero rowss (16384 floats)
        ((float4*)rowss)[b * 1024 + tid * 4 / 4] = make_float4(0.f, 0.f, 0.f, 0.f);
        // note: each thread writes one float4: index = b*1024 + tid
        return;
    }
    b -= 16;
    if (b < 256) { transpose_tile(Wr, WT16, DIM, DH, b, tid); return; }
    b -= 256;
    if (b < 256) { transpose_tile(Wi, WT16 + 256 * DIM, DIM, DH, b, tid); return; }
    b -= 256;
    if (b < 32)  { transpose_tile(uw1, uw1T16, DIM, HIDN, b, tid); return; }
    b -= 32;
    if (b < 1024){ transpose_tile(ow, owT16, DIM, DIM, b, tid); return; }
    b -= 1024;
    if (b < 4096){ transpose_tile(fw1, fw1T16, DIM, DFF, b, tid); return; }
    b -= 4096;
    if (b < 4096){ transpose_tile(fw2, fw2T16, DFF, DIM, b, tid); return; }
    b -= 4096;
    if (b < 256) {                                  // val cvt16 (flat kperm)
        int i = (b * 256 + tid) * 4;
        float4 v = *(const float4*)(values + i);
        int p0 = kperm(i);
        *(__half2*)(val16 + p0) = __floats2half2_rn(v.x, v.y);
        *(__half2*)(val16 + p0 + 8) = __floats2half2_rn(v.z, v.w);
        return;
    }
    b -= 256;
    if (b < 256) {                                  // memnorm -> Mp16
        int s = b, d = tid;
        float a = mr[s * DH + d], bb2 = mi[s * DH + d];
        float tot = block_sum_256(a * a + bb2 * bb2);
        float inv = 1.f / fmaxf(sqrtf(tot), 1e-12f);
        float ra = a * inv, rb = bb2 * inv;
        Mp16[(size_t)s * 512 + kperm(d)] = __float2half_rn(ra);
        Mp16[(size_t)s * 512 + kperm(256 + d)] = __float2half_rn(rb);
        Mp16[(size_t)(256 + s) * 512 + kperm(d)] = __float2half_rn(rb);
        Mp16[(size_t)(256 + s) * 512 + kperm(256 + d)] = __float2half_rn(-ra);
        return;
    }
    b -= 256;
    {                                               // pack bias
        bc[tid] = br[tid];
        bc[256 + tid] = bi[tid];
    }
}
#define PREP_BLOCKS (16 + 256 + 256 + 32 + 1024 + 4096 + 4096 + 256 + 256 + 1)

// ---------------- elementwise kernels ----------------
// ctx partial sums AND h -> h16 (kperm) in one pass over h
__global__ void ctx_partial_cvt_kernel(const float* __restrict__ h,
                                       float* __restrict__ part,
                                       __half* __restrict__ h16) {
    int d = blockIdx.x * 256 + threadIdx.x;
    int b = blockIdx.y;
    int c = blockIdx.z;
    int pd = (d & ~31) | kperm(d);   // kperm within 32-block (kperm keeps high bits)
    size_t row0 = ((size_t)b * NSEQ + c * 128);
    const float* base = h + row0 * DIM + d;
    float s = 0.f;
#pragma unroll 4
    for (int n = 0; n < 128; n++) {
        float v = base[(size_t)n * DIM];
        s += v;
        h16[(row0 + n) * DIM + pd] = __float2half_rn(v);
    }
    part[(size_t)(b * 32 + c) * DIM + d] = s;
}

__global__ void ctx_final_kernel(const float* __restrict__ part, float* __restrict__ ctx) {
    int i = blockIdx.x * 256 + threadIdx.x;
    int b = i >> 10, d = i & 1023;
    float s = 0.f;
#pragma unroll
    for (int c = 0; c < 32; c++) s += part[(size_t)(b * 32 + c) * DIM + d];
    ctx[i] = s * (1.f / (float)NSEQ);
}

// gamma gate (BB=4 rows): fully fused fp32
__global__ void gate_kernel(const float* __restrict__ x,
                            const float* __restrict__ w1, const float* __restrict__ b1,
                            const float* __restrict__ gain, const float* __restrict__ beta,
                            const float* __restrict__ w2, const float* __restrict__ b2,
                            float* __restrict__ out, float scale)
{
    int row = blockIdx.x;
    const float* xr = x + (size_t)row * DIM;
    __shared__ float part[8][HIDN + 1];
    int tid = threadIdx.x;
    int j = tid & 31;
    int t = tid >> 5;
    float s = 0.f;
    int k0 = t * (DIM / 8);
#pragma unroll 4
    for (int i = 0; i < DIM / 8; i++) {
        float xv = xr[k0 + i];
        s += xv * w1[(k0 + i) * HIDN + j];
    }
    part[t][j] = s;
    __syncthreads();
    if (tid < HIDN) {
        float v = 0.f;
#pragma unroll
        for (int q = 0; q < 8; q++) v += part[q][tid];
        v += b1[tid];
        float m = v;
#pragma unroll
        for (int o = 16; o; o >>= 1) m += __shfl_xor_sync(0xffffffffu, m, o);
        m *= (1.f / 32.f);
        float d = v - m;
        float var = d * d;
#pragma unroll
        for (int o = 16; o; o >>= 1) var += __shfl_xor_sync(0xffffffffu, var, o);
        var *= (1.f / 32.f);
        float tn = d / sqrtf(var + 1e-5f) * gain[tid] + beta[tid];
        float si = tn / (1.f + expf(-tn));
        float p = si * w2[tid];
#pragma unroll
        for (int o = 16; o; o >>= 1) p += __shfl_xor_sync(0xffffffffu, p, o);
        if (tid == 0) out[row] = scale / (1.f + expf(-(p + b2[0])));
    }
}

__global__ void gate_finish_kernel(const float* __restrict__ t1,
                                   const float* __restrict__ gain, const float* __restrict__ beta,
                                   const float* __restrict__ w2, const float* __restrict__ b2,
                                   float* __restrict__ out, float scale)
{
    int row = blockIdx.x * 8 + (threadIdx.x >> 5);
    int j = threadIdx.x & 31;
    float v = t1[row * HIDN + j];
    float m = v;
#pragma unroll
    for (int o = 16; o; o >>= 1) m += __shfl_xor_sync(0xffffffffu, m, o);
    m *= (1.f / 32.f);
    float d = v - m;
    float var = d * d;
#pragma unroll
    for (int o = 16; o; o >>= 1) var += __shfl_xor_sync(0xffffffffu, var, o);
    var *= (1.f / 32.f);
    float tn = d / sqrtf(var + 1e-5f) * gain[j] + beta[j];
    float si = tn / (1.f + expf(-tn));
    float p = si * w2[j];
#pragma unroll
    for (int o = 16; o; o >>= 1) p += __shfl_xor_sync(0xffffffffu, p, o);
    if (j == 0) out[row] = scale / (1.f + expf(-(p + b2[0])));
}

// attention weights from fp16 reim (physical layout pass-through) + 1/||psi||^2
__global__ void attn_kernel(const __half* __restrict__ reim16, __half* __restrict__ attn16,
                            const float* __restrict__ pinit, const float* __restrict__ gamma,
                            const float* __restrict__ rowss) {
    int row = blockIdx.x;
    int s = threadIdx.x;
    int b = row >> 12;
    float p = pinit[row] * (1.f - gamma[b]);
    float inv_n2 = 1.f / fmaxf(rowss[row], 1e-24f);
    size_t base = (size_t)row * 512;
    float r = __half2float(reim16[base + s]);
    float i = __half2float(reim16[base + 256 + s]);
    float raw = (1.f - p) * (r * r + i * i) * inv_n2 + p * (1.f / (float)DH);
    float tot = block_sum_256(raw);
    attn16[(size_t)row * SS + s] = __float2half_rn(raw / (tot + 1e-8f));
}

template <bool RC>
__global__ void ln_add_kernel(const float* __restrict__ a, const float* __restrict__ bsrc,
                              const float* __restrict__ g, const float* __restrict__ beta,
                              float* __restrict__ out, __half* __restrict__ outr) {
    size_t off = (size_t)blockIdx.x * DIM;
    int tid = threadIdx.x;
    float v[4];
    float s = 0.f;
#pragma unroll
    for (int q = 0; q < 4; q++) {
        int i = tid + q * 256;
        v[q] = a[off + i] + bsrc[off + i];
        s += v[q];
    }
    float mu = block_sum_256(s) * (1.f / (float)DIM);
    float s2 = 0.f;
#pragma unroll
    for (int q = 0; q < 4; q++) {
        float d = v[q] - mu;
        s2 += d * d;
    }
    float var = block_sum_256(s2) * (1.f / (float)DIM);
    float inv = 1.f / sqrtf(var + 1e-5f);
#pragma unroll
    for (int q = 0; q < 4; q++) {
        int i = tid + q * 256;
        float o = (v[q] - mu) * inv * g[i] + beta[i];
        out[off + i] = o;
        if (RC) outr[off + kperm(i)] = __float2half_rn(o);
    }
}

// ---------------- launch ----------------
static inline void* symv(const void* s) {
    void* p = nullptr;
    cudaGetSymbolAddress(&p, s);
    return p;
}

extern "C" void kernel_launch(void* const* d_in, const int* in_sizes, int n_in,
                              void* d_out, int out_size) {
    const float* h     = (const float*)d_in[0];
    const float* Wr    = (const float*)d_in[1];
    const float* br    = (const float*)d_in[2];
    const float* Wi    = (const float*)d_in[3];
    const float* bi    = (const float*)d_in[4];
    const float* uw1   = (const float*)d_in[5];
    const float* ub1   = (const float*)d_in[6];
    const float* ug    = (const float*)d_in[7];
    const float* ubeta = (const float*)d_in[8];
    const float* uw2   = (const float*)d_in[9];
    const float* ub2   = (const float*)d_in[10];
    const float* gw1   = (const float*)d_in[11];
    const float* gb1   = (const float*)d_in[12];
    const float* gg    = (const float*)d_in[13];
    const float* gbeta = (const float*)d_in[14];
    const float* gw2   = (const float*)d_in[15];
    const float* gb2   = (const float*)d_in[16];
    const float* m_real= (const float*)d_in[17];
    const float* m_imag= (const float*)d_in[18];
    const float* values= (const float*)d_in[19];
    const float* ow    = (const float*)d_in[20];
    const float* ob    = (const float*)d_in[21];
    const float* n1g   = (const float*)d_in[22];
    const float* n1b   = (const float*)d_in[23];
    const float* n2g   = (const float*)d_in[24];
    const float* n2b   = (const float*)d_in[25];
    const float* fw1   = (const float*)d_in[26];
    const float* fb1   = (const float*)d_in[27];
    const float* fw2   = (const float*)d_in[28];
    const float* fb2   = (const float*)d_in[29];
    float* out = (float*)d_out;

    float* t1    = (float*)symv(g_t1);
    float* pinit = (float*)symv(g_pinit);
    float* gam   = (float*)symv(g_gamma);
    float* ctx   = (float*)symv(g_ctx);
    float* ctxp  = (float*)symv(g_ctxpart);
    float* rowss = (float*)symv(g_rowss);
    float* ao    = (float*)symv(g_ao);
    float* h1    = (float*)symv(g_h1);
    float* ff2   = (float*)symv(g_ff2);
    float* bc    = (float*)symv(g_bc);
    __half* h16    = (__half*)symv(g_h16);
    __half* psi16  = (__half*)symv(g_psi16);
    __half* reim16 = (__half*)symv(g_reim16);
    __half* attn16 = (__half*)symv(g_attn16);
    __half* h1r16  = (__half*)symv(g_h1r16);
    __half* ff116  = (__half*)symv(g_ff116);
    __half* WT16   = (__half*)symv(g_WT16);
    __half* uw1T16 = (__half*)symv(g_uw1T16);
    __half* Mp16   = (__half*)symv(g_Mp16);
    __half* owT16  = (__half*)symv(g_owT16);
    __half* val16  = (__half*)symv(g_val16);
    __half* VOT16  = (__half*)symv(g_VOT16);
    __half* fw1T16 = (__half*)symv(g_fw1T16);
    __half* fw2T16 = (__half*)symv(g_fw2T16);

    const int smBIG = (128 + 256) * 64 * 3;   // 73728
    const int sm32  = (128 + 32) * 64 * 3;    // 30720
    cudaFuncSetAttribute(hgemm_big<false, false, false>, cudaFuncAttributeMaxDynamicSharedMemorySize, smBIG);
    cudaFuncSetAttribute(hgemm_big<false, true,  false>, cudaFuncAttributeMaxDynamicSharedMemorySize, smBIG);
    cudaFuncSetAttribute(hgemm_big<true,  true,  false>, cudaFuncAttributeMaxDynamicSharedMemorySize, smBIG);
    cudaFuncSetAttribute(hgemm_big<false, true,  true >, cudaFuncAttributeMaxDynamicSharedMemorySize, smBIG);
    cudaFuncSetAttribute(hgemm32, cudaFuncAttributeMaxDynamicSharedMemorySize, sm32);

    dim3 thr(256);

    // [0] all weight prep + rowss zeroing, one launch
    prep_kernel<<<PREP_BLOCKS, thr>>>(Wr, Wi, uw1, ow, fw1, fw2, values,
                                      m_real, m_imag, br, bi,
                                      WT16, uw1T16, owT16, fw1T16, fw2T16,
                                      val16, Mp16, bc, rowss);

    // [1] ctx partials + h -> h16
    ctx_partial_cvt_kernel<<<dim3(DIM / 256, BB, 32), thr>>>(h, ctxp, h16);
    // [2][3] ctx mean + gamma gate
    ctx_final_kernel<<<(BB * DIM) / 256, thr>>>(ctxp, ctx);
    gate_kernel<<<BB, 256>>>(ctx, gw1, gb1, gg, gbeta, gw2, gb2, gam, 1.0f);

    // [4] uncertainty gate projection
    hgemm32<<<dim3(1, 128), thr, sm32>>>(h16, uw1T16, ub1, t1, DIM, HIDN);

    // [5] psi = h @ [Wr|Wi] + [br|bi] -> psi16 (unnormalized) + rowss  (NCU target)
    hgemm_big<false, true, true><<<dim3(2, 128), thr, smBIG>>>(h16, WT16, bc, psi16, rowss, DIM, 512);

    // [6] finish uncertainty gate
    gate_finish_kernel<<<NTOK / 8, 256>>>(t1, ug, ubeta, uw2, ub2, pinit, 0.95f);

    // [7] VOT = owT @ values^T -> [1024, 256] fp16 kperm'd
    hgemm_big<false, true, false><<<dim3(1, 8), thr, smBIG>>>(owT16, val16, nullptr, VOT16, nullptr, DIM, SS);

    // [8] reim = psi @ Mpack^T -> fp16 (scaled by ||psi||)
    hgemm_big<false, true, false><<<dim3(2, 128), thr, smBIG>>>(psi16, Mp16, nullptr, reim16, nullptr, 512, 512);

    // [9] attention weights
    attn_kernel<<<NTOK, SS>>>(reim16, attn16, pinit, gam, rowss);

    // [10] ao = attn @ VOT^T + ob
    hgemm_big<false, false, false><<<dim3(4, 128), thr, smBIG>>>(attn16, VOT16, ob, ao, nullptr, SS, DIM);

    // [11] h1 = LN(h + ao) (+ fp16 kperm'd copy)
    ln_add_kernel<true><<<NTOK, 256>>>(h, ao, n1g, n1b, h1, h1r16);

    // [12][13] FFN
    hgemm_big<true,  true,  false><<<dim3(16, 128), thr, smBIG>>>(h1r16, fw1T16, fb1, ff116, nullptr, DIM, DFF);
    hgemm_big<false, false, false><<<dim3(4, 128), thr, smBIG>>>(ff116, fw2T16, fb2, ff2, nullptr, DFF, DIM);

    // [14] out = LN(h1 + ff2)
    ln_add_kernel<false><<<NTOK, 256>>>(h1, ff2, n2g, n2b, out, nullptr);
}

// round 9
// speedup vs baseline: 5.7255x; 1.0462x over previous
#include <cuda_runtime.h>
#include <cuda_fp16.h>
#include <math.h>
#include <stdint.h>

// ---------------- problem constants ----------------
#define BB    4
#define NSEQ  4096
#define NTOK  16384        // BB*NSEQ
#define DIM   1024
#define DH    256
#define SS    256
#define HIDN  32
#define DFF   4096

// ---------------- scratch (device globals: allowed) ----------------
__device__ float g_pinit[NTOK];
__device__ float g_gamma[BB];
__device__ float g_ctxpart[BB * 32 * DIM];
__device__ float g_rowsspart[2 * NTOK];   // per-CTA psi sum-of-squares partials
__device__ float g_h1[NTOK * DIM];
__device__ float g_bc[512];               // [br | bi]
__device__ float g_VOTpart[4 * DIM * SS]; // split-K fp32 partials
// fp16 k-permuted GEMM operands
__device__ __half g_h16[NTOK * DIM];
__device__ __half g_psi16[NTOK * 512];    // unnormalized [pr|pi]
__device__ __half g_reim16[NTOK * 512];
__device__ __half g_attn16[NTOK * SS];
__device__ __half g_h1r16[NTOK * DIM];
__device__ __half g_ff116[NTOK * DFF];
__device__ __half g_ao16[NTOK * DIM];     // plain fp16
__device__ __half g_ff216[NTOK * DIM];    // plain fp16
__device__ __half g_WT16[512 * DIM];
__device__ __half g_uw1T16[HIDN * DIM];
__device__ __half g_Mp16[512 * 512];
__device__ __half g_owT16[DIM * DIM];
__device__ __half g_val16[SS * DIM];
__device__ __half g_VOT16[DIM * SS];
__device__ __half g_fw1T16[DFF * DIM];
__device__ __half g_fw2T16[DIM * DFF];

// ---------------- helpers ----------------
__device__ __forceinline__ int kperm(int k) {
    int r = k & 31;
    int t = (r >> 1) & 3, w = r >> 4, hh = (r >> 3) & 1, j = r & 1;
    return (k & ~31) | (t << 3) | (w << 2) | (hh << 1) | j;
}

__device__ __forceinline__ float gelu_exact(float x) {
    return 0.5f * x * (1.0f + erff(x * 0.7071067811865475f));
}

__device__ __forceinline__ float block_sum_256(float v) {
    __shared__ float sh[8];
    int lane = threadIdx.x & 31, w = threadIdx.x >> 5;
#pragma unroll
    for (int o = 16; o; o >>= 1) v += __shfl_xor_sync(0xffffffffu, v, o);
    if (lane == 0) sh[w] = v;
    __syncthreads();
    float r = (lane < 8) ? sh[lane] : 0.f;
    if (w == 0) {
#pragma unroll
        for (int o = 4; o; o >>= 1) r += __shfl_xor_sync(0xffffffffu, r, o);
        if (lane == 0) sh[0] = r;
    }
    __syncthreads();
    float out = sh[0];
    __syncthreads();
    return out;
}

__device__ __forceinline__ uint32_t smem_u32(const void* p) {
    return (uint32_t)__cvta_generic_to_shared(p);
}
__device__ __forceinline__ void cp16(uint32_t dst, const void* src) {
    asm volatile("cp.async.cg.shared.global [%0], [%1], 16;" :: "r"(dst), "l"(src));
}
__device__ __forceinline__ void cp_commit() { asm volatile("cp.async.commit_group;"); }
template <int N>
__device__ __forceinline__ void cp_wait() { asm volatile("cp.async.wait_group %0;" :: "n"(N)); }

#define MMA_F16(d, a0, a1, a2, a3, b0, b1) \
    asm volatile( \
        "mma.sync.aligned.m16n8k16.row.col.f32.f16.f16.f32 " \
        "{%0,%1,%2,%3}, {%4,%5,%6,%7}, {%8,%9}, {%0,%1,%2,%3};" \
        : "+f"((d)[0]), "+f"((d)[1]), "+f"((d)[2]), "+f"((d)[3]) \
        : "r"(a0), "r"(a1), "r"(a2), "r"(a3), "r"(b0), "r"(b1))

// ============================================================
// BIG fp16 GEMM: 128 x 256 CTA tile, 8 warps, warp tile 64 x 64.
// OMODE: 0 = fp32 out, 1 = fp16 kperm'd out, 2 = fp16 plain out,
//        3 = fp32 split-K partial (Cv + blockIdx.z * zstride)
// SUMSQ: per-row sum of squares written to rowss[bx*NTOK + row] (no atomics)
// gridDim.z = K-split factor (1 for normal).
// ============================================================
__device__ __forceinline__ void load_slab_h(char* smem, int stage,
                                            const __half* gA, const __half* gB,
                                            int k0, int K, int tid) {
    constexpr int STAGE = (128 + 256) * 64;
    uint32_t base = smem_u32(smem) + stage * STAGE;
#pragma unroll
    for (int i = 0; i < 2; i++) {
        int idx = tid + i * 256;
        int row = idx >> 2, c = idx & 3;
        cp16(base + (uint32_t)(row * 64 + c * 16),
             gA + (size_t)row * K + k0 + c * 8);
    }
    uint32_t bb = base + 128 * 64;
#pragma unroll
    for (int i = 0; i < 4; i++) {
        int idx = tid + i * 256;
        int row = idx >> 2, c = idx & 3;
        cp16(bb + (uint32_t)(row * 64 + c * 16),
             gB + (size_t)row * K + k0 + c * 8);
    }
}

template <bool GELU, int OMODE, bool SUMSQ>
__global__ __launch_bounds__(256, 1) void hgemm_big(
    const __half* __restrict__ A, const __half* __restrict__ B,
    const float* __restrict__ bias, void* __restrict__ Cv,
    float* __restrict__ rowss, int K, int Ntot, size_t zstride)
{
    extern __shared__ char smem[];
    constexpr int STAGE = (128 + 256) * 64;

    const int tid = threadIdx.x, wid = tid >> 5, lane = tid & 31;
    const int warp_m = (wid & 1) * 64;
    const int warp_n = (wid >> 1) * 64;
    const int g = lane >> 2, tg = lane & 3;

    const int kchunk = K / gridDim.z;
    const __half* gA = A + (size_t)blockIdx.y * 128 * K + blockIdx.z * kchunk;
    const __half* gB = B + (size_t)blockIdx.x * 256 * K + blockIdx.z * kchunk;
    const int NS = kchunk >> 5;

    float acc[4][8][4] = {};

    load_slab_h(smem, 0, gA, gB, 0, K, tid);  cp_commit();
    load_slab_h(smem, 1, gA, gB, 32, K, tid); cp_commit();

    for (int ks = 0; ks < NS; ks++) {
        if (ks + 2 < NS) {
            load_slab_h(smem, (ks + 2) % 3, gA, gB, (ks + 2) * 32, K, tid);
            cp_commit();
        }
        int rem = NS - 1 - ks;
        if (rem >= 2) cp_wait<2>();
        else if (rem == 1) cp_wait<1>();
        else cp_wait<0>();
        __syncthreads();

        const __half* As = (const __half*)(smem + (size_t)(ks % 3) * STAGE);
        const __half* Bs = As + 128 * 32;

        uint4 aq[4][2];
#pragma unroll
        for (int mi = 0; mi < 4; mi++) {
            aq[mi][0] = *(const uint4*)(As + (warp_m + mi * 16 + g) * 32 + 8 * tg);
            aq[mi][1] = *(const uint4*)(As + (warp_m + mi * 16 + 8 + g) * 32 + 8 * tg);
        }
        uint4 bq[8];
#pragma unroll
        for (int ni = 0; ni < 8; ni++)
            bq[ni] = *(const uint4*)(Bs + (warp_n + ni * 8 + g) * 32 + 8 * tg);

#pragma unroll
        for (int mi = 0; mi < 4; mi++) {
#pragma unroll
            for (int ni = 0; ni < 8; ni++) {
                MMA_F16(acc[mi][ni], aq[mi][0].x, aq[mi][1].x, aq[mi][0].y, aq[mi][1].y,
                        bq[ni].x, bq[ni].y);
                MMA_F16(acc[mi][ni], aq[mi][0].z, aq[mi][1].z, aq[mi][0].w, aq[mi][1].w,
                        bq[ni].z, bq[ni].w);
            }
        }
        __syncthreads();
    }

    float ss[4][2];
    if (SUMSQ) {
#pragma unroll
        for (int mi = 0; mi < 4; mi++) { ss[mi][0] = 0.f; ss[mi][1] = 0.f; }
    }

#pragma unroll
    for (int mi = 0; mi < 4; mi++) {
        int r0 = blockIdx.y * 128 + warp_m + mi * 16 + g;
#pragma unroll
        for (int ni = 0; ni < 8; ni++) {
            int col = blockIdx.x * 256 + warp_n + ni * 8 + 2 * tg;
            float bx = 0.f, by = 0.f;
            if (OMODE != 3 && bias) { bx = bias[col]; by = bias[col + 1]; }
#pragma unroll
            for (int half = 0; half < 2; half++) {
                int row = r0 + half * 8;
                float vx = acc[mi][ni][half * 2 + 0] + bx;
                float vy = acc[mi][ni][half * 2 + 1] + by;
                if (GELU) { vx = gelu_exact(vx); vy = gelu_exact(vy); }
                if (SUMSQ) ss[mi][half] += vx * vx + vy * vy;
                if (OMODE == 1) {
                    *(__half2*)((__half*)Cv + (size_t)row * Ntot + kperm(col)) =
                        __floats2half2_rn(vx, vy);
                } else if (OMODE == 2) {
                    *(__half2*)((__half*)Cv + (size_t)row * Ntot + col) =
                        __floats2half2_rn(vx, vy);
                } else if (OMODE == 3) {
                    *(float2*)((float*)Cv + blockIdx.z * zstride + (size_t)row * Ntot + col) =
                        make_float2(vx, vy);
                } else {
                    *(float2*)((float*)Cv + (size_t)row * Ntot + col) = make_float2(vx, vy);
                }
            }
        }
    }

    if (SUMSQ) {
        float* red = (float*)smem;   // [128][4]
#pragma unroll
        for (int mi = 0; mi < 4; mi++) {
#pragma unroll
            for (int half = 0; half < 2; half++) {
                float v = ss[mi][half];
                v += __shfl_xor_sync(0xffffffffu, v, 1);
                v += __shfl_xor_sync(0xffffffffu, v, 2);
                if (tg == 0) {
                    int rl = warp_m + mi * 16 + half * 8 + g;
                    red[rl * 4 + (wid >> 1)] = v;
                }
            }
        }
        __syncthreads();
        if (tid < 128) {
            float tot = red[tid * 4] + red[tid * 4 + 1] + red[tid * 4 + 2] + red[tid * 4 + 3];
            rowss[blockIdx.x * NTOK + blockIdx.y * 128 + tid] = tot;
        }
    }
}

// ============================================================
// Gate GEMM (N = 32) with FUSED gate finish: LN(32) -> SiLU -> dot -> sigmoid
// Writes pinit directly; no t1 buffer, no second launch.
// ============================================================
__device__ __forceinline__ void load_slab_h32(char* smem, int stage,
                                              const __half* gA, const __half* gB,
                                              int k0, int K, int tid) {
    constexpr int STAGE = (128 + 32) * 64;
    uint32_t base = smem_u32(smem) + stage * STAGE;
#pragma unroll
    for (int i = 0; i < 2; i++) {
        int idx = tid + i * 256;
        int row = idx >> 2, c = idx & 3;
        cp16(base + (uint32_t)(row * 64 + c * 16),
             gA + (size_t)row * K + k0 + c * 8);
    }
    uint32_t bb = base + 128 * 64;
    if (tid < 128) {
        int row = tid >> 2, c = tid & 3;
        cp16(bb + (uint32_t)(row * 64 + c * 16),
             gB + (size_t)row * K + k0 + c * 8);
    }
}

__global__ __launch_bounds__(256) void hgemm_gate(
    const __half* __restrict__ A, const __half* __restrict__ B,
    const float* __restrict__ b1, const float* __restrict__ gain,
    const float* __restrict__ beta, const float* __restrict__ w2,
    const float* __restrict__ b2, float* __restrict__ pinit,
    float scale, int K)
{
    extern __shared__ char smem[];
    constexpr int STAGE = (128 + 32) * 64;

    const int tid = threadIdx.x, wid = tid >> 5, lane = tid & 31;
    const int warp_m = wid * 16;
    const int g = lane >> 5 ? 0 : (lane >> 2);  // g = lane>>2
    const int gg2 = lane >> 2, tg = lane & 3;

    const __half* gA = A + (size_t)blockIdx.y * 128 * K;
    const __half* gB = B;
    const int NS = K >> 5;

    float acc[4][4] = {};

    load_slab_h32(smem, 0, gA, gB, 0, K, tid);  cp_commit();
    load_slab_h32(smem, 1, gA, gB, 32, K, tid); cp_commit();

    for (int ks = 0; ks < NS; ks++) {
        if (ks + 2 < NS) {
            load_slab_h32(smem, (ks + 2) % 3, gA, gB, (ks + 2) * 32, K, tid);
            cp_commit();
        }
        int rem = NS - 1 - ks;
        if (rem >= 2) cp_wait<2>();
        else if (rem == 1) cp_wait<1>();
        else cp_wait<0>();
        __syncthreads();

        const __half* As = (const __half*)(smem + (size_t)(ks % 3) * STAGE);
        const __half* Bs = As + 128 * 32;

        uint4 alo = *(const uint4*)(As + (warp_m + gg2) * 32 + 8 * tg);
        uint4 ahi = *(const uint4*)(As + (warp_m + 8 + gg2) * 32 + 8 * tg);
        uint4 bq[4];
#pragma unroll
        for (int ni = 0; ni < 4; ni++)
            bq[ni] = *(const uint4*)(Bs + (ni * 8 + gg2) * 32 + 8 * tg);
#pragma unroll
        for (int ni = 0; ni < 4; ni++) {
            MMA_F16(acc[ni], alo.x, ahi.x, alo.y, ahi.y, bq[ni].x, bq[ni].y);
            MMA_F16(acc[ni], alo.z, ahi.z, alo.w, ahi.w, bq[ni].z, bq[ni].w);
        }
        __syncthreads();
    }

    // fused gate finish: per row-half, the 32 outputs live in the 4 threads of
    // this quad (tg = 0..3), 8 values each.
#pragma unroll
    for (int half = 0; half < 2; half++) {
        float vv[8];
        float sum = 0.f;
#pragma unroll
        for (int ni = 0; ni < 4; ni++) {
#pragma unroll
            for (int j = 0; j < 2; j++) {
                int col = ni * 8 + 2 * tg + j;
                float v = acc[ni][half * 2 + j] + b1[col];
                vv[ni * 2 + j] = v;
                sum += v;
            }
        }
        sum += __shfl_xor_sync(0xffffffffu, sum, 1);
        sum += __shfl_xor_sync(0xffffffffu, sum, 2);
        float m = sum * (1.f / 32.f);
        float s2 = 0.f;
#pragma unroll
        for (int q = 0; q < 8; q++) { float d = vv[q] - m; s2 += d * d; }
        s2 += __shfl_xor_sync(0xffffffffu, s2, 1);
        s2 += __shfl_xor_sync(0xffffffffu, s2, 2);
        float inv = rsqrtf(s2 * (1.f / 32.f) + 1e-5f);
        float p = 0.f;
#pragma unroll
        for (int ni = 0; ni < 4; ni++) {
#pragma unroll
            for (int j = 0; j < 2; j++) {
                int col = ni * 8 + 2 * tg + j;
                float tn = (vv[ni * 2 + j] - m) * inv * gain[col] + beta[col];
                float si = tn / (1.f + expf(-tn));
                p += si * w2[col];
            }
        }
        p += __shfl_xor_sync(0xffffffffu, p, 1);
        p += __shfl_xor_sync(0xffffffffu, p, 2);
        if (tg == 0) {
            int row = blockIdx.y * 128 + warp_m + half * 8 + gg2;
            pinit[row] = scale / (1.f + expf(-(p + b2[0])));
        }
    }
}

// ============================================================
// PREP megakernel (job table). All blocks 256 threads.
// ============================================================
__device__ __forceinline__ void transpose_tile(const float* in, __half* out,
                                               int R, int C, int lb, int tid) {
    __shared__ float t[32][33];
    int nbx = C >> 5;
    int bx = lb % nbx, by = lb / nbx;
    int c0 = bx * 32, r0 = by * 32;
    int x = tid & 31, y = tid >> 5;
#pragma unroll
    for (int dy = 0; dy < 32; dy += 8)
        t[y + dy][x] = in[(size_t)(r0 + y + dy) * C + c0 + x];
    __syncthreads();
#pragma unroll
    for (int dy = 0; dy < 32; dy += 8)
        out[(size_t)(c0 + y + dy) * R + kperm(r0 + x)] = __float2half_rn(t[x][y + dy]);
}

__global__ void prep_kernel(
    const float* __restrict__ Wr, const float* __restrict__ Wi,
    const float* __restrict__ uw1, const float* __restrict__ ow,
    const float* __restrict__ fw1, const float* __restrict__ fw2,
    const float* __restrict__ values,
    const float* __restrict__ mr, const float* __restrict__ mi,
    const float* __restrict__ br, const float* __restrict__ bi,
    __half* __restrict__ WT16, __half* __restrict__ uw1T16,
    __half* __restrict__ owT16, __half* __restrict__ fw1T16,
    __half* __restrict__ fw2T16, __half* __restrict__ val16,
    __half* __restrict__ Mp16, float* __restrict__ bc)
{
    int b = blockIdx.x, tid = threadIdx.x;
    if (b < 256) { transpose_tile(Wr, WT16, DIM, DH, b, tid); return; }
    b -= 256;
    if (b < 256) { transpose_tile(Wi, WT16 + 256 * DIM, DIM, DH, b, tid); return; }
    b -= 256;
    if (b < 32)  { transpose_tile(uw1, uw1T16, DIM, HIDN, b, tid); return; }
    b -= 32;
    if (b < 1024){ transpose_tile(ow, owT16, DIM, DIM, b, tid); return; }
    b -= 1024;
    if (b < 4096){ transpose_tile(fw1, fw1T16, DIM, DFF, b, tid); return; }
    b -= 4096;
    if (b < 4096){ transpose_tile(fw2, fw2T16, DFF, DIM, b, tid); return; }
    b -= 4096;
    if (b < 256) {
        int i = (b * 256 + tid) * 4;
        float4 v = *(const float4*)(values + i);
        int p0 = kperm(i);
        *(__half2*)(val16 + p0) = __floats2half2_rn(v.x, v.y);
        *(__half2*)(val16 + p0 + 8) = __floats2half2_rn(v.z, v.w);
        return;
    }
    b -= 256;
    if (b < 256) {
        int s = b, d = tid;
        float a = mr[s * DH + d], bb2 = mi[s * DH + d];
        float tot = block_sum_256(a * a + bb2 * bb2);
        float inv = 1.f / fmaxf(sqrtf(tot), 1e-12f);
        float ra = a * inv, rb = bb2 * inv;
        Mp16[(size_t)s * 512 + kperm(d)] = __float2half_rn(ra);
        Mp16[(size_t)s * 512 + kperm(256 + d)] = __float2half_rn(rb);
        Mp16[(size_t)(256 + s) * 512 + kperm(d)] = __float2half_rn(rb);
        Mp16[(size_t)(256 + s) * 512 + kperm(256 + d)] = __float2half_rn(-ra);
        return;
    }
    {
        bc[tid] = br[tid];
        bc[256 + tid] = bi[tid];
    }
}
#define PREP_BLOCKS (256 + 256 + 32 + 1024 + 4096 + 4096 + 256 + 256 + 1)

// ---------------- elementwise kernels ----------------
__global__ void ctx_partial_cvt_kernel(const float* __restrict__ h,
                                       float* __restrict__ part,
                                       __half* __restrict__ h16) {
    int d = blockIdx.x * 256 + threadIdx.x;
    int b = blockIdx.y;
    int c = blockIdx.z;
    int pd = kperm(d);
    size_t row0 = ((size_t)b * NSEQ + c * 128);
    const float* base = h + row0 * DIM + d;
    float s = 0.f;
#pragma unroll 4
    for (int n = 0; n < 128; n++) {
        float v = base[(size_t)n * DIM];
        s += v;
        h16[(row0 + n) * DIM + pd] = __float2half_rn(v);
    }
    part[(size_t)(b * 32 + c) * DIM + d] = s;
}

// fused: ctx mean + full gamma gate. grid = BB, block = 1024.
__global__ __launch_bounds__(1024) void ctxgate_kernel(
    const float* __restrict__ part,
    const float* __restrict__ w1, const float* __restrict__ b1,
    const float* __restrict__ gain, const float* __restrict__ beta,
    const float* __restrict__ w2, const float* __restrict__ b2,
    float* __restrict__ gamma)
{
    __shared__ float cs[DIM];
    __shared__ float tj[HIDN];
    int b = blockIdx.x, tid = threadIdx.x;
    int w = tid >> 5, l = tid & 31;

    float s = 0.f;
#pragma unroll
    for (int c = 0; c < 32; c++) s += part[(size_t)(b * 32 + c) * DIM + tid];
    cs[tid] = s * (1.f / (float)NSEQ);
    __syncthreads();

    // warp w computes hidden unit w
    float acc = 0.f;
#pragma unroll 8
    for (int it = 0; it < DIM / 32; it++) {
        int d = l + it * 32;
        acc += cs[d] * w1[d * HIDN + w];
    }
#pragma unroll
    for (int o = 16; o; o >>= 1) acc += __shfl_xor_sync(0xffffffffu, acc, o);
    if (l == 0) tj[w] = acc + b1[w];
    __syncthreads();

    if (tid < HIDN) {
        float v = tj[tid];
        float m = v;
#pragma unroll
        for (int o = 16; o; o >>= 1) m += __shfl_xor_sync(0xffffffffu, m, o);
        m *= (1.f / 32.f);
        float d = v - m;
        float var = d * d;
#pragma unroll
        for (int o = 16; o; o >>= 1) var += __shfl_xor_sync(0xffffffffu, var, o);
        var *= (1.f / 32.f);
        float tn = d * rsqrtf(var + 1e-5f) * gain[tid] + beta[tid];
        float si = tn / (1.f + expf(-tn));
        float p = si * w2[tid];
#pragma unroll
        for (int o = 16; o; o >>= 1) p += __shfl_xor_sync(0xffffffffu, p, o);
        if (tid == 0) gamma[b] = 1.f / (1.f + expf(-(p + b2[0])));
    }
}

// combine 4 split-K partials -> fp16 kperm'd VOT
__global__ void cvt_vot_kernel(const float* __restrict__ part, __half* __restrict__ out) {
    int i = (blockIdx.x * 256 + threadIdx.x) * 4;
    const int SZ = DIM * SS;
    float4 a = *(const float4*)(part + i);
    float4 b = *(const float4*)(part + SZ + i);
    float4 c = *(const float4*)(part + 2 * SZ + i);
    float4 d = *(const float4*)(part + 3 * SZ + i);
    float x = a.x + b.x + c.x + d.x;
    float y = a.y + b.y + c.y + d.y;
    float z = a.z + b.z + c.z + d.z;
    float w = a.w + b.w + c.w + d.w;
    int p0 = kperm(i);
    *(__half2*)(out + p0) = __floats2half2_rn(x, y);
    *(__half2*)(out + p0 + 8) = __floats2half2_rn(z, w);
}

// attention weights: warp per row, no block syncs
__global__ void attn_kernel(const __half* __restrict__ reim16, __half* __restrict__ attn16,
                            const float* __restrict__ pinit, const float* __restrict__ gamma,
                            const float* __restrict__ rowssp) {
    int wid = threadIdx.x >> 5, lane = threadIdx.x & 31;
    int row = blockIdx.x * 8 + wid;
    int b = row >> 12;
    float p = pinit[row] * (1.f - gamma[b]);
    float inv_n2 = 1.f / fmaxf(rowssp[row] + rowssp[NTOK + row], 1e-24f);
    float c1 = (1.f - p) * inv_n2, c0 = p * (1.f / (float)DH);
    size_t base = (size_t)row * 512;
    float raw[8];
    float tot = 0.f;
#pragma unroll
    for (int q = 0; q < 8; q++) {
        int s = lane + q * 32;
        float r = __half2float(reim16[base + s]);
        float i = __half2float(reim16[base + 256 + s]);
        raw[q] = c1 * (r * r + i * i) + c0;
        tot += raw[q];
    }
#pragma unroll
    for (int o = 16; o; o >>= 1) tot += __shfl_xor_sync(0xffffffffu, tot, o);
    float inv = 1.f / (tot + 1e-8f);
#pragma unroll
    for (int q = 0; q < 8; q++)
        attn16[(size_t)row * SS + lane + q * 32] = __float2half_rn(raw[q] * inv);
}

// residual + LN; b-input type templated (fp16 saves traffic)
template <bool RC>
__global__ void ln_add_kernel(const float* __restrict__ a, const __half* __restrict__ bsrc,
                              const float* __restrict__ g, const float* __restrict__ beta,
                              float* __restrict__ out, __half* __restrict__ outr) {
    size_t off = (size_t)blockIdx.x * DIM;
    int tid = threadIdx.x;
    float v[4];
    float s = 0.f;
#pragma unroll
    for (int q = 0; q < 4; q++) {
        int i = tid + q * 256;
        v[q] = a[off + i] + __half2float(bsrc[off + i]);
        s += v[q];
    }
    float mu = block_sum_256(s) * (1.f / (float)DIM);
    float s2 = 0.f;
#pragma unroll
    for (int q = 0; q < 4; q++) {
        float d = v[q] - mu;
        s2 += d * d;
    }
    float var = block_sum_256(s2) * (1.f / (float)DIM);
    float inv = rsqrtf(var + 1e-5f);
#pragma unroll
    for (int q = 0; q < 4; q++) {
        int i = tid + q * 256;
        float o = (v[q] - mu) * inv * g[i] + beta[i];
        out[off + i] = o;
        if (RC) outr[off + kperm(i)] = __float2half_rn(o);
    }
}

// ---------------- launch ----------------
static inline void* symv(const void* s) {
    void* p = nullptr;
    cudaGetSymbolAddress(&p, s);
    return p;
}

extern "C" void kernel_launch(void* const* d_in, const int* in_sizes, int n_in,
                              void* d_out, int out_size) {
    const float* h     = (const float*)d_in[0];
    const float* Wr    = (const float*)d_in[1];
    const float* br    = (const float*)d_in[2];
    const float* Wi    = (const float*)d_in[3];
    const float* bi    = (const float*)d_in[4];
    const float* uw1   = (const float*)d_in[5];
    const float* ub1   = (const float*)d_in[6];
    const float* ug    = (const float*)d_in[7];
    const float* ubeta = (const float*)d_in[8];
    const float* uw2   = (const float*)d_in[9];
    const float* ub2   = (const float*)d_in[10];
    const float* gw1   = (const float*)d_in[11];
    const float* gb1   = (const float*)d_in[12];
    const float* gg    = (const float*)d_in[13];
    const float* gbeta = (const float*)d_in[14];
    const float* gw2   = (const float*)d_in[15];
    const float* gb2   = (const float*)d_in[16];
    const float* m_real= (const float*)d_in[17];
    const float* m_imag= (const float*)d_in[18];
    const float* values= (const float*)d_in[19];
    const float* ow    = (const float*)d_in[20];
    const float* ob    = (const float*)d_in[21];
    const float* n1g   = (const float*)d_in[22];
    const float* n1b   = (const float*)d_in[23];
    const float* n2g   = (const float*)d_in[24];
    const float* n2b   = (const float*)d_in[25];
    const float* fw1   = (const float*)d_in[26];
    const float* fb1   = (const float*)d_in[27];
    const float* fw2   = (const float*)d_in[28];
    const float* fb2   = (const float*)d_in[29];
    float* out = (float*)d_out;

    float* pinit = (float*)symv(g_pinit);
    float* gam   = (float*)symv(g_gamma);
    float* ctxp  = (float*)symv(g_ctxpart);
    float* rowssp= (float*)symv(g_rowsspart);
    float* h1    = (float*)symv(g_h1);
    float* bc    = (float*)symv(g_bc);
    float* VOTp  = (float*)symv(g_VOTpart);
    __half* h16    = (__half*)symv(g_h16);
    __half* psi16  = (__half*)symv(g_psi16);
    __half* reim16 = (__half*)symv(g_reim16);
    __half* attn16 = (__half*)symv(g_attn16);
    __half* h1r16  = (__half*)symv(g_h1r16);
    __half* ff116  = (__half*)symv(g_ff116);
    __half* ao16   = (__half*)symv(g_ao16);
    __half* ff216  = (__half*)symv(g_ff216);
    __half* WT16   = (__half*)symv(g_WT16);
    __half* uw1T16 = (__half*)symv(g_uw1T16);
    __half* Mp16   = (__half*)symv(g_Mp16);
    __half* owT16  = (__half*)symv(g_owT16);
    __half* val16  = (__half*)symv(g_val16);
    __half* VOT16  = (__half*)symv(g_VOT16);
    __half* fw1T16 = (__half*)symv(g_fw1T16);
    __half* fw2T16 = (__half*)symv(g_fw2T16);

    const int smBIG = (128 + 256) * 64 * 3;   // 73728
    const int sm32  = (128 + 32) * 64 * 3;    // 30720
    cudaFuncSetAttribute(hgemm_big<false, 0, false>, cudaFuncAttributeMaxDynamicSharedMemorySize, smBIG);
    cudaFuncSetAttribute(hgemm_big<false, 1, false>, cudaFuncAttributeMaxDynamicSharedMemorySize, smBIG);
    cudaFuncSetAttribute(hgemm_big<false, 1, true >, cudaFuncAttributeMaxDynamicSharedMemorySize, smBIG);
    cudaFuncSetAttribute(hgemm_big<false, 2, false>, cudaFuncAttributeMaxDynamicSharedMemorySize, smBIG);
    cudaFuncSetAttribute(hgemm_big<false, 3, false>, cudaFuncAttributeMaxDynamicSharedMemorySize, smBIG);
    cudaFuncSetAttribute(hgemm_big<true,  1, false>, cudaFuncAttributeMaxDynamicSharedMemorySize, smBIG);
    cudaFuncSetAttribute(hgemm_gate, cudaFuncAttributeMaxDynamicSharedMemorySize, sm32);

    dim3 thr(256);

    // [0] weight prep (one launch)
    prep_kernel<<<PREP_BLOCKS, thr>>>(Wr, Wi, uw1, ow, fw1, fw2, values,
                                      m_real, m_imag, br, bi,
                                      WT16, uw1T16, owT16, fw1T16, fw2T16,
                                      val16, Mp16, bc);

    // [1] ctx partials + h -> h16
    ctx_partial_cvt_kernel<<<dim3(DIM / 256, BB, 32), thr>>>(h, ctxp, h16);

    // [2] fused ctx mean + gamma gate
    ctxgate_kernel<<<BB, 1024>>>(ctxp, gw1, gb1, gg, gbeta, gw2, gb2, gam);

    // [3] uncertainty gate: GEMM + fused finish -> pinit
    hgemm_gate<<<dim3(1, 128), thr, sm32>>>(h16, uw1T16, ub1, ug, ubeta, uw2, ub2,
                                            pinit, 0.95f, DIM);

    // [4] psi = h @ [Wr|Wi] + [br|bi] -> psi16 + rowss partials
    hgemm_big<false, 1, true><<<dim3(2, 128), thr, smBIG>>>(
        h16, WT16, bc, psi16, rowssp, DIM, 512, 0);

    // [5] VOT = owT @ values^T, split-K x4 -> fp32 partials
    hgemm_big<false, 3, false><<<dim3(1, 8, 4), thr, smBIG>>>(
        owT16, val16, nullptr, VOTp, nullptr, DIM, SS, (size_t)DIM * SS);

    // [6] combine partials -> VOT16
    cvt_vot_kernel<<<DIM * SS / 1024, thr>>>(VOTp, VOT16);

    // [7] reim = psi @ Mpack^T
    hgemm_big<false, 1, false><<<dim3(2, 128), thr, smBIG>>>(
        psi16, Mp16, nullptr, reim16, nullptr, 512, 512, 0);

    // [8] attention weights (warp per row)
    attn_kernel<<<NTOK / 8, thr>>>(reim16, attn16, pinit, gam, rowssp);

    // [9] ao = attn @ VOT^T + ob   (fp16 plain out)
    hgemm_big<false, 2, false><<<dim3(4, 128), thr, smBIG>>>(
        attn16, VOT16, ob, ao16, nullptr, SS, DIM, 0);

    // [10] h1 = LN(h + ao) (+ fp16 kperm'd copy)
    ln_add_kernel<true><<<NTOK, 256>>>(h, ao16, n1g, n1b, h1, h1r16);

    // [11][12] FFN (ff2 fp16 plain out)
    hgemm_big<true,  1, false><<<dim3(16, 128), thr, smBIG>>>(
        h1r16, fw1T16, fb1, ff116, nullptr, DIM, DFF, 0);
    hgemm_big<false, 2, false><<<dim3(4, 128), thr, smBIG>>>(
        ff116, fw2T16, fb2, ff216, nullptr, DFF, DIM, 0);

    // [13] out = LN(h1 + ff2)
    ln_add_kernel<false><<<NTOK, 256>>>(h1, ff216, n2g, n2b, out, nullptr);
}

// round 10
// speedup vs baseline: 6.3066x; 1.1015x over previous
#include <cuda_runtime.h>
#include <cuda_fp16.h>
#include <math.h>
#include <stdint.h>

// ---------------- problem constants ----------------
#define BB    4
#define NSEQ  4096
#define NTOK  16384        // BB*NSEQ
#define DIM   1024
#define DH    256
#define SS    256
#define HIDN  32
#define DFF   4096

// ---------------- scratch (device globals: allowed) ----------------
__device__ float g_pinit[NTOK];
__device__ float g_gamma[BB];
__device__ float g_ctxpart[BB * 32 * DIM];
__device__ float g_rowsspart[2 * NTOK];   // per-CTA psi sum-of-squares partials
__device__ float g_bc[512];               // [br | bi]
__device__ float g_VOTpart[4 * DIM * SS]; // split-K fp32 partials
// fp16 GEMM operands (kperm'd where used as GEMM input)
__device__ __half g_h16[NTOK * DIM];
__device__ __half g_psi16[NTOK * 512];    // unnormalized [pr|pi]
__device__ __half g_reim16[NTOK * 512];
__device__ __half g_attn16[NTOK * SS];
__device__ __half g_h1r16[NTOK * DIM];    // h1, fp16, kperm'd (only copy of h1)
__device__ __half g_ff116[NTOK * DFF];
__device__ __half g_ao16[NTOK * DIM];     // plain fp16
__device__ __half g_ff216[NTOK * DIM];    // plain fp16
__device__ __half g_WT16[512 * DIM];
__device__ __half g_uw1T16[HIDN * DIM];
__device__ __half g_Mp16[512 * 512];
__device__ __half g_owT16[DIM * DIM];
__device__ __half g_val16[SS * DIM];
__device__ __half g_VOT16[DIM * SS];
__device__ __half g_fw1T16[DFF * DIM];
__device__ __half g_fw2T16[DIM * DFF];

// ---------------- helpers ----------------
__device__ __forceinline__ int kperm(int k) {
    int r = k & 31;
    int t = (r >> 1) & 3, w = r >> 4, hh = (r >> 3) & 1, j = r & 1;
    return (k & ~31) | (t << 3) | (w << 2) | (hh << 1) | j;
}

__device__ __forceinline__ float gelu_exact(float x) {
    return 0.5f * x * (1.0f + erff(x * 0.7071067811865475f));
}

__device__ __forceinline__ float block_sum_256(float v) {
    __shared__ float sh[8];
    int lane = threadIdx.x & 31, w = threadIdx.x >> 5;
#pragma unroll
    for (int o = 16; o; o >>= 1) v += __shfl_xor_sync(0xffffffffu, v, o);
    if (lane == 0) sh[w] = v;
    __syncthreads();
    float r = (lane < 8) ? sh[lane] : 0.f;
    if (w == 0) {
#pragma unroll
        for (int o = 4; o; o >>= 1) r += __shfl_xor_sync(0xffffffffu, r, o);
        if (lane == 0) sh[0] = r;
    }
    __syncthreads();
    float out = sh[0];
    __syncthreads();
    return out;
}

__device__ __forceinline__ uint32_t smem_u32(const void* p) {
    return (uint32_t)__cvta_generic_to_shared(p);
}
__device__ __forceinline__ void cp16(uint32_t dst, const void* src) {
    asm volatile("cp.async.cg.shared.global [%0], [%1], 16;" :: "r"(dst), "l"(src));
}
__device__ __forceinline__ void cp_commit() { asm volatile("cp.async.commit_group;"); }
template <int N>
__device__ __forceinline__ void cp_wait() { asm volatile("cp.async.wait_group %0;" :: "n"(N)); }

#define MMA_F16(d, a0, a1, a2, a3, b0, b1) \
    asm volatile( \
        "mma.sync.aligned.m16n8k16.row.col.f32.f16.f16.f32 " \
        "{%0,%1,%2,%3}, {%4,%5,%6,%7}, {%8,%9}, {%0,%1,%2,%3};" \
        : "+f"((d)[0]), "+f"((d)[1]), "+f"((d)[2]), "+f"((d)[3]) \
        : "r"(a0), "r"(a1), "r"(a2), "r"(a3), "r"(b0), "r"(b1))

// ============================================================
// BIG fp16 GEMM: 128 x BN CTA tile (BN = 256 or 128), 8 warps.
// Warp tile: 64 x (BN/4).  OMODE: 0 fp32, 1 fp16 kperm, 2 fp16 plain,
// 3 fp32 split-K partial.  SUMSQ: per-row sumsq partials (no atomics).
// ============================================================
template <int BN>
__device__ __forceinline__ void load_slab_h(char* smem, int stage,
                                            const __half* gA, const __half* gB,
                                            int k0, int K, int tid) {
    constexpr int STAGE = (128 + BN) * 64;
    uint32_t base = smem_u32(smem) + stage * STAGE;
#pragma unroll
    for (int i = 0; i < 2; i++) {
        int idx = tid + i * 256;
        int row = idx >> 2, c = idx & 3;
        cp16(base + (uint32_t)(row * 64 + c * 16),
             gA + (size_t)row * K + k0 + c * 8);
    }
    uint32_t bb = base + 128 * 64;
#pragma unroll
    for (int i = 0; i < BN / 64; i++) {
        int idx = tid + i * 256;
        int row = idx >> 2, c = idx & 3;
        cp16(bb + (uint32_t)(row * 64 + c * 16),
             gB + (size_t)row * K + k0 + c * 8);
    }
}

template <int BN, bool GELU, int OMODE, bool SUMSQ>
__global__ __launch_bounds__(256, 1) void hgemm_big(
    const __half* __restrict__ A, const __half* __restrict__ B,
    const float* __restrict__ bias, void* __restrict__ Cv,
    float* __restrict__ rowss, int K, int Ntot, size_t zstride)
{
    extern __shared__ char smem[];
    constexpr int STAGE = (128 + BN) * 64;
    constexpr int NI = BN / 32;      // n8 atoms per warp

    const int tid = threadIdx.x, wid = tid >> 5, lane = tid & 31;
    const int warp_m = (wid & 1) * 64;
    const int warp_n = (wid >> 1) * (BN / 4);
    const int g = lane >> 2, tg = lane & 3;

    const int kchunk = K / gridDim.z;
    const __half* gA = A + (size_t)blockIdx.y * 128 * K + blockIdx.z * kchunk;
    const __half* gB = B + (size_t)blockIdx.x * BN * K + blockIdx.z * kchunk;
    const int NS = kchunk >> 5;

    float acc[4][NI][4] = {};

    load_slab_h<BN>(smem, 0, gA, gB, 0, K, tid);  cp_commit();
    load_slab_h<BN>(smem, 1, gA, gB, 32, K, tid); cp_commit();

    for (int ks = 0; ks < NS; ks++) {
        if (ks + 2 < NS) {
            load_slab_h<BN>(smem, (ks + 2) % 3, gA, gB, (ks + 2) * 32, K, tid);
            cp_commit();
        }
        int rem = NS - 1 - ks;
        if (rem >= 2) cp_wait<2>();
        else if (rem == 1) cp_wait<1>();
        else cp_wait<0>();
        __syncthreads();

        const __half* As = (const __half*)(smem + (size_t)(ks % 3) * STAGE);
        const __half* Bs = As + 128 * 32;

        uint4 aq[4][2];
#pragma unroll
        for (int mi = 0; mi < 4; mi++) {
            aq[mi][0] = *(const uint4*)(As + (warp_m + mi * 16 + g) * 32 + 8 * tg);
            aq[mi][1] = *(const uint4*)(As + (warp_m + mi * 16 + 8 + g) * 32 + 8 * tg);
        }
        uint4 bq[NI];
#pragma unroll
        for (int ni = 0; ni < NI; ni++)
            bq[ni] = *(const uint4*)(Bs + (warp_n + ni * 8 + g) * 32 + 8 * tg);

#pragma unroll
        for (int mi = 0; mi < 4; mi++) {
#pragma unroll
            for (int ni = 0; ni < NI; ni++) {
                MMA_F16(acc[mi][ni], aq[mi][0].x, aq[mi][1].x, aq[mi][0].y, aq[mi][1].y,
                        bq[ni].x, bq[ni].y);
                MMA_F16(acc[mi][ni], aq[mi][0].z, aq[mi][1].z, aq[mi][0].w, aq[mi][1].w,
                        bq[ni].z, bq[ni].w);
            }
        }
        __syncthreads();
    }

    float ss[4][2];
    if (SUMSQ) {
#pragma unroll
        for (int mi = 0; mi < 4; mi++) { ss[mi][0] = 0.f; ss[mi][1] = 0.f; }
    }

#pragma unroll
    for (int mi = 0; mi < 4; mi++) {
        int r0 = blockIdx.y * 128 + warp_m + mi * 16 + g;
#pragma unroll
        for (int ni = 0; ni < NI; ni++) {
            int col = blockIdx.x * BN + warp_n + ni * 8 + 2 * tg;
            float bx = 0.f, by = 0.f;
            if (OMODE != 3 && bias) { bx = bias[col]; by = bias[col + 1]; }
#pragma unroll
            for (int half = 0; half < 2; half++) {
                int row = r0 + half * 8;
                float vx = acc[mi][ni][half * 2 + 0] + bx;
                float vy = acc[mi][ni][half * 2 + 1] + by;
                if (GELU) { vx = gelu_exact(vx); vy = gelu_exact(vy); }
                if (SUMSQ) ss[mi][half] += vx * vx + vy * vy;
                if (OMODE == 1) {
                    *(__half2*)((__half*)Cv + (size_t)row * Ntot + kperm(col)) =
                        __floats2half2_rn(vx, vy);
                } else if (OMODE == 2) {
                    *(__half2*)((__half*)Cv + (size_t)row * Ntot + col) =
                        __floats2half2_rn(vx, vy);
                } else if (OMODE == 3) {
                    *(float2*)((float*)Cv + blockIdx.z * zstride + (size_t)row * Ntot + col) =
                        make_float2(vx, vy);
                } else {
                    *(float2*)((float*)Cv + (size_t)row * Ntot + col) = make_float2(vx, vy);
                }
            }
        }
    }

    if (SUMSQ) {
        float* red = (float*)smem;   // [128][4]
#pragma unroll
        for (int mi = 0; mi < 4; mi++) {
#pragma unroll
            for (int half = 0; half < 2; half++) {
                float v = ss[mi][half];
                v += __shfl_xor_sync(0xffffffffu, v, 1);
                v += __shfl_xor_sync(0xffffffffu, v, 2);
                if (tg == 0) {
                    int rl = warp_m + mi * 16 + half * 8 + g;
                    red[rl * 4 + (wid >> 1)] = v;
                }
            }
        }
        __syncthreads();
        if (tid < 128) {
            float tot = red[tid * 4] + red[tid * 4 + 1] + red[tid * 4 + 2] + red[tid * 4 + 3];
            rowss[blockIdx.x * NTOK + blockIdx.y * 128 + tid] = tot;
        }
    }
}

// ============================================================
// Gate GEMM (N = 32) with FUSED finish, 6-stage pipeline (DRAM-latency bound).
// ============================================================
__device__ __forceinline__ void load_slab_h32(char* smem, int stage,
                                              const __half* gA, const __half* gB,
                                              int k0, int K, int tid) {
    constexpr int STAGE = (128 + 32) * 64;
    uint32_t base = smem_u32(smem) + stage * STAGE;
#pragma unroll
    for (int i = 0; i < 2; i++) {
        int idx = tid + i * 256;
        int row = idx >> 2, c = idx & 3;
        cp16(base + (uint32_t)(row * 64 + c * 16),
             gA + (size_t)row * K + k0 + c * 8);
    }
    uint32_t bb = base + 128 * 64;
    if (tid < 128) {
        int row = tid >> 2, c = tid & 3;
        cp16(bb + (uint32_t)(row * 64 + c * 16),
             gB + (size_t)row * K + k0 + c * 8);
    }
}

__global__ __launch_bounds__(256) void hgemm_gate(
    const __half* __restrict__ A, const __half* __restrict__ B,
    const float* __restrict__ b1, const float* __restrict__ gain,
    const float* __restrict__ beta, const float* __restrict__ w2,
    const float* __restrict__ b2, float* __restrict__ pinit,
    float scale, int K)
{
    extern __shared__ char smem[];
    constexpr int STAGE = (128 + 32) * 64;

    const int tid = threadIdx.x, wid = tid >> 5, lane = tid & 31;
    const int warp_m = wid * 16;
    const int gg2 = lane >> 2, tg = lane & 3;

    const __half* gA = A + (size_t)blockIdx.y * 128 * K;
    const __half* gB = B;
    const int NS = K >> 5;   // 32

    float acc[4][4] = {};

#pragma unroll
    for (int s = 0; s < 5; s++) {
        load_slab_h32(smem, s, gA, gB, s * 32, K, tid);
        cp_commit();
    }

    for (int ks = 0; ks < NS; ks++) {
        if (ks + 5 < NS) {
            load_slab_h32(smem, (ks + 5) % 6, gA, gB, (ks + 5) * 32, K, tid);
            cp_commit();
        }
        int rem = NS - 1 - ks;
        if (rem >= 5) cp_wait<5>();
        else if (rem == 4) cp_wait<4>();
        else if (rem == 3) cp_wait<3>();
        else if (rem == 2) cp_wait<2>();
        else if (rem == 1) cp_wait<1>();
        else cp_wait<0>();
        __syncthreads();

        const __half* As = (const __half*)(smem + (size_t)(ks % 6) * STAGE);
        const __half* Bs = As + 128 * 32;

        uint4 alo = *(const uint4*)(As + (warp_m + gg2) * 32 + 8 * tg);
        uint4 ahi = *(const uint4*)(As + (warp_m + 8 + gg2) * 32 + 8 * tg);
        uint4 bq[4];
#pragma unroll
        for (int ni = 0; ni < 4; ni++)
            bq[ni] = *(const uint4*)(Bs + (ni * 8 + gg2) * 32 + 8 * tg);
#pragma unroll
        for (int ni = 0; ni < 4; ni++) {
            MMA_F16(acc[ni], alo.x, ahi.x, alo.y, ahi.y, bq[ni].x, bq[ni].y);
            MMA_F16(acc[ni], alo.z, ahi.z, alo.w, ahi.w, bq[ni].z, bq[ni].w);
        }
        __syncthreads();
    }

    // fused gate finish
#pragma unroll
    for (int half = 0; half < 2; half++) {
        float vv[8];
        float sum = 0.f;
#pragma unroll
        for (int ni = 0; ni < 4; ni++) {
#pragma unroll
            for (int j = 0; j < 2; j++) {
                int col = ni * 8 + 2 * tg + j;
                float v = acc[ni][half * 2 + j] + b1[col];
                vv[ni * 2 + j] = v;
                sum += v;
            }
        }
        sum += __shfl_xor_sync(0xffffffffu, sum, 1);
        sum += __shfl_xor_sync(0xffffffffu, sum, 2);
        float m = sum * (1.f / 32.f);
        float s2 = 0.f;
#pragma unroll
        for (int q = 0; q < 8; q++) { float d = vv[q] - m; s2 += d * d; }
        s2 += __shfl_xor_sync(0xffffffffu, s2, 1);
        s2 += __shfl_xor_sync(0xffffffffu, s2, 2);
        float inv = rsqrtf(s2 * (1.f / 32.f) + 1e-5f);
        float p = 0.f;
#pragma unroll
        for (int ni = 0; ni < 4; ni++) {
#pragma unroll
            for (int j = 0; j < 2; j++) {
                int col = ni * 8 + 2 * tg + j;
                float tn = (vv[ni * 2 + j] - m) * inv * gain[col] + beta[col];
                float si = tn / (1.f + expf(-tn));
                p += si * w2[col];
            }
        }
        p += __shfl_xor_sync(0xffffffffu, p, 1);
        p += __shfl_xor_sync(0xffffffffu, p, 2);
        if (tg == 0) {
            int row = blockIdx.y * 128 + warp_m + half * 8 + gg2;
            pinit[row] = scale / (1.f + expf(-(p + b2[0])));
        }
    }
}

// ============================================================
// PREP megakernel (job table). All blocks 256 threads.
// ============================================================
__device__ __forceinline__ void transpose_tile(const float* in, __half* out,
                                               int R, int C, int lb, int tid) {
    __shared__ float t[32][33];
    int nbx = C >> 5;
    int bx = lb % nbx, by = lb / nbx;
    int c0 = bx * 32, r0 = by * 32;
    int x = tid & 31, y = tid >> 5;
#pragma unroll
    for (int dy = 0; dy < 32; dy += 8)
        t[y + dy][x] = in[(size_t)(r0 + y + dy) * C + c0 + x];
    __syncthreads();
#pragma unroll
    for (int dy = 0; dy < 32; dy += 8)
        out[(size_t)(c0 + y + dy) * R + kperm(r0 + x)] = __float2half_rn(t[x][y + dy]);
}

__global__ void prep_kernel(
    const float* __restrict__ Wr, const float* __restrict__ Wi,
    const float* __restrict__ uw1, const float* __restrict__ ow,
    const float* __restrict__ fw1, const float* __restrict__ fw2,
    const float* __restrict__ values,
    const float* __restrict__ mr, const float* __restrict__ mi,
    const float* __restrict__ br, const float* __restrict__ bi,
    __half* __restrict__ WT16, __half* __restrict__ uw1T16,
    __half* __restrict__ owT16, __half* __restrict__ fw1T16,
    __half* __restrict__ fw2T16, __half* __restrict__ val16,
    __half* __restrict__ Mp16, float* __restrict__ bc)
{
    int b = blockIdx.x, tid = threadIdx.x;
    if (b < 256) { transpose_tile(Wr, WT16, DIM, DH, b, tid); return; }
    b -= 256;
    if (b < 256) { transpose_tile(Wi, WT16 + 256 * DIM, DIM, DH, b, tid); return; }
    b -= 256;
    if (b < 32)  { transpose_tile(uw1, uw1T16, DIM, HIDN, b, tid); return; }
    b -= 32;
    if (b < 1024){ transpose_tile(ow, owT16, DIM, DIM, b, tid); return; }
    b -= 1024;
    if (b < 4096){ transpose_tile(fw1, fw1T16, DIM, DFF, b, tid); return; }
    b -= 4096;
    if (b < 4096){ transpose_tile(fw2, fw2T16, DFF, DIM, b, tid); return; }
    b -= 4096;
    if (b < 256) {
        int i = (b * 256 + tid) * 4;
        float4 v = *(const float4*)(values + i);
        int p0 = kperm(i);
        *(__half2*)(val16 + p0) = __floats2half2_rn(v.x, v.y);
        *(__half2*)(val16 + p0 + 8) = __floats2half2_rn(v.z, v.w);
        return;
    }
    b -= 256;
    if (b < 256) {
        int s = b, d = tid;
        float a = mr[s * DH + d], bb2 = mi[s * DH + d];
        float tot = block_sum_256(a * a + bb2 * bb2);
        float inv = 1.f / fmaxf(sqrtf(tot), 1e-12f);
        float ra = a * inv, rb = bb2 * inv;
        Mp16[(size_t)s * 512 + kperm(d)] = __float2half_rn(ra);
        Mp16[(size_t)s * 512 + kperm(256 + d)] = __float2half_rn(rb);
        Mp16[(size_t)(256 + s) * 512 + kperm(d)] = __float2half_rn(rb);
        Mp16[(size_t)(256 + s) * 512 + kperm(256 + d)] = __float2half_rn(-ra);
        return;
    }
    {
        bc[tid] = br[tid];
        bc[256 + tid] = bi[tid];
    }
}
#define PREP_BLOCKS (256 + 256 + 32 + 1024 + 4096 + 4096 + 256 + 256 + 1)

// ---------------- elementwise kernels ----------------
__global__ void ctx_partial_cvt_kernel(const float* __restrict__ h,
                                       float* __restrict__ part,
                                       __half* __restrict__ h16) {
    int d = blockIdx.x * 256 + threadIdx.x;
    int b = blockIdx.y;
    int c = blockIdx.z;
    int pd = kperm(d);
    size_t row0 = ((size_t)b * NSEQ + c * 128);
    const float* base = h + row0 * DIM + d;
    float s = 0.f;
#pragma unroll 4
    for (int n = 0; n < 128; n++) {
        float v = base[(size_t)n * DIM];
        s += v;
        h16[(row0 + n) * DIM + pd] = __float2half_rn(v);
    }
    part[(size_t)(b * 32 + c) * DIM + d] = s;
}

// fused: ctx mean + full gamma gate. grid = BB, block = 1024.
__global__ __launch_bounds__(1024) void ctxgate_kernel(
    const float* __restrict__ part,
    const float* __restrict__ w1, const float* __restrict__ b1,
    const float* __restrict__ gain, const float* __restrict__ beta,
    const float* __restrict__ w2, const float* __restrict__ b2,
    float* __restrict__ gamma)
{
    __shared__ float cs[DIM];
    __shared__ float tj[HIDN];
    int b = blockIdx.x, tid = threadIdx.x;
    int w = tid >> 5, l = tid & 31;

    float s = 0.f;
#pragma unroll
    for (int c = 0; c < 32; c++) s += part[(size_t)(b * 32 + c) * DIM + tid];
    cs[tid] = s * (1.f / (float)NSEQ);
    __syncthreads();

    float acc = 0.f;
#pragma unroll 8
    for (int it = 0; it < DIM / 32; it++) {
        int d = l + it * 32;
        acc += cs[d] * w1[d * HIDN + w];
    }
#pragma unroll
    for (int o = 16; o; o >>= 1) acc += __shfl_xor_sync(0xffffffffu, acc, o);
    if (l == 0) tj[w] = acc + b1[w];
    __syncthreads();

    if (tid < HIDN) {
        float v = tj[tid];
        float m = v;
#pragma unroll
        for (int o = 16; o; o >>= 1) m += __shfl_xor_sync(0xffffffffu, m, o);
        m *= (1.f / 32.f);
        float d = v - m;
        float var = d * d;
#pragma unroll
        for (int o = 16; o; o >>= 1) var += __shfl_xor_sync(0xffffffffu, var, o);
        var *= (1.f / 32.f);
        float tn = d * rsqrtf(var + 1e-5f) * gain[tid] + beta[tid];
        float si = tn / (1.f + expf(-tn));
        float p = si * w2[tid];
#pragma unroll
        for (int o = 16; o; o >>= 1) p += __shfl_xor_sync(0xffffffffu, p, o);
        if (tid == 0) gamma[b] = 1.f / (1.f + expf(-(p + b2[0])));
    }
}

// combine 4 split-K partials -> fp16 kperm'd VOT
__global__ void cvt_vot_kernel(const float* __restrict__ part, __half* __restrict__ out) {
    int i = (blockIdx.x * 256 + threadIdx.x) * 4;
    const int SZ = DIM * SS;
    float4 a = *(const float4*)(part + i);
    float4 b = *(const float4*)(part + SZ + i);
    float4 c = *(const float4*)(part + 2 * SZ + i);
    float4 d = *(const float4*)(part + 3 * SZ + i);
    float x = a.x + b.x + c.x + d.x;
    float y = a.y + b.y + c.y + d.y;
    float z = a.z + b.z + c.z + d.z;
    float w = a.w + b.w + c.w + d.w;
    int p0 = kperm(i);
    *(__half2*)(out + p0) = __floats2half2_rn(x, y);
    *(__half2*)(out + p0 + 8) = __floats2half2_rn(z, w);
}

// attention weights: warp per row
__global__ void attn_kernel(const __half* __restrict__ reim16, __half* __restrict__ attn16,
                            const float* __restrict__ pinit, const float* __restrict__ gamma,
                            const float* __restrict__ rowssp) {
    int wid = threadIdx.x >> 5, lane = threadIdx.x & 31;
    int row = blockIdx.x * 8 + wid;
    int b = row >> 12;
    float p = pinit[row] * (1.f - gamma[b]);
    float inv_n2 = 1.f / fmaxf(rowssp[row] + rowssp[NTOK + row], 1e-24f);
    float c1 = (1.f - p) * inv_n2, c0 = p * (1.f / (float)DH);
    size_t base = (size_t)row * 512;
    float raw[8];
    float tot = 0.f;
#pragma unroll
    for (int q = 0; q < 8; q++) {
        int s = lane + q * 32;
        float r = __half2float(reim16[base + s]);
        float i = __half2float(reim16[base + 256 + s]);
        raw[q] = c1 * (r * r + i * i) + c0;
        tot += raw[q];
    }
#pragma unroll
    for (int o = 16; o; o >>= 1) tot += __shfl_xor_sync(0xffffffffu, tot, o);
    float inv = 1.f / (tot + 1e-8f);
#pragma unroll
    for (int q = 0; q < 8; q++)
        attn16[(size_t)row * SS + lane + q * 32] = __float2half_rn(raw[q] * inv);
}

// mid LN: h1 = LN(h + ao16); writes ONLY fp16 kperm'd copy
__global__ void ln_add_mid_kernel(const float* __restrict__ a, const __half* __restrict__ bsrc,
                                  const float* __restrict__ g, const float* __restrict__ beta,
                                  __half* __restrict__ outr) {
    size_t off = (size_t)blockIdx.x * DIM;
    int tid = threadIdx.x;
    float v[4];
    float s = 0.f;
#pragma unroll
    for (int q = 0; q < 4; q++) {
        int i = tid + q * 256;
        v[q] = a[off + i] + __half2float(bsrc[off + i]);
        s += v[q];
    }
    float mu = block_sum_256(s) * (1.f / (float)DIM);
    float s2 = 0.f;
#pragma unroll
    for (int q = 0; q < 4; q++) {
        float d = v[q] - mu;
        s2 += d * d;
    }
    float var = block_sum_256(s2) * (1.f / (float)DIM);
    float inv = rsqrtf(var + 1e-5f);
#pragma unroll
    for (int q = 0; q < 4; q++) {
        int i = tid + q * 256;
        float o = (v[q] - mu) * inv * g[i] + beta[i];
        outr[off + kperm(i)] = __float2half_rn(o);
    }
}

// final LN: out = LN(h1r16[kperm] + ff216)
__global__ void ln_add_final_kernel(const __half* __restrict__ a, const __half* __restrict__ bsrc,
                                    const float* __restrict__ g, const float* __restrict__ beta,
                                    float* __restrict__ out) {
    size_t off = (size_t)blockIdx.x * DIM;
    int tid = threadIdx.x;
    float v[4];
    float s = 0.f;
#pragma unroll
    for (int q = 0; q < 4; q++) {
        int i = tid + q * 256;
        v[q] = __half2float(a[off + kperm(i)]) + __half2float(bsrc[off + i]);
        s += v[q];
    }
    float mu = block_sum_256(s) * (1.f / (float)DIM);
    float s2 = 0.f;
#pragma unroll
    for (int q = 0; q < 4; q++) {
        float d = v[q] - mu;
        s2 += d * d;
    }
    float var = block_sum_256(s2) * (1.f / (float)DIM);
    float inv = rsqrtf(var + 1e-5f);
#pragma unroll
    for (int q = 0; q < 4; q++) {
        int i = tid + q * 256;
        out[off + i] = (v[q] - mu) * inv * g[i] + beta[i];
    }
}

// ---------------- launch ----------------
static inline void* symv(const void* s) {
    void* p = nullptr;
    cudaGetSymbolAddress(&p, s);
    return p;
}

extern "C" void kernel_launch(void* const* d_in, const int* in_sizes, int n_in,
                              void* d_out, int out_size) {
    const float* h     = (const float*)d_in[0];
    const float* Wr    = (const float*)d_in[1];
    const float* br    = (const float*)d_in[2];
    const float* Wi    = (const float*)d_in[3];
    const float* bi    = (const float*)d_in[4];
    const float* uw1   = (const float*)d_in[5];
    const float* ub1   = (const float*)d_in[6];
    const float* ug    = (const float*)d_in[7];
    const float* ubeta = (const float*)d_in[8];
    const float* uw2   = (const float*)d_in[9];
    const float* ub2   = (const float*)d_in[10];
    const float* gw1   = (const float*)d_in[11];
    const float* gb1   = (const float*)d_in[12];
    const float* gg    = (const float*)d_in[13];
    const float* gbeta = (const float*)d_in[14];
    const float* gw2   = (const float*)d_in[15];
    const float* gb2   = (const float*)d_in[16];
    const float* m_real= (const float*)d_in[17];
    const float* m_imag= (const float*)d_in[18];
    const float* values= (const float*)d_in[19];
    const float* ow    = (const float*)d_in[20];
    const float* ob    = (const float*)d_in[21];
    const float* n1g   = (const float*)d_in[22];
    const float* n1b   = (const float*)d_in[23];
    const float* n2g   = (const float*)d_in[24];
    const float* n2b   = (const float*)d_in[25];
    const float* fw1   = (const float*)d_in[26];
    const float* fb1   = (const float*)d_in[27];
    const float* fw2   = (const float*)d_in[28];
    const float* fb2   = (const float*)d_in[29];
    float* out = (float*)d_out;

    float* pinit = (float*)symv(g_pinit);
    float* gam   = (float*)symv(g_gamma);
    float* ctxp  = (float*)symv(g_ctxpart);
    float* rowssp= (float*)symv(g_rowsspart);
    float* bc    = (float*)symv(g_bc);
    float* VOTp  = (float*)symv(g_VOTpart);
    __half* h16    = (__half*)symv(g_h16);
    __half* psi16  = (__half*)symv(g_psi16);
    __half* reim16 = (__half*)symv(g_reim16);
    __half* attn16 = (__half*)symv(g_attn16);
    __half* h1r16  = (__half*)symv(g_h1r16);
    __half* ff116  = (__half*)symv(g_ff116);
    __half* ao16   = (__half*)symv(g_ao16);
    __half* ff216  = (__half*)symv(g_ff216);
    __half* WT16   = (__half*)symv(g_WT16);
    __half* uw1T16 = (__half*)symv(g_uw1T16);
    __half* Mp16   = (__half*)symv(g_Mp16);
    __half* owT16  = (__half*)symv(g_owT16);
    __half* val16  = (__half*)symv(g_val16);
    __half* VOT16  = (__half*)symv(g_VOT16);
    __half* fw1T16 = (__half*)symv(g_fw1T16);
    __half* fw2T16 = (__half*)symv(g_fw2T16);

    const int smBIG  = (128 + 256) * 64 * 3;   // 73728
    const int smBIG1 = (128 + 128) * 64 * 3;   // 49152
    const int smGATE = (128 + 32) * 64 * 6;    // 61440
    cudaFuncSetAttribute(hgemm_big<256, false, 1, false>, cudaFuncAttributeMaxDynamicSharedMemorySize, smBIG);
    cudaFuncSetAttribute(hgemm_big<256, false, 1, true >, cudaFuncAttributeMaxDynamicSharedMemorySize, smBIG);
    cudaFuncSetAttribute(hgemm_big<256, false, 2, false>, cudaFuncAttributeMaxDynamicSharedMemorySize, smBIG);
    cudaFuncSetAttribute(hgemm_big<256, false, 3, false>, cudaFuncAttributeMaxDynamicSharedMemorySize, smBIG);
    cudaFuncSetAttribute(hgemm_big<256, true,  1, false>, cudaFuncAttributeMaxDynamicSharedMemorySize, smBIG);
    cudaFuncSetAttribute(hgemm_big<128, false, 2, false>, cudaFuncAttributeMaxDynamicSharedMemorySize, smBIG1);
    cudaFuncSetAttribute(hgemm_gate, cudaFuncAttributeMaxDynamicSharedMemorySize, smGATE);

    dim3 thr(256);

    // [0] weight prep (one launch)
    prep_kernel<<<PREP_BLOCKS, thr>>>(Wr, Wi, uw1, ow, fw1, fw2, values,
                                      m_real, m_imag, br, bi,
                                      WT16, uw1T16, owT16, fw1T16, fw2T16,
                                      val16, Mp16, bc);

    // [1] ctx partials + h -> h16
    ctx_partial_cvt_kernel<<<dim3(DIM / 256, BB, 32), thr>>>(h, ctxp, h16);

    // [2] fused ctx mean + gamma gate
    ctxgate_kernel<<<BB, 1024>>>(ctxp, gw1, gb1, gg, gbeta, gw2, gb2, gam);

    // [3] uncertainty gate: GEMM (6-stage) + fused finish -> pinit
    hgemm_gate<<<dim3(1, 128), thr, smGATE>>>(h16, uw1T16, ub1, ug, ubeta, uw2, ub2,
                                              pinit, 0.95f, DIM);

    // [4] psi = h @ [Wr|Wi] + [br|bi] -> psi16 + rowss partials
    hgemm_big<256, false, 1, true><<<dim3(2, 128), thr, smBIG>>>(
        h16, WT16, bc, psi16, rowssp, DIM, 512, 0);

    // [5] VOT = owT @ values^T, split-K x4 -> fp32 partials
    hgemm_big<256, false, 3, false><<<dim3(1, 8, 4), thr, smBIG>>>(
        owT16, val16, nullptr, VOTp, nullptr, DIM, SS, (size_t)DIM * SS);

    // [6] combine partials -> VOT16
    cvt_vot_kernel<<<DIM * SS / 1024, thr>>>(VOTp, VOT16);

    // [7] reim = psi @ Mpack^T
    hgemm_big<256, false, 1, false><<<dim3(2, 128), thr, smBIG>>>(
        psi16, Mp16, nullptr, reim16, nullptr, 512, 512, 0);

    // [8] attention weights
    attn_kernel<<<NTOK / 8, thr>>>(reim16, attn16, pinit, gam, rowssp);

    // [9] ao = attn @ VOT^T + ob   (fp16 plain)
    hgemm_big<256, false, 2, false><<<dim3(4, 128), thr, smBIG>>>(
        attn16, VOT16, ob, ao16, nullptr, SS, DIM, 0);

    // [10] h1 = LN(h + ao) -> fp16 kperm'd only
    ln_add_mid_kernel<<<NTOK, 256>>>(h, ao16, n1g, n1b, h1r16);

    // [11] FFN1 (BN=256, 2048 tiles -> good waves)
    hgemm_big<256, true, 1, false><<<dim3(16, 128), thr, smBIG>>>(
        h1r16, fw1T16, fb1, ff116, nullptr, DIM, DFF, 0);

    // [12] FFN2 with BN=128: 1024 tiles -> 7 waves (was 4 quantized from 3.46)
    hgemm_big<128, false, 2, false><<<dim3(8, 128), thr, smBIG1>>>(
        ff116, fw2T16, fb2, ff216, nullptr, DFF, DIM, 0);

    // [13] out = LN(h1 + ff2)
    ln_add_final_kernel<<<NTOK, 256>>>(h1r16, ff216, n2g, n2b, out);
}

// round 11
// speedup vs baseline: 6.5525x; 1.0390x over previous
#include <cuda_runtime.h>
#include <cuda_fp16.h>
#include <math.h>
#include <stdint.h>

// ---------------- problem constants ----------------
#define BB    4
#define NSEQ  4096
#define NTOK  16384        // BB*NSEQ
#define DIM   1024
#define DH    256
#define SS    256
#define HIDN  32
#define DFF   4096

// ---------------- scratch (device globals: allowed) ----------------
__device__ float g_pinit[NTOK];
__device__ float g_gamma[BB];
__device__ float g_ctxpart[BB * 32 * DIM];
__device__ float g_rowsspart[2 * NTOK];   // per-CTA psi sum-of-squares partials
__device__ float g_bc[512];               // [br | bi]
__device__ float g_VOTpart[4 * DIM * SS]; // split-K fp32 partials
// fp16 GEMM operands (kperm'd where used as GEMM input)
__device__ __half g_h16[NTOK * DIM];
__device__ __half g_psi16[NTOK * 512];    // unnormalized [pr|pi]
__device__ __half g_reim16[NTOK * 512];
__device__ __half g_attn16[NTOK * SS];
__device__ __half g_h1r16[NTOK * DIM];    // h1, fp16, kperm'd (only copy of h1)
__device__ __half g_ff116[NTOK * DFF];
__device__ __half g_ao16[NTOK * DIM];     // plain fp16
__device__ __half g_ff216[NTOK * DIM];    // plain fp16
__device__ __half g_WT16[512 * DIM];
__device__ __half g_uw1T16[HIDN * DIM];
__device__ __half g_Mp16[512 * 512];
__device__ __half g_owT16[DIM * DIM];
__device__ __half g_val16[SS * DIM];
__device__ __half g_VOT16[DIM * SS];
__device__ __half g_fw1T16[DFF * DIM];
__device__ __half g_fw2T16[DIM * DFF];

// ---------------- helpers ----------------
__device__ __forceinline__ int kperm(int k) {
    int r = k & 31;
    int t = (r >> 1) & 3, w = r >> 4, hh = (r >> 3) & 1, j = r & 1;
    return (k & ~31) | (t << 3) | (w << 2) | (hh << 1) | j;
}

__device__ __forceinline__ float gelu_exact(float x) {
    return 0.5f * x * (1.0f + erff(x * 0.7071067811865475f));
}

__device__ __forceinline__ float block_sum_256(float v) {
    __shared__ float sh[8];
    int lane = threadIdx.x & 31, w = threadIdx.x >> 5;
#pragma unroll
    for (int o = 16; o; o >>= 1) v += __shfl_xor_sync(0xffffffffu, v, o);
    if (lane == 0) sh[w] = v;
    __syncthreads();
    float r = (lane < 8) ? sh[lane] : 0.f;
    if (w == 0) {
#pragma unroll
        for (int o = 4; o; o >>= 1) r += __shfl_xor_sync(0xffffffffu, r, o);
        if (lane == 0) sh[0] = r;
    }
    __syncthreads();
    float out = sh[0];
    __syncthreads();
    return out;
}

__device__ __forceinline__ uint32_t smem_u32(const void* p) {
    return (uint32_t)__cvta_generic_to_shared(p);
}
__device__ __forceinline__ void cp16(uint32_t dst, const void* src) {
    asm volatile("cp.async.cg.shared.global [%0], [%1], 16;" :: "r"(dst), "l"(src));
}
__device__ __forceinline__ void cp_commit() { asm volatile("cp.async.commit_group;"); }
template <int N>
__device__ __forceinline__ void cp_wait() { asm volatile("cp.async.wait_group %0;" :: "n"(N)); }

#define MMA_F16(d, a0, a1, a2, a3, b0, b1) \
    asm volatile( \
        "mma.sync.aligned.m16n8k16.row.col.f32.f16.f16.f32 " \
        "{%0,%1,%2,%3}, {%4,%5,%6,%7}, {%8,%9}, {%0,%1,%2,%3};" \
        : "+f"((d)[0]), "+f"((d)[1]), "+f"((d)[2]), "+f"((d)[3]) \
        : "r"(a0), "r"(a1), "r"(a2), "r"(a3), "r"(b0), "r"(b1))

// ============================================================
// BIG fp16 GEMM: 128 x BN CTA tile (BN = 256 or 128), 8 warps.
// ============================================================
template <int BN>
__device__ __forceinline__ void load_slab_h(char* smem, int stage,
                                            const __half* gA, const __half* gB,
                                            int k0, int K, int tid) {
    constexpr int STAGE = (128 + BN) * 64;
    uint32_t base = smem_u32(smem) + stage * STAGE;
#pragma unroll
    for (int i = 0; i < 2; i++) {
        int idx = tid + i * 256;
        int row = idx >> 2, c = idx & 3;
        cp16(base + (uint32_t)(row * 64 + c * 16),
             gA + (size_t)row * K + k0 + c * 8);
    }
    uint32_t bb = base + 128 * 64;
#pragma unroll
    for (int i = 0; i < BN / 64; i++) {
        int idx = tid + i * 256;
        int row = idx >> 2, c = idx & 3;
        cp16(bb + (uint32_t)(row * 64 + c * 16),
             gB + (size_t)row * K + k0 + c * 8);
    }
}

template <int BN, bool GELU, int OMODE, bool SUMSQ>
__global__ __launch_bounds__(256, 1) void hgemm_big(
    const __half* __restrict__ A, const __half* __restrict__ B,
    const float* __restrict__ bias, void* __restrict__ Cv,
    float* __restrict__ rowss, int K, int Ntot, size_t zstride)
{
    extern __shared__ char smem[];
    constexpr int STAGE = (128 + BN) * 64;
    constexpr int NI = BN / 32;

    const int tid = threadIdx.x, wid = tid >> 5, lane = tid & 31;
    const int warp_m = (wid & 1) * 64;
    const int warp_n = (wid >> 1) * (BN / 4);
    const int g = lane >> 2, tg = lane & 3;

    const int kchunk = K / gridDim.z;
    const __half* gA = A + (size_t)blockIdx.y * 128 * K + blockIdx.z * kchunk;
    const __half* gB = B + (size_t)blockIdx.x * BN * K + blockIdx.z * kchunk;
    const int NS = kchunk >> 5;

    float acc[4][NI][4] = {};

    load_slab_h<BN>(smem, 0, gA, gB, 0, K, tid);  cp_commit();
    load_slab_h<BN>(smem, 1, gA, gB, 32, K, tid); cp_commit();

    for (int ks = 0; ks < NS; ks++) {
        if (ks + 2 < NS) {
            load_slab_h<BN>(smem, (ks + 2) % 3, gA, gB, (ks + 2) * 32, K, tid);
            cp_commit();
        }
        int rem = NS - 1 - ks;
        if (rem >= 2) cp_wait<2>();
        else if (rem == 1) cp_wait<1>();
        else cp_wait<0>();
        __syncthreads();

        const __half* As = (const __half*)(smem + (size_t)(ks % 3) * STAGE);
        const __half* Bs = As + 128 * 32;

        uint4 aq[4][2];
#pragma unroll
        for (int mi = 0; mi < 4; mi++) {
            aq[mi][0] = *(const uint4*)(As + (warp_m + mi * 16 + g) * 32 + 8 * tg);
            aq[mi][1] = *(const uint4*)(As + (warp_m + mi * 16 + 8 + g) * 32 + 8 * tg);
        }
        uint4 bq[NI];
#pragma unroll
        for (int ni = 0; ni < NI; ni++)
            bq[ni] = *(const uint4*)(Bs + (warp_n + ni * 8 + g) * 32 + 8 * tg);

#pragma unroll
        for (int mi = 0; mi < 4; mi++) {
#pragma unroll
            for (int ni = 0; ni < NI; ni++) {
                MMA_F16(acc[mi][ni], aq[mi][0].x, aq[mi][1].x, aq[mi][0].y, aq[mi][1].y,
                        bq[ni].x, bq[ni].y);
                MMA_F16(acc[mi][ni], aq[mi][0].z, aq[mi][1].z, aq[mi][0].w, aq[mi][1].w,
                        bq[ni].z, bq[ni].w);
            }
        }
        __syncthreads();
    }

    float ss[4][2];
    if (SUMSQ) {
#pragma unroll
        for (int mi = 0; mi < 4; mi++) { ss[mi][0] = 0.f; ss[mi][1] = 0.f; }
    }

#pragma unroll
    for (int mi = 0; mi < 4; mi++) {
        int r0 = blockIdx.y * 128 + warp_m + mi * 16 + g;
#pragma unroll
        for (int ni = 0; ni < NI; ni++) {
            int col = blockIdx.x * BN + warp_n + ni * 8 + 2 * tg;
            float bx = 0.f, by = 0.f;
            if (OMODE != 3 && bias) { bx = bias[col]; by = bias[col + 1]; }
#pragma unroll
            for (int half = 0; half < 2; half++) {
                int row = r0 + half * 8;
                float vx = acc[mi][ni][half * 2 + 0] + bx;
                float vy = acc[mi][ni][half * 2 + 1] + by;
                if (GELU) { vx = gelu_exact(vx); vy = gelu_exact(vy); }
                if (SUMSQ) ss[mi][half] += vx * vx + vy * vy;
                if (OMODE == 1) {
                    *(__half2*)((__half*)Cv + (size_t)row * Ntot + kperm(col)) =
                        __floats2half2_rn(vx, vy);
                } else if (OMODE == 2) {
                    *(__half2*)((__half*)Cv + (size_t)row * Ntot + col) =
                        __floats2half2_rn(vx, vy);
                } else if (OMODE == 3) {
                    *(float2*)((float*)Cv + blockIdx.z * zstride + (size_t)row * Ntot + col) =
                        make_float2(vx, vy);
                } else {
                    *(float2*)((float*)Cv + (size_t)row * Ntot + col) = make_float2(vx, vy);
                }
            }
        }
    }

    if (SUMSQ) {
        float* red = (float*)smem;   // [128][4]
#pragma unroll
        for (int mi = 0; mi < 4; mi++) {
#pragma unroll
            for (int half = 0; half < 2; half++) {
                float v = ss[mi][half];
                v += __shfl_xor_sync(0xffffffffu, v, 1);
                v += __shfl_xor_sync(0xffffffffu, v, 2);
                if (tg == 0) {
                    int rl = warp_m + mi * 16 + half * 8 + g;
                    red[rl * 4 + (wid >> 1)] = v;
                }
            }
        }
        __syncthreads();
        if (tid < 128) {
            float tot = red[tid * 4] + red[tid * 4 + 1] + red[tid * 4 + 2] + red[tid * 4 + 3];
            rowss[blockIdx.x * NTOK + blockIdx.y * 128 + tid] = tot;
        }
    }
}

// ============================================================
// Gate GEMM (N = 32) with FUSED finish, 6-stage pipeline.
// ============================================================
__device__ __forceinline__ void load_slab_h32(char* smem, int stage,
                                              const __half* gA, const __half* gB,
                                              int k0, int K, int tid) {
    constexpr int STAGE = (128 + 32) * 64;
    uint32_t base = smem_u32(smem) + stage * STAGE;
#pragma unroll
    for (int i = 0; i < 2; i++) {
        int idx = tid + i * 256;
        int row = idx >> 2, c = idx & 3;
        cp16(base + (uint32_t)(row * 64 + c * 16),
             gA + (size_t)row * K + k0 + c * 8);
    }
    uint32_t bb = base + 128 * 64;
    if (tid < 128) {
        int row = tid >> 2, c = tid & 3;
        cp16(bb + (uint32_t)(row * 64 + c * 16),
             gB + (size_t)row * K + k0 + c * 8);
    }
}

__global__ __launch_bounds__(256) void hgemm_gate(
    const __half* __restrict__ A, const __half* __restrict__ B,
    const float* __restrict__ b1, const float* __restrict__ gain,
    const float* __restrict__ beta, const float* __restrict__ w2,
    const float* __restrict__ b2, float* __restrict__ pinit,
    float scale, int K)
{
    extern __shared__ char smem[];
    constexpr int STAGE = (128 + 32) * 64;

    const int tid = threadIdx.x, wid = tid >> 5, lane = tid & 31;
    const int warp_m = wid * 16;
    const int gg2 = lane >> 2, tg = lane & 3;

    const __half* gA = A + (size_t)blockIdx.y * 128 * K;
    const __half* gB = B;
    const int NS = K >> 5;

    float acc[4][4] = {};

#pragma unroll
    for (int s = 0; s < 5; s++) {
        load_slab_h32(smem, s, gA, gB, s * 32, K, tid);
        cp_commit();
    }

    for (int ks = 0; ks < NS; ks++) {
        if (ks + 5 < NS) {
            load_slab_h32(smem, (ks + 5) % 6, gA, gB, (ks + 5) * 32, K, tid);
            cp_commit();
        }
        int rem = NS - 1 - ks;
        if (rem >= 5) cp_wait<5>();
        else if (rem == 4) cp_wait<4>();
        else if (rem == 3) cp_wait<3>();
        else if (rem == 2) cp_wait<2>();
        else if (rem == 1) cp_wait<1>();
        else cp_wait<0>();
        __syncthreads();

        const __half* As = (const __half*)(smem + (size_t)(ks % 6) * STAGE);
        const __half* Bs = As + 128 * 32;

        uint4 alo = *(const uint4*)(As + (warp_m + gg2) * 32 + 8 * tg);
        uint4 ahi = *(const uint4*)(As + (warp_m + 8 + gg2) * 32 + 8 * tg);
        uint4 bq[4];
#pragma unroll
        for (int ni = 0; ni < 4; ni++)
            bq[ni] = *(const uint4*)(Bs + (ni * 8 + gg2) * 32 + 8 * tg);
#pragma unroll
        for (int ni = 0; ni < 4; ni++) {
            MMA_F16(acc[ni], alo.x, ahi.x, alo.y, ahi.y, bq[ni].x, bq[ni].y);
            MMA_F16(acc[ni], alo.z, ahi.z, alo.w, ahi.w, bq[ni].z, bq[ni].w);
        }
        __syncthreads();
    }

#pragma unroll
    for (int half = 0; half < 2; half++) {
        float vv[8];
        float sum = 0.f;
#pragma unroll
        for (int ni = 0; ni < 4; ni++) {
#pragma unroll
            for (int j = 0; j < 2; j++) {
                int col = ni * 8 + 2 * tg + j;
                float v = acc[ni][half * 2 + j] + b1[col];
                vv[ni * 2 + j] = v;
                sum += v;
            }
        }
        sum += __shfl_xor_sync(0xffffffffu, sum, 1);
        sum += __shfl_xor_sync(0xffffffffu, sum, 2);
        float m = sum * (1.f / 32.f);
        float s2 = 0.f;
#pragma unroll
        for (int q = 0; q < 8; q++) { float d = vv[q] - m; s2 += d * d; }
        s2 += __shfl_xor_sync(0xffffffffu, s2, 1);
        s2 += __shfl_xor_sync(0xffffffffu, s2, 2);
        float inv = rsqrtf(s2 * (1.f / 32.f) + 1e-5f);
        float p = 0.f;
#pragma unroll
        for (int ni = 0; ni < 4; ni++) {
#pragma unroll
            for (int j = 0; j < 2; j++) {
                int col = ni * 8 + 2 * tg + j;
                float tn = (vv[ni * 2 + j] - m) * inv * gain[col] + beta[col];
                float si = tn / (1.f + expf(-tn));
                p += si * w2[col];
            }
        }
        p += __shfl_xor_sync(0xffffffffu, p, 1);
        p += __shfl_xor_sync(0xffffffffu, p, 2);
        if (tg == 0) {
            int row = blockIdx.y * 128 + warp_m + half * 8 + gg2;
            pinit[row] = scale / (1.f + expf(-(p + b2[0])));
        }
    }
}

// ============================================================
// PREP megakernel (job table). All blocks 256 threads.
// ============================================================
__device__ __forceinline__ void transpose_tile(const float* in, __half* out,
                                               int R, int C, int lb, int tid) {
    __shared__ float t[32][33];
    int nbx = C >> 5;
    int bx = lb % nbx, by = lb / nbx;
    int c0 = bx * 32, r0 = by * 32;
    int x = tid & 31, y = tid >> 5;
#pragma unroll
    for (int dy = 0; dy < 32; dy += 8)
        t[y + dy][x] = in[(size_t)(r0 + y + dy) * C + c0 + x];
    __syncthreads();
#pragma unroll
    for (int dy = 0; dy < 32; dy += 8)
        out[(size_t)(c0 + y + dy) * R + kperm(r0 + x)] = __float2half_rn(t[x][y + dy]);
}

__global__ void prep_kernel(
    const float* __restrict__ Wr, const float* __restrict__ Wi,
    const float* __restrict__ uw1, const float* __restrict__ ow,
    const float* __restrict__ fw1, const float* __restrict__ fw2,
    const float* __restrict__ values,
    const float* __restrict__ mr, const float* __restrict__ mi,
    const float* __restrict__ br, const float* __restrict__ bi,
    __half* __restrict__ WT16, __half* __restrict__ uw1T16,
    __half* __restrict__ owT16, __half* __restrict__ fw1T16,
    __half* __restrict__ fw2T16, __half* __restrict__ val16,
    __half* __restrict__ Mp16, float* __restrict__ bc)
{
    int b = blockIdx.x, tid = threadIdx.x;
    if (b < 256) { transpose_tile(Wr, WT16, DIM, DH, b, tid); return; }
    b -= 256;
    if (b < 256) { transpose_tile(Wi, WT16 + 256 * DIM, DIM, DH, b, tid); return; }
    b -= 256;
    if (b < 32)  { transpose_tile(uw1, uw1T16, DIM, HIDN, b, tid); return; }
    b -= 32;
    if (b < 1024){ transpose_tile(ow, owT16, DIM, DIM, b, tid); return; }
    b -= 1024;
    if (b < 4096){ transpose_tile(fw1, fw1T16, DIM, DFF, b, tid); return; }
    b -= 4096;
    if (b < 4096){ transpose_tile(fw2, fw2T16, DFF, DIM, b, tid); return; }
    b -= 4096;
    if (b < 256) {
        int i = (b * 256 + tid) * 4;
        float4 v = *(const float4*)(values + i);
        int p0 = kperm(i);
        *(__half2*)(val16 + p0) = __floats2half2_rn(v.x, v.y);
        *(__half2*)(val16 + p0 + 8) = __floats2half2_rn(v.z, v.w);
        return;
    }
    b -= 256;
    if (b < 256) {
        int s = b, d = tid;
        float a = mr[s * DH + d], bb2 = mi[s * DH + d];
        float tot = block_sum_256(a * a + bb2 * bb2);
        float inv = 1.f / fmaxf(sqrtf(tot), 1e-12f);
        float ra = a * inv, rb = bb2 * inv;
        Mp16[(size_t)s * 512 + kperm(d)] = __float2half_rn(ra);
        Mp16[(size_t)s * 512 + kperm(256 + d)] = __float2half_rn(rb);
        Mp16[(size_t)(256 + s) * 512 + kperm(d)] = __float2half_rn(rb);
        Mp16[(size_t)(256 + s) * 512 + kperm(256 + d)] = __float2half_rn(-ra);
        return;
    }
    {
        bc[tid] = br[tid];
        bc[256 + tid] = bi[tid];
    }
}
#define PREP_BLOCKS (256 + 256 + 32 + 1024 + 4096 + 4096 + 256 + 256 + 1)

// ---------------- elementwise kernels ----------------
__global__ void ctx_partial_cvt_kernel(const float* __restrict__ h,
                                       float* __restrict__ part,
                                       __half* __restrict__ h16) {
    int d = blockIdx.x * 256 + threadIdx.x;
    int b = blockIdx.y;
    int c = blockIdx.z;
    int pd = kperm(d);
    size_t row0 = ((size_t)b * NSEQ + c * 128);
    const float* base = h + row0 * DIM + d;
    float s = 0.f;
#pragma unroll 4
    for (int n = 0; n < 128; n++) {
        float v = base[(size_t)n * DIM];
        s += v;
        h16[(row0 + n) * DIM + pd] = __float2half_rn(v);
    }
    part[(size_t)(b * 32 + c) * DIM + d] = s;
}

// fused: ctx mean + full gamma gate. grid = BB, block = 1024.
__global__ __launch_bounds__(1024) void ctxgate_kernel(
    const float* __restrict__ part,
    const float* __restrict__ w1, const float* __restrict__ b1,
    const float* __restrict__ gain, const float* __restrict__ beta,
    const float* __restrict__ w2, const float* __restrict__ b2,
    float* __restrict__ gamma)
{
    __shared__ float cs[DIM];
    __shared__ float tj[HIDN];
    int b = blockIdx.x, tid = threadIdx.x;
    int w = tid >> 5, l = tid & 31;

    float s = 0.f;
#pragma unroll
    for (int c = 0; c < 32; c++) s += part[(size_t)(b * 32 + c) * DIM + tid];
    cs[tid] = s * (1.f / (float)NSEQ);
    __syncthreads();

    float acc = 0.f;
#pragma unroll 8
    for (int it = 0; it < DIM / 32; it++) {
        int d = l + it * 32;
        acc += cs[d] * w1[d * HIDN + w];
    }
#pragma unroll
    for (int o = 16; o; o >>= 1) acc += __shfl_xor_sync(0xffffffffu, acc, o);
    if (l == 0) tj[w] = acc + b1[w];
    __syncthreads();

    if (tid < HIDN) {
        float v = tj[tid];
        float m = v;
#pragma unroll
        for (int o = 16; o; o >>= 1) m += __shfl_xor_sync(0xffffffffu, m, o);
        m *= (1.f / 32.f);
        float d = v - m;
        float var = d * d;
#pragma unroll
        for (int o = 16; o; o >>= 1) var += __shfl_xor_sync(0xffffffffu, var, o);
        var *= (1.f / 32.f);
        float tn = d * rsqrtf(var + 1e-5f) * gain[tid] + beta[tid];
        float si = tn / (1.f + expf(-tn));
        float p = si * w2[tid];
#pragma unroll
        for (int o = 16; o; o >>= 1) p += __shfl_xor_sync(0xffffffffu, p, o);
        if (tid == 0) gamma[b] = 1.f / (1.f + expf(-(p + b2[0])));
    }
}

// combine 4 split-K partials -> fp16 kperm'd VOT
__global__ void cvt_vot_kernel(const float* __restrict__ part, __half* __restrict__ out) {
    int i = (blockIdx.x * 256 + threadIdx.x) * 4;
    const int SZ = DIM * SS;
    float4 a = *(const float4*)(part + i);
    float4 b = *(const float4*)(part + SZ + i);
    float4 c = *(const float4*)(part + 2 * SZ + i);
    float4 d = *(const float4*)(part + 3 * SZ + i);
    float x = a.x + b.x + c.x + d.x;
    float y = a.y + b.y + c.y + d.y;
    float z = a.z + b.z + c.z + d.z;
    float w = a.w + b.w + c.w + d.w;
    int p0 = kperm(i);
    *(__half2*)(out + p0) = __floats2half2_rn(x, y);
    *(__half2*)(out + p0 + 8) = __floats2half2_rn(z, w);
}

// attention weights: warp per row
__global__ void attn_kernel(const __half* __restrict__ reim16, __half* __restrict__ attn16,
                            const float* __restrict__ pinit, const float* __restrict__ gamma,
                            const float* __restrict__ rowssp) {
    int wid = threadIdx.x >> 5, lane = threadIdx.x & 31;
    int row = blockIdx.x * 8 + wid;
    int b = row >> 12;
    float p = pinit[row] * (1.f - gamma[b]);
    float inv_n2 = 1.f / fmaxf(rowssp[row] + rowssp[NTOK + row], 1e-24f);
    float c1 = (1.f - p) * inv_n2, c0 = p * (1.f / (float)DH);
    size_t base = (size_t)row * 512;
    float raw[8];
    float tot = 0.f;
#pragma unroll
    for (int q = 0; q < 8; q++) {
        int s = lane + q * 32;
        float r = __half2float(reim16[base + s]);
        float i = __half2float(reim16[base + 256 + s]);
        raw[q] = c1 * (r * r + i * i) + c0;
        tot += raw[q];
    }
#pragma unroll
    for (int o = 16; o; o >>= 1) tot += __shfl_xor_sync(0xffffffffu, tot, o);
    float inv = 1.f / (tot + 1e-8f);
#pragma unroll
    for (int q = 0; q < 8; q++)
        attn16[(size_t)row * SS + lane + q * 32] = __float2half_rn(raw[q] * inv);
}

// mid LN: h1 = LN(h16 + ao16); writes ONLY fp16 kperm'd copy
__global__ void ln_add_mid_kernel(const __half* __restrict__ a, const __half* __restrict__ bsrc,
                                  const float* __restrict__ g, const float* __restrict__ beta,
                                  __half* __restrict__ outr) {
    size_t off = (size_t)blockIdx.x * DIM;
    int tid = threadIdx.x;
    float v[4];
    float s = 0.f;
#pragma unroll
    for (int q = 0; q < 4; q++) {
        int i = tid + q * 256;
        v[q] = __half2float(a[off + kperm(i)]) + __half2float(bsrc[off + i]);
        s += v[q];
    }
    float mu = block_sum_256(s) * (1.f / (float)DIM);
    float s2 = 0.f;
#pragma unroll
    for (int q = 0; q < 4; q++) {
        float d = v[q] - mu;
        s2 += d * d;
    }
    float var = block_sum_256(s2) * (1.f / (float)DIM);
    float inv = rsqrtf(var + 1e-5f);
#pragma unroll
    for (int q = 0; q < 4; q++) {
        int i = tid + q * 256;
        float o = (v[q] - mu) * inv * g[i] + beta[i];
        outr[off + kperm(i)] = __float2half_rn(o);
    }
}

// final LN: out = LN(h1r16[kperm] + ff216)
__global__ void ln_add_final_kernel(const __half* __restrict__ a, const __half* __restrict__ bsrc,
                                    const float* __restrict__ g, const float* __restrict__ beta,
                                    float* __restrict__ out) {
    size_t off = (size_t)blockIdx.x * DIM;
    int tid = threadIdx.x;
    float v[4];
    float s = 0.f;
#pragma unroll
    for (int q = 0; q < 4; q++) {
        int i = tid + q * 256;
        v[q] = __half2float(a[off + kperm(i)]) + __half2float(bsrc[off + i]);
        s += v[q];
    }
    float mu = block_sum_256(s) * (1.f / (float)DIM);
    float s2 = 0.f;
#pragma unroll
    for (int q = 0; q < 4; q++) {
        float d = v[q] - mu;
        s2 += d * d;
    }
    float var = block_sum_256(s2) * (1.f / (float)DIM);
    float inv = rsqrtf(var + 1e-5f);
#pragma unroll
    for (int q = 0; q < 4; q++) {
        int i = tid + q * 256;
        out[off + i] = (v[q] - mu) * inv * g[i] + beta[i];
    }
}

// ---------------- launch ----------------
static inline void* symv(const void* s) {
    void* p = nullptr;
    cudaGetSymbolAddress(&p, s);
    return p;
}

extern "C" void kernel_launch(void* const* d_in, const int* in_sizes, int n_in,
                              void* d_out, int out_size) {
    const float* h     = (const float*)d_in[0];
    const float* Wr    = (const float*)d_in[1];
    const float* br    = (const float*)d_in[2];
    const float* Wi    = (const float*)d_in[3];
    const float* bi    = (const float*)d_in[4];
    const float* uw1   = (const float*)d_in[5];
    const float* ub1   = (const float*)d_in[6];
    const float* ug    = (const float*)d_in[7];
    const float* ubeta = (const float*)d_in[8];
    const float* uw2   = (const float*)d_in[9];
    const float* ub2   = (const float*)d_in[10];
    const float* gw1   = (const float*)d_in[11];
    const float* gb1   = (const float*)d_in[12];
    const float* gg    = (const float*)d_in[13];
    const float* gbeta = (const float*)d_in[14];
    const float* gw2   = (const float*)d_in[15];
    const float* gb2   = (const float*)d_in[16];
    const float* m_real= (const float*)d_in[17];
    const float* m_imag= (const float*)d_in[18];
    const float* values= (const float*)d_in[19];
    const float* ow    = (const float*)d_in[20];
    const float* ob    = (const float*)d_in[21];
    const float* n1g   = (const float*)d_in[22];
    const float* n1b   = (const float*)d_in[23];
    const float* n2g   = (const float*)d_in[24];
    const float* n2b   = (const float*)d_in[25];
    const float* fw1   = (const float*)d_in[26];
    const float* fb1   = (const float*)d_in[27];
    const float* fw2   = (const float*)d_in[28];
    const float* fb2   = (const float*)d_in[29];
    float* out = (float*)d_out;

    float* pinit = (float*)symv(g_pinit);
    float* gam   = (float*)symv(g_gamma);
    float* ctxp  = (float*)symv(g_ctxpart);
    float* rowssp= (float*)symv(g_rowsspart);
    float* bc    = (float*)symv(g_bc);
    float* VOTp  = (float*)symv(g_VOTpart);
    __half* h16    = (__half*)symv(g_h16);
    __half* psi16  = (__half*)symv(g_psi16);
    __half* reim16 = (__half*)symv(g_reim16);
    __half* attn16 = (__half*)symv(g_attn16);
    __half* h1r16  = (__half*)symv(g_h1r16);
    __half* ff116  = (__half*)symv(g_ff116);
    __half* ao16   = (__half*)symv(g_ao16);
    __half* ff216  = (__half*)symv(g_ff216);
    __half* WT16   = (__half*)symv(g_WT16);
    __half* uw1T16 = (__half*)symv(g_uw1T16);
    __half* Mp16   = (__half*)symv(g_Mp16);
    __half* owT16  = (__half*)symv(g_owT16);
    __half* val16  = (__half*)symv(g_val16);
    __half* VOT16  = (__half*)symv(g_VOT16);
    __half* fw1T16 = (__half*)symv(g_fw1T16);
    __half* fw2T16 = (__half*)symv(g_fw2T16);

    const int smBIG  = (128 + 256) * 64 * 3;   // 73728
    const int smBIG1 = (128 + 128) * 64 * 3;   // 49152
    const int smGATE = (128 + 32) * 64 * 6;    // 61440
    cudaFuncSetAttribute(hgemm_big<256, false, 1, false>, cudaFuncAttributeMaxDynamicSharedMemorySize, smBIG);
    cudaFuncSetAttribute(hgemm_big<256, false, 1, true >, cudaFuncAttributeMaxDynamicSharedMemorySize, smBIG);
    cudaFuncSetAttribute(hgemm_big<256, false, 2, false>, cudaFuncAttributeMaxDynamicSharedMemorySize, smBIG);
    cudaFuncSetAttribute(hgemm_big<256, false, 3, false>, cudaFuncAttributeMaxDynamicSharedMemorySize, smBIG);
    cudaFuncSetAttribute(hgemm_big<256, true,  1, false>, cudaFuncAttributeMaxDynamicSharedMemorySize, smBIG);
    cudaFuncSetAttribute(hgemm_big<128, false, 2, false>, cudaFuncAttributeMaxDynamicSharedMemorySize, smBIG1);
    cudaFuncSetAttribute(hgemm_gate, cudaFuncAttributeMaxDynamicSharedMemorySize, smGATE);

    // fork-join streams/events (created once, outside capture on first call)
    static cudaStream_t s1 = nullptr, s2 = nullptr;
    static cudaEvent_t evEntry = nullptr, evPrep = nullptr, evCtx = nullptr,
                       evGate = nullptr, evVot = nullptr;
    if (!s1) {
        cudaStreamCreateWithFlags(&s1, cudaStreamNonBlocking);
        cudaStreamCreateWithFlags(&s2, cudaStreamNonBlocking);
        cudaEventCreateWithFlags(&evEntry, cudaEventDisableTiming);
        cudaEventCreateWithFlags(&evPrep, cudaEventDisableTiming);
        cudaEventCreateWithFlags(&evCtx, cudaEventDisableTiming);
        cudaEventCreateWithFlags(&evGate, cudaEventDisableTiming);
        cudaEventCreateWithFlags(&evVot, cudaEventDisableTiming);
    }

    dim3 thr(256);

    // fork s2 from entry: weight prep + VOT chain
    cudaEventRecord(evEntry, 0);
    cudaStreamWaitEvent(s2, evEntry, 0);
    prep_kernel<<<PREP_BLOCKS, thr, 0, s2>>>(Wr, Wi, uw1, ow, fw1, fw2, values,
                                             m_real, m_imag, br, bi,
                                             WT16, uw1T16, owT16, fw1T16, fw2T16,
                                             val16, Mp16, bc);
    cudaEventRecord(evPrep, s2);
    // s2 continues: VOT split-K + combine (needs only prep outputs)
    hgemm_big<256, false, 3, false><<<dim3(1, 8, 4), thr, smBIG, s2>>>(
        owT16, val16, nullptr, VOTp, nullptr, DIM, SS, (size_t)DIM * SS);
    cvt_vot_kernel<<<DIM * SS / 1024, thr, 0, s2>>>(VOTp, VOT16);
    cudaEventRecord(evVot, s2);

    // main: ctx partials + h -> h16 (overlaps prep)
    ctx_partial_cvt_kernel<<<dim3(DIM / 256, BB, 32), thr>>>(h, ctxp, h16);
    cudaEventRecord(evCtx, 0);

    // s1: gamma gate + uncertainty gate (overlap psi/reim on main)
    cudaStreamWaitEvent(s1, evCtx, 0);
    cudaStreamWaitEvent(s1, evPrep, 0);
    ctxgate_kernel<<<BB, 1024, 0, s1>>>(ctxp, gw1, gb1, gg, gbeta, gw2, gb2, gam);
    hgemm_gate<<<dim3(1, 128), thr, smGATE, s1>>>(h16, uw1T16, ub1, ug, ubeta, uw2, ub2,
                                                  pinit, 0.95f, DIM);
    cudaEventRecord(evGate, s1);

    // main: psi (needs prep weights) -> reim
    cudaStreamWaitEvent(0, evPrep, 0);
    hgemm_big<256, false, 1, true><<<dim3(2, 128), thr, smBIG>>>(
        h16, WT16, bc, psi16, rowssp, DIM, 512, 0);
    hgemm_big<256, false, 1, false><<<dim3(2, 128), thr, smBIG>>>(
        psi16, Mp16, nullptr, reim16, nullptr, 512, 512, 0);

    // join gate, then attention weights
    cudaStreamWaitEvent(0, evGate, 0);
    attn_kernel<<<NTOK / 8, thr>>>(reim16, attn16, pinit, gam, rowssp);

    // join VOT, then ao = attn @ VOT^T + ob
    cudaStreamWaitEvent(0, evVot, 0);
    hgemm_big<256, false, 2, false><<<dim3(4, 128), thr, smBIG>>>(
        attn16, VOT16, ob, ao16, nullptr, SS, DIM, 0);

    // h1 = LN(h16 + ao16) -> fp16 kperm'd only
    ln_add_mid_kernel<<<NTOK, 256>>>(h16, ao16, n1g, n1b, h1r16);

    // FFN
    hgemm_big<256, true, 1, false><<<dim3(16, 128), thr, smBIG>>>(
        h1r16, fw1T16, fb1, ff116, nullptr, DIM, DFF, 0);
    hgemm_big<128, false, 2, false><<<dim3(8, 128), thr, smBIG1>>>(
        ff116, fw2T16, fb2, ff216, nullptr, DFF, DIM, 0);

    // out = LN(h1 + ff2)
    ln_add_final_kernel<<<NTOK, 256>>>(h1r16, ff216, n2g, n2b, out);
}

// round 12
// speedup vs baseline: 6.8454x; 1.0447x over previous
#include <cuda_runtime.h>
#include <cuda_fp16.h>
#include <math.h>
#include <stdint.h>

// ---------------- problem constants ----------------
#define BB    4
#define NSEQ  4096
#define NTOK  16384        // BB*NSEQ
#define DIM   1024
#define DH    256
#define SS    256
#define HIDN  32
#define DFF   4096

// ---------------- scratch (device globals: allowed) ----------------
__device__ float g_pinit[NTOK];
__device__ float g_gamma[BB];
__device__ float g_ctxpart[BB * 64 * DIM];
__device__ float g_rowsspart[2 * NTOK];   // per-CTA psi sum-of-squares partials
__device__ float g_bc[512];               // [br | bi]
__device__ float g_VOTpart[4 * DIM * SS]; // split-K fp32 partials
// fp16 GEMM operands (kperm'd where used as GEMM input)
__device__ __half g_h16[NTOK * DIM];
__device__ __half g_psi16[NTOK * 512];    // unnormalized [pr|pi]
__device__ __half g_reim16[NTOK * 512];
__device__ __half g_attn16[NTOK * SS];
__device__ __half g_h1r16[NTOK * DIM];    // h1, fp16, kperm'd (only copy of h1)
__device__ __half g_ff116[NTOK * DFF];
__device__ __half g_ao16[NTOK * DIM];     // plain fp16
__device__ __half g_ff216[NTOK * DIM];    // plain fp16
__device__ __half g_WT16[512 * DIM];
__device__ __half g_uw1T16[HIDN * DIM];
__device__ __half g_Mp16[512 * 512];
__device__ __half g_owT16[DIM * DIM];
__device__ __half g_val16[SS * DIM];
__device__ __half g_VOT16[DIM * SS];
__device__ __half g_fw1T16[DFF * DIM];
__device__ __half g_fw2T16[DIM * DFF];

// ---------------- helpers ----------------
__device__ __forceinline__ int kperm(int k) {
    int r = k & 31;
    int t = (r >> 1) & 3, w = r >> 4, hh = (r >> 3) & 1, j = r & 1;
    return (k & ~31) | (t << 3) | (w << 2) | (hh << 1) | j;
}

__device__ __forceinline__ float gelu_exact(float x) {
    return 0.5f * x * (1.0f + erff(x * 0.7071067811865475f));
}

__device__ __forceinline__ float block_sum_256(float v) {
    __shared__ float sh[8];
    int lane = threadIdx.x & 31, w = threadIdx.x >> 5;
#pragma unroll
    for (int o = 16; o; o >>= 1) v += __shfl_xor_sync(0xffffffffu, v, o);
    if (lane == 0) sh[w] = v;
    __syncthreads();
    float r = (lane < 8) ? sh[lane] : 0.f;
    if (w == 0) {
#pragma unroll
        for (int o = 4; o; o >>= 1) r += __shfl_xor_sync(0xffffffffu, r, o);
        if (lane == 0) sh[0] = r;
    }
    __syncthreads();
    float out = sh[0];
    __syncthreads();
    return out;
}

__device__ __forceinline__ uint32_t smem_u32(const void* p) {
    return (uint32_t)__cvta_generic_to_shared(p);
}
__device__ __forceinline__ void cp16(uint32_t dst, const void* src) {
    asm volatile("cp.async.cg.shared.global [%0], [%1], 16;" :: "r"(dst), "l"(src));
}
__device__ __forceinline__ void cp_commit() { asm volatile("cp.async.commit_group;"); }
template <int N>
__device__ __forceinline__ void cp_wait() { asm volatile("cp.async.wait_group %0;" :: "n"(N)); }

#define MMA_F16(d, a0, a1, a2, a3, b0, b1) \
    asm volatile( \
        "mma.sync.aligned.m16n8k16.row.col.f32.f16.f16.f32 " \
        "{%0,%1,%2,%3}, {%4,%5,%6,%7}, {%8,%9}, {%0,%1,%2,%3};" \
        : "+f"((d)[0]), "+f"((d)[1]), "+f"((d)[2]), "+f"((d)[3]) \
        : "r"(a0), "r"(a1), "r"(a2), "r"(a3), "r"(b0), "r"(b1))

// ============================================================
// BIG fp16 GEMM: 128 x BN CTA tile (BN = 256 or 128), 8 warps.
// 4-stage cp.async pipeline, prefetch distance 2, ONE sync per iter.
// Safety: write target (j+2)%4 vs in-flight reads (j-1)%4 differ (dist 3 mod 4);
// reads 2 iters back are fenced by the intervening barrier.
// ============================================================
template <int BN>
__device__ __forceinline__ void load_slab_h(char* smem, int stage,
                                            const __half* gA, const __half* gB,
                                            int k0, int K, int tid) {
    constexpr int STAGE = (128 + BN) * 64;
    uint32_t base = smem_u32(smem) + stage * STAGE;
#pragma unroll
    for (int i = 0; i < 2; i++) {
        int idx = tid + i * 256;
        int row = idx >> 2, c = idx & 3;
        cp16(base + (uint32_t)(row * 64 + c * 16),
             gA + (size_t)row * K + k0 + c * 8);
    }
    uint32_t bb = base + 128 * 64;
#pragma unroll
    for (int i = 0; i < BN / 64; i++) {
        int idx = tid + i * 256;
        int row = idx >> 2, c = idx & 3;
        cp16(bb + (uint32_t)(row * 64 + c * 16),
             gB + (size_t)row * K + k0 + c * 8);
    }
}

template <int BN, bool GELU, int OMODE, bool SUMSQ>
__global__ __launch_bounds__(256, 1) void hgemm_big(
    const __half* __restrict__ A, const __half* __restrict__ B,
    const float* __restrict__ bias, void* __restrict__ Cv,
    float* __restrict__ rowss, int K, int Ntot, size_t zstride)
{
    extern __shared__ char smem[];
    constexpr int STAGE = (128 + BN) * 64;
    constexpr int NI = BN / 32;

    const int tid = threadIdx.x, wid = tid >> 5, lane = tid & 31;
    const int warp_m = (wid & 1) * 64;
    const int warp_n = (wid >> 1) * (BN / 4);
    const int g = lane >> 2, tg = lane & 3;

    const int kchunk = K / gridDim.z;
    const __half* gA = A + (size_t)blockIdx.y * 128 * K + blockIdx.z * kchunk;
    const __half* gB = B + (size_t)blockIdx.x * BN * K + blockIdx.z * kchunk;
    const int NS = kchunk >> 5;

    float acc[4][NI][4] = {};

    load_slab_h<BN>(smem, 0, gA, gB, 0, K, tid);  cp_commit();
    load_slab_h<BN>(smem, 1, gA, gB, 32, K, tid); cp_commit();

    for (int ks = 0; ks < NS; ks++) {
        if (ks + 2 < NS) {
            load_slab_h<BN>(smem, (ks + 2) & 3, gA, gB, (ks + 2) * 32, K, tid);
            cp_commit();
        }
        int rem = NS - 1 - ks;
        if (rem >= 2) cp_wait<2>();
        else if (rem == 1) cp_wait<1>();
        else cp_wait<0>();
        __syncthreads();

        const __half* As = (const __half*)(smem + (size_t)(ks & 3) * STAGE);
        const __half* Bs = As + 128 * 32;

        uint4 aq[4][2];
#pragma unroll
        for (int mi = 0; mi < 4; mi++) {
            aq[mi][0] = *(const uint4*)(As + (warp_m + mi * 16 + g) * 32 + 8 * tg);
            aq[mi][1] = *(const uint4*)(As + (warp_m + mi * 16 + 8 + g) * 32 + 8 * tg);
        }
        uint4 bq[NI];
#pragma unroll
        for (int ni = 0; ni < NI; ni++)
            bq[ni] = *(const uint4*)(Bs + (warp_n + ni * 8 + g) * 32 + 8 * tg);

#pragma unroll
        for (int mi = 0; mi < 4; mi++) {
#pragma unroll
            for (int ni = 0; ni < NI; ni++) {
                MMA_F16(acc[mi][ni], aq[mi][0].x, aq[mi][1].x, aq[mi][0].y, aq[mi][1].y,
                        bq[ni].x, bq[ni].y);
                MMA_F16(acc[mi][ni], aq[mi][0].z, aq[mi][1].z, aq[mi][0].w, aq[mi][1].w,
                        bq[ni].z, bq[ni].w);
            }
        }
        // no trailing sync (4-stage safety argument above)
    }
    __syncthreads();   // protect smem reuse below; also quiesce lagging readers

    float ss[4][2];
    if (SUMSQ) {
#pragma unroll
        for (int mi = 0; mi < 4; mi++) { ss[mi][0] = 0.f; ss[mi][1] = 0.f; }
    }

#pragma unroll
    for (int mi = 0; mi < 4; mi++) {
        int r0 = blockIdx.y * 128 + warp_m + mi * 16 + g;
#pragma unroll
        for (int ni = 0; ni < NI; ni++) {
            int col = blockIdx.x * BN + warp_n + ni * 8 + 2 * tg;
            float bx = 0.f, by = 0.f;
            if (OMODE != 3 && bias) { bx = bias[col]; by = bias[col + 1]; }
#pragma unroll
            for (int half = 0; half < 2; half++) {
                int row = r0 + half * 8;
                float vx = acc[mi][ni][half * 2 + 0] + bx;
                float vy = acc[mi][ni][half * 2 + 1] + by;
                if (GELU) { vx = gelu_exact(vx); vy = gelu_exact(vy); }
                if (SUMSQ) ss[mi][half] += vx * vx + vy * vy;
                if (OMODE == 1) {
                    *(__half2*)((__half*)Cv + (size_t)row * Ntot + kperm(col)) =
                        __floats2half2_rn(vx, vy);
                } else if (OMODE == 2) {
                    *(__half2*)((__half*)Cv + (size_t)row * Ntot + col) =
                        __floats2half2_rn(vx, vy);
                } else if (OMODE == 3) {
                    *(float2*)((float*)Cv + blockIdx.z * zstride + (size_t)row * Ntot + col) =
                        make_float2(vx, vy);
                } else {
                    *(float2*)((float*)Cv + (size_t)row * Ntot + col) = make_float2(vx, vy);
                }
            }
        }
    }

    if (SUMSQ) {
        float* red = (float*)smem;   // [128][4]
#pragma unroll
        for (int mi = 0; mi < 4; mi++) {
#pragma unroll
            for (int half = 0; half < 2; half++) {
                float v = ss[mi][half];
                v += __shfl_xor_sync(0xffffffffu, v, 1);
                v += __shfl_xor_sync(0xffffffffu, v, 2);
                if (tg == 0) {
                    int rl = warp_m + mi * 16 + half * 8 + g;
                    red[rl * 4 + (wid >> 1)] = v;
                }
            }
        }
        __syncthreads();
        if (tid < 128) {
            float tot = red[tid * 4] + red[tid * 4 + 1] + red[tid * 4 + 2] + red[tid * 4 + 3];
            rowss[blockIdx.x * NTOK + blockIdx.y * 128 + tid] = tot;
        }
    }
}

// ============================================================
// Gate GEMM (N = 32) with FUSED finish, 6-stage pipeline.
// ============================================================
__device__ __forceinline__ void load_slab_h32(char* smem, int stage,
                                              const __half* gA, const __half* gB,
                                              int k0, int K, int tid) {
    constexpr int STAGE = (128 + 32) * 64;
    uint32_t base = smem_u32(smem) + stage * STAGE;
#pragma unroll
    for (int i = 0; i < 2; i++) {
        int idx = tid + i * 256;
        int row = idx >> 2, c = idx & 3;
        cp16(base + (uint32_t)(row * 64 + c * 16),
             gA + (size_t)row * K + k0 + c * 8);
    }
    uint32_t bb = base + 128 * 64;
    if (tid < 128) {
        int row = tid >> 2, c = tid & 3;
        cp16(bb + (uint32_t)(row * 64 + c * 16),
             gB + (size_t)row * K + k0 + c * 8);
    }
}

__global__ __launch_bounds__(256) void hgemm_gate(
    const __half* __restrict__ A, const __half* __restrict__ B,
    const float* __restrict__ b1, const float* __restrict__ gain,
    const float* __restrict__ beta, const float* __restrict__ w2,
    const float* __restrict__ b2, float* __restrict__ pinit,
    float scale, int K)
{
    extern __shared__ char smem[];
    constexpr int STAGE = (128 + 32) * 64;

    const int tid = threadIdx.x, wid = tid >> 5, lane = tid & 31;
    const int warp_m = wid * 16;
    const int gg2 = lane >> 2, tg = lane & 3;

    const __half* gA = A + (size_t)blockIdx.y * 128 * K;
    const __half* gB = B;
    const int NS = K >> 5;

    float acc[4][4] = {};

#pragma unroll
    for (int s = 0; s < 5; s++) {
        load_slab_h32(smem, s, gA, gB, s * 32, K, tid);
        cp_commit();
    }

    for (int ks = 0; ks < NS; ks++) {
        if (ks + 5 < NS) {
            load_slab_h32(smem, (ks + 5) % 6, gA, gB, (ks + 5) * 32, K, tid);
            cp_commit();
        }
        int rem = NS - 1 - ks;
        if (rem >= 5) cp_wait<5>();
        else if (rem == 4) cp_wait<4>();
        else if (rem == 3) cp_wait<3>();
        else if (rem == 2) cp_wait<2>();
        else if (rem == 1) cp_wait<1>();
        else cp_wait<0>();
        __syncthreads();

        const __half* As = (const __half*)(smem + (size_t)(ks % 6) * STAGE);
        const __half* Bs = As + 128 * 32;

        uint4 alo = *(const uint4*)(As + (warp_m + gg2) * 32 + 8 * tg);
        uint4 ahi = *(const uint4*)(As + (warp_m + 8 + gg2) * 32 + 8 * tg);
        uint4 bq[4];
#pragma unroll
        for (int ni = 0; ni < 4; ni++)
            bq[ni] = *(const uint4*)(Bs + (ni * 8 + gg2) * 32 + 8 * tg);
#pragma unroll
        for (int ni = 0; ni < 4; ni++) {
            MMA_F16(acc[ni], alo.x, ahi.x, alo.y, ahi.y, bq[ni].x, bq[ni].y);
            MMA_F16(acc[ni], alo.z, ahi.z, alo.w, ahi.w, bq[ni].z, bq[ni].w);
        }
        __syncthreads();
    }

#pragma unroll
    for (int half = 0; half < 2; half++) {
        float vv[8];
        float sum = 0.f;
#pragma unroll
        for (int ni = 0; ni < 4; ni++) {
#pragma unroll
            for (int j = 0; j < 2; j++) {
                int col = ni * 8 + 2 * tg + j;
                float v = acc[ni][half * 2 + j] + b1[col];
                vv[ni * 2 + j] = v;
                sum += v;
            }
        }
        sum += __shfl_xor_sync(0xffffffffu, sum, 1);
        sum += __shfl_xor_sync(0xffffffffu, sum, 2);
        float m = sum * (1.f / 32.f);
        float s2 = 0.f;
#pragma unroll
        for (int q = 0; q < 8; q++) { float d = vv[q] - m; s2 += d * d; }
        s2 += __shfl_xor_sync(0xffffffffu, s2, 1);
        s2 += __shfl_xor_sync(0xffffffffu, s2, 2);
        float inv = rsqrtf(s2 * (1.f / 32.f) + 1e-5f);
        float p = 0.f;
#pragma unroll
        for (int ni = 0; ni < 4; ni++) {
#pragma unroll
            for (int j = 0; j < 2; j++) {
                int col = ni * 8 + 2 * tg + j;
                float tn = (vv[ni * 2 + j] - m) * inv * gain[col] + beta[col];
                float si = tn / (1.f + expf(-tn));
                p += si * w2[col];
            }
        }
        p += __shfl_xor_sync(0xffffffffu, p, 1);
        p += __shfl_xor_sync(0xffffffffu, p, 2);
        if (tg == 0) {
            int row = blockIdx.y * 128 + warp_m + half * 8 + gg2;
            pinit[row] = scale / (1.f + expf(-(p + b2[0])));
        }
    }
}

// ============================================================
// PREP megakernel (job table). All blocks 256 threads.
// ============================================================
__device__ __forceinline__ void transpose_tile(const float* in, __half* out,
                                               int R, int C, int lb, int tid) {
    __shared__ float t[32][33];
    int nbx = C >> 5;
    int bx = lb % nbx, by = lb / nbx;
    int c0 = bx * 32, r0 = by * 32;
    int x = tid & 31, y = tid >> 5;
#pragma unroll
    for (int dy = 0; dy < 32; dy += 8)
        t[y + dy][x] = in[(size_t)(r0 + y + dy) * C + c0 + x];
    __syncthreads();
#pragma unroll
    for (int dy = 0; dy < 32; dy += 8)
        out[(size_t)(c0 + y + dy) * R + kperm(r0 + x)] = __float2half_rn(t[x][y + dy]);
}

__global__ void prep_kernel(
    const float* __restrict__ Wr, const float* __restrict__ Wi,
    const float* __restrict__ uw1, const float* __restrict__ ow,
    const float* __restrict__ fw1, const float* __restrict__ fw2,
    const float* __restrict__ values,
    const float* __restrict__ mr, const float* __restrict__ mi,
    const float* __restrict__ br, const float* __restrict__ bi,
    __half* __restrict__ WT16, __half* __restrict__ uw1T16,
    __half* __restrict__ owT16, __half* __restrict__ fw1T16,
    __half* __restrict__ fw2T16, __half* __restrict__ val16,
    __half* __restrict__ Mp16, float* __restrict__ bc)
{
    int b = blockIdx.x, tid = threadIdx.x;
    if (b < 256) { transpose_tile(Wr, WT16, DIM, DH, b, tid); return; }
    b -= 256;
    if (b < 256) { transpose_tile(Wi, WT16 + 256 * DIM, DIM, DH, b, tid); return; }
    b -= 256;
    if (b < 32)  { transpose_tile(uw1, uw1T16, DIM, HIDN, b, tid); return; }
    b -= 32;
    if (b < 1024){ transpose_tile(ow, owT16, DIM, DIM, b, tid); return; }
    b -= 1024;
    if (b < 4096){ transpose_tile(fw1, fw1T16, DIM, DFF, b, tid); return; }
    b -= 4096;
    if (b < 4096){ transpose_tile(fw2, fw2T16, DFF, DIM, b, tid); return; }
    b -= 4096;
    if (b < 256) {
        int i = (b * 256 + tid) * 4;
        float4 v = *(const float4*)(values + i);
        int p0 = kperm(i);
        *(__half2*)(val16 + p0) = __floats2half2_rn(v.x, v.y);
        *(__half2*)(val16 + p0 + 8) = __floats2half2_rn(v.z, v.w);
        return;
    }
    b -= 256;
    if (b < 256) {
        int s = b, d = tid;
        float a = mr[s * DH + d], bb2 = mi[s * DH + d];
        float tot = block_sum_256(a * a + bb2 * bb2);
        float inv = 1.f / fmaxf(sqrtf(tot), 1e-12f);
        float ra = a * inv, rb = bb2 * inv;
        Mp16[(size_t)s * 512 + kperm(d)] = __float2half_rn(ra);
        Mp16[(size_t)s * 512 + kperm(256 + d)] = __float2half_rn(rb);
        Mp16[(size_t)(256 + s) * 512 + kperm(d)] = __float2half_rn(rb);
        Mp16[(size_t)(256 + s) * 512 + kperm(256 + d)] = __float2half_rn(-ra);
        return;
    }
    {
        bc[tid] = br[tid];
        bc[256 + tid] = bi[tid];
    }
}
#define PREP_BLOCKS (256 + 256 + 32 + 1024 + 4096 + 4096 + 256 + 256 + 1)

// ---------------- elementwise kernels ----------------
// ctx partials (64-row chunks) + h -> h16 (kperm'd), vectorized:
// float4 reads, __half2 writes. grid (1, BB, 64), block 256.
__global__ void ctx_partial_cvt_kernel(const float* __restrict__ h,
                                       float* __restrict__ part,
                                       __half* __restrict__ h16) {
    int tid = threadIdx.x;
    int d0 = tid * 4;
    int b = blockIdx.y, c = blockIdx.z;
    int p0 = kperm(d0);
    size_t row0 = (size_t)b * NSEQ + c * 64;
    const float* base = h + row0 * DIM;
    float s0 = 0.f, s1 = 0.f, s2 = 0.f, s3 = 0.f;
#pragma unroll 4
    for (int n = 0; n < 64; n++) {
        float4 v = *(const float4*)(base + (size_t)n * DIM + d0);
        s0 += v.x; s1 += v.y; s2 += v.z; s3 += v.w;
        __half* hr = h16 + (row0 + n) * DIM;
        *(__half2*)(hr + p0) = __floats2half2_rn(v.x, v.y);
        *(__half2*)(hr + p0 + 8) = __floats2half2_rn(v.z, v.w);
    }
    *(float4*)(part + (size_t)(b * 64 + c) * DIM + d0) = make_float4(s0, s1, s2, s3);
}

// fused: ctx mean + full gamma gate. grid = BB, block = 1024.
__global__ __launch_bounds__(1024) void ctxgate_kernel(
    const float* __restrict__ part,
    const float* __restrict__ w1, const float* __restrict__ b1,
    const float* __restrict__ gain, const float* __restrict__ beta,
    const float* __restrict__ w2, const float* __restrict__ b2,
    float* __restrict__ gamma)
{
    __shared__ float cs[DIM];
    __shared__ float tj[HIDN];
    int b = blockIdx.x, tid = threadIdx.x;
    int w = tid >> 5, l = tid & 31;

    float s = 0.f;
#pragma unroll
    for (int c = 0; c < 64; c++) s += part[(size_t)(b * 64 + c) * DIM + tid];
    cs[tid] = s * (1.f / (float)NSEQ);
    __syncthreads();

    float acc = 0.f;
#pragma unroll 8
    for (int it = 0; it < DIM / 32; it++) {
        int d = l + it * 32;
        acc += cs[d] * w1[d * HIDN + w];
    }
#pragma unroll
    for (int o = 16; o; o >>= 1) acc += __shfl_xor_sync(0xffffffffu, acc, o);
    if (l == 0) tj[w] = acc + b1[w];
    __syncthreads();

    if (tid < HIDN) {
        float v = tj[tid];
        float m = v;
#pragma unroll
        for (int o = 16; o; o >>= 1) m += __shfl_xor_sync(0xffffffffu, m, o);
        m *= (1.f / 32.f);
        float d = v - m;
        float var = d * d;
#pragma unroll
        for (int o = 16; o; o >>= 1) var += __shfl_xor_sync(0xffffffffu, var, o);
        var *= (1.f / 32.f);
        float tn = d * rsqrtf(var + 1e-5f) * gain[tid] + beta[tid];
        float si = tn / (1.f + expf(-tn));
        float p = si * w2[tid];
#pragma unroll
        for (int o = 16; o; o >>= 1) p += __shfl_xor_sync(0xffffffffu, p, o);
        if (tid == 0) gamma[b] = 1.f / (1.f + expf(-(p + b2[0])));
    }
}

// combine 4 split-K partials -> fp16 kperm'd VOT
__global__ void cvt_vot_kernel(const float* __restrict__ part, __half* __restrict__ out) {
    int i = (blockIdx.x * 256 + threadIdx.x) * 4;
    const int SZ = DIM * SS;
    float4 a = *(const float4*)(part + i);
    float4 b = *(const float4*)(part + SZ + i);
    float4 c = *(const float4*)(part + 2 * SZ + i);
    float4 d = *(const float4*)(part + 3 * SZ + i);
    float x = a.x + b.x + c.x + d.x;
    float y = a.y + b.y + c.y + d.y;
    float z = a.z + b.z + c.z + d.z;
    float w = a.w + b.w + c.w + d.w;
    int p0 = kperm(i);
    *(__half2*)(out + p0) = __floats2half2_rn(x, y);
    *(__half2*)(out + p0 + 8) = __floats2half2_rn(z, w);
}

// attention weights: warp per row
__global__ void attn_kernel(const __half* __restrict__ reim16, __half* __restrict__ attn16,
                            const float* __restrict__ pinit, const float* __restrict__ gamma,
                            const float* __restrict__ rowssp) {
    int wid = threadIdx.x >> 5, lane = threadIdx.x & 31;
    int row = blockIdx.x * 8 + wid;
    int b = row >> 12;
    float p = pinit[row] * (1.f - gamma[b]);
    float inv_n2 = 1.f / fmaxf(rowssp[row] + rowssp[NTOK + row], 1e-24f);
    float c1 = (1.f - p) * inv_n2, c0 = p * (1.f / (float)DH);
    size_t base = (size_t)row * 512;
    float raw[8];
    float tot = 0.f;
#pragma unroll
    for (int q = 0; q < 8; q++) {
        int s = lane + q * 32;
        float r = __half2float(reim16[base + s]);
        float i = __half2float(reim16[base + 256 + s]);
        raw[q] = c1 * (r * r + i * i) + c0;
        tot += raw[q];
    }
#pragma unroll
    for (int o = 16; o; o >>= 1) tot += __shfl_xor_sync(0xffffffffu, tot, o);
    float inv = 1.f / (tot + 1e-8f);
#pragma unroll
    for (int q = 0; q < 8; q++)
        attn16[(size_t)row * SS + lane + q * 32] = __float2half_rn(raw[q] * inv);
}

// mid LN: h1 = LN(h16 + ao16); writes ONLY fp16 kperm'd copy
__global__ void ln_add_mid_kernel(const __half* __restrict__ a, const __half* __restrict__ bsrc,
                                  const float* __restrict__ g, const float* __restrict__ beta,
                                  __half* __restrict__ outr) {
    size_t off = (size_t)blockIdx.x * DIM;
    int tid = threadIdx.x;
    float v[4];
    float s = 0.f;
#pragma unroll
    for (int q = 0; q < 4; q++) {
        int i = tid + q * 256;
        v[q] = __half2float(a[off + kperm(i)]) + __half2float(bsrc[off + i]);
        s += v[q];
    }
    float mu = block_sum_256(s) * (1.f / (float)DIM);
    float s2 = 0.f;
#pragma unroll
    for (int q = 0; q < 4; q++) {
        float d = v[q] - mu;
        s2 += d * d;
    }
    float var = block_sum_256(s2) * (1.f / (float)DIM);
    float inv = rsqrtf(var + 1e-5f);
#pragma unroll
    for (int q = 0; q < 4; q++) {
        int i = tid + q * 256;
        float o = (v[q] - mu) * inv * g[i] + beta[i];
        outr[off + kperm(i)] = __float2half_rn(o);
    }
}

// final LN: out = LN(h1r16[kperm] + ff216)
__global__ void ln_add_final_kernel(const __half* __restrict__ a, const __half* __restrict__ bsrc,
                                    const float* __restrict__ g, const float* __restrict__ beta,
                                    float* __restrict__ out) {
    size_t off = (size_t)blockIdx.x * DIM;
    int tid = threadIdx.x;
    float v[4];
    float s = 0.f;
#pragma unroll
    for (int q = 0; q < 4; q++) {
        int i = tid + q * 256;
        v[q] = __half2float(a[off + kperm(i)]) + __half2float(bsrc[off + i]);
        s += v[q];
    }
    float mu = block_sum_256(s) * (1.f / (float)DIM);
    float s2 = 0.f;
#pragma unroll
    for (int q = 0; q < 4; q++) {
        float d = v[q] - mu;
        s2 += d * d;
    }
    float var = block_sum_256(s2) * (1.f / (float)DIM);
    float inv = rsqrtf(var + 1e-5f);
#pragma unroll
    for (int q = 0; q < 4; q++) {
        int i = tid + q * 256;
        out[off + i] = (v[q] - mu) * inv * g[i] + beta[i];
    }
}

// ---------------- launch ----------------
static inline void* symv(const void* s) {
    void* p = nullptr;
    cudaGetSymbolAddress(&p, s);
    return p;
}

extern "C" void kernel_launch(void* const* d_in, const int* in_sizes, int n_in,
                              void* d_out, int out_size) {
    const float* h     = (const float*)d_in[0];
    const float* Wr    = (const float*)d_in[1];
    const float* br    = (const float*)d_in[2];
    const float* Wi    = (const float*)d_in[3];
    const float* bi    = (const float*)d_in[4];
    const float* uw1   = (const float*)d_in[5];
    const float* ub1   = (const float*)d_in[6];
    const float* ug    = (const float*)d_in[7];
    const float* ubeta = (const float*)d_in[8];
    const float* uw2   = (const float*)d_in[9];
    const float* ub2   = (const float*)d_in[10];
    const float* gw1   = (const float*)d_in[11];
    const float* gb1   = (const float*)d_in[12];
    const float* gg    = (const float*)d_in[13];
    const float* gbeta = (const float*)d_in[14];
    const float* gw2   = (const float*)d_in[15];
    const float* gb2   = (const float*)d_in[16];
    const float* m_real= (const float*)d_in[17];
    const float* m_imag= (const float*)d_in[18];
    const float* values= (const float*)d_in[19];
    const float* ow    = (const float*)d_in[20];
    const float* ob    = (const float*)d_in[21];
    const float* n1g   = (const float*)d_in[22];
    const float* n1b   = (const float*)d_in[23];
    const float* n2g   = (const float*)d_in[24];
    const float* n2b   = (const float*)d_in[25];
    const float* fw1   = (const float*)d_in[26];
    const float* fb1   = (const float*)d_in[27];
    const float* fw2   = (const float*)d_in[28];
    const float* fb2   = (const float*)d_in[29];
    float* out = (float*)d_out;

    float* pinit = (float*)symv(g_pinit);
    float* gam   = (float*)symv(g_gamma);
    float* ctxp  = (float*)symv(g_ctxpart);
    float* rowssp= (float*)symv(g_rowsspart);
    float* bc    = (float*)symv(g_bc);
    float* VOTp  = (float*)symv(g_VOTpart);
    __half* h16    = (__half*)symv(g_h16);
    __half* psi16  = (__half*)symv(g_psi16);
    __half* reim16 = (__half*)symv(g_reim16);
    __half* attn16 = (__half*)symv(g_attn16);
    __half* h1r16  = (__half*)symv(g_h1r16);
    __half* ff116  = (__half*)symv(g_ff116);
    __half* ao16   = (__half*)symv(g_ao16);
    __half* ff216  = (__half*)symv(g_ff216);
    __half* WT16   = (__half*)symv(g_WT16);
    __half* uw1T16 = (__half*)symv(g_uw1T16);
    __half* Mp16   = (__half*)symv(g_Mp16);
    __half* owT16  = (__half*)symv(g_owT16);
    __half* val16  = (__half*)symv(g_val16);
    __half* VOT16  = (__half*)symv(g_VOT16);
    __half* fw1T16 = (__half*)symv(g_fw1T16);
    __half* fw2T16 = (__half*)symv(g_fw2T16);

    const int smBIG  = (128 + 256) * 64 * 4;   // 98304
    const int smBIG1 = (128 + 128) * 64 * 4;   // 65536
    const int smGATE = (128 + 32) * 64 * 6;    // 61440
    cudaFuncSetAttribute(hgemm_big<256, false, 1, false>, cudaFuncAttributeMaxDynamicSharedMemorySize, smBIG);
    cudaFuncSetAttribute(hgemm_big<256, false, 1, true >, cudaFuncAttributeMaxDynamicSharedMemorySize, smBIG);
    cudaFuncSetAttribute(hgemm_big<256, false, 2, false>, cudaFuncAttributeMaxDynamicSharedMemorySize, smBIG);
    cudaFuncSetAttribute(hgemm_big<256, false, 3, false>, cudaFuncAttributeMaxDynamicSharedMemorySize, smBIG);
    cudaFuncSetAttribute(hgemm_big<256, true,  1, false>, cudaFuncAttributeMaxDynamicSharedMemorySize, smBIG);
    cudaFuncSetAttribute(hgemm_big<128, false, 2, false>, cudaFuncAttributeMaxDynamicSharedMemorySize, smBIG1);
    cudaFuncSetAttribute(hgemm_gate, cudaFuncAttributeMaxDynamicSharedMemorySize, smGATE);

    // fork-join streams/events (created once, outside capture on first call)
    static cudaStream_t s1 = nullptr, s2 = nullptr;
    static cudaEvent_t evEntry = nullptr, evPrep = nullptr, evCtx = nullptr,
                       evGate = nullptr, evVot = nullptr;
    if (!s1) {
        cudaStreamCreateWithFlags(&s1, cudaStreamNonBlocking);
        cudaStreamCreateWithFlags(&s2, cudaStreamNonBlocking);
        cudaEventCreateWithFlags(&evEntry, cudaEventDisableTiming);
        cudaEventCreateWithFlags(&evPrep, cudaEventDisableTiming);
        cudaEventCreateWithFlags(&evCtx, cudaEventDisableTiming);
        cudaEventCreateWithFlags(&evGate, cudaEventDisableTiming);
        cudaEventCreateWithFlags(&evVot, cudaEventDisableTiming);
    }

    dim3 thr(256);

    // fork s2 from entry: weight prep + VOT chain
    cudaEventRecord(evEntry, 0);
    cudaStreamWaitEvent(s2, evEntry, 0);
    prep_kernel<<<PREP_BLOCKS, thr, 0, s2>>>(Wr, Wi, uw1, ow, fw1, fw2, values,
                                             m_real, m_imag, br, bi,
                                             WT16, uw1T16, owT16, fw1T16, fw2T16,
                                             val16, Mp16, bc);
    cudaEventRecord(evPrep, s2);
    // s2 continues: VOT split-K + combine
    hgemm_big<256, false, 3, false><<<dim3(1, 8, 4), thr, smBIG, s2>>>(
        owT16, val16, nullptr, VOTp, nullptr, DIM, SS, (size_t)DIM * SS);
    cvt_vot_kernel<<<DIM * SS / 1024, thr, 0, s2>>>(VOTp, VOT16);
    cudaEventRecord(evVot, s2);

    // main: ctx partials + h -> h16 (overlaps prep)
    ctx_partial_cvt_kernel<<<dim3(1, BB, 64), thr>>>(h, ctxp, h16);
    cudaEventRecord(evCtx, 0);

    // s1: gamma gate + uncertainty gate (overlap psi/reim on main)
    cudaStreamWaitEvent(s1, evCtx, 0);
    cudaStreamWaitEvent(s1, evPrep, 0);
    ctxgate_kernel<<<BB, 1024, 0, s1>>>(ctxp, gw1, gb1, gg, gbeta, gw2, gb2, gam);
    hgemm_gate<<<dim3(1, 128), thr, smGATE, s1>>>(h16, uw1T16, ub1, ug, ubeta, uw2, ub2,
                                                  pinit, 0.95f, DIM);
    cudaEventRecord(evGate, s1);

    // main: psi (needs prep weights) -> reim
    cudaStreamWaitEvent(0, evPrep, 0);
    hgemm_big<256, false, 1, true><<<dim3(2, 128), thr, smBIG>>>(
        h16, WT16, bc, psi16, rowssp, DIM, 512, 0);
    hgemm_big<256, false, 1, false><<<dim3(2, 128), thr, smBIG>>>(
        psi16, Mp16, nullptr, reim16, nullptr, 512, 512, 0);

    // join gate, then attention weights
    cudaStreamWaitEvent(0, evGate, 0);
    attn_kernel<<<NTOK / 8, thr>>>(reim16, attn16, pinit, gam, rowssp);

    // join VOT, then ao = attn @ VOT^T + ob
    cudaStreamWaitEvent(0, evVot, 0);
    hgemm_big<256, false, 2, false><<<dim3(4, 128), thr, smBIG>>>(
        attn16, VOT16, ob, ao16, nullptr, SS, DIM, 0);

    // h1 = LN(h16 + ao16) -> fp16 kperm'd only
    ln_add_mid_kernel<<<NTOK, 256>>>(h16, ao16, n1g, n1b, h1r16);

    // FFN
    hgemm_big<256, true, 1, false><<<dim3(16, 128), thr, smBIG>>>(
        h1r16, fw1T16, fb1, ff116, nullptr, DIM, DFF, 0);
    hgemm_big<128, false, 2, false><<<dim3(8, 128), thr, smBIG1>>>(
        ff116, fw2T16, fb2, ff216, nullptr, DFF, DIM, 0);

    // out = LN(h1 + ff2)
    ln_add_final_kernel<<<NTOK, 256>>>(h1r16, ff216, n2g, n2b, out);
}

// round 13
// speedup vs baseline: 6.8981x; 1.0077x over previous
#include <cuda_runtime.h>
#include <cuda_fp16.h>
#include <math.h>
#include <stdint.h>

// ---------------- problem constants ----------------
#define BB    4
#define NSEQ  4096
#define NTOK  16384        // BB*NSEQ
#define DIM   1024
#define DH    256
#define SS    256
#define HIDN  32
#define DFF   4096

// ---------------- scratch (device globals: allowed) ----------------
__device__ float g_pinit[NTOK];
__device__ float g_gamma[BB];
__device__ float g_ctxpart[BB * 128 * DIM];
__device__ float g_rowsspart[2 * NTOK];   // psi sum-of-squares partials
__device__ float g_ovsump[2 * NTOK];      // overlap-sum partials
__device__ float g_alpha[NTOK];           // attn row scale (c1/D)
__device__ float g_beta[NTOK];            // attn row offset scale (c0/D)
__device__ float g_votS[DIM];             // colsum of VOT
__device__ float g_bc[512];               // [br | bi]
__device__ float g_VOTpart[4 * DIM * SS]; // split-K fp32 partials
// fp16 GEMM operands (kperm'd where used as GEMM input)
__device__ __half g_h16[NTOK * DIM];
__device__ __half g_psi16[NTOK * 512];    // unnormalized [pr|pi]
__device__ __half g_ov16[NTOK * SS];      // overlap, kperm'd on s
__device__ __half g_h1r16[NTOK * DIM];    // h1, fp16, kperm'd
__device__ __half g_ff116[NTOK * DFF];
__device__ __half g_ao16[NTOK * DIM];     // plain fp16
__device__ __half g_ff216[NTOK * DIM];    // plain fp16
__device__ __half g_WT16[512 * DIM];
__device__ __half g_uw1T16[HIDN * DIM];
__device__ __half g_Mp16[512 * 512];      // INTERLEAVED: row 2s=[Mr|Mi], 2s+1=[Mi|-Mr]
__device__ __half g_owT16[DIM * DIM];
__device__ __half g_val16[SS * DIM];
__device__ __half g_VOT16[DIM * SS];
__device__ __half g_fw1T16[DFF * DIM];
__device__ __half g_fw2T16[DIM * DFF];

// ---------------- helpers ----------------
__device__ __forceinline__ int kperm(int k) {
    int r = k & 31;
    int t = (r >> 1) & 3, w = r >> 4, hh = (r >> 3) & 1, j = r & 1;
    return (k & ~31) | (t << 3) | (w << 2) | (hh << 1) | j;
}

__device__ __forceinline__ float gelu_exact(float x) {
    return 0.5f * x * (1.0f + erff(x * 0.7071067811865475f));
}

__device__ __forceinline__ float block_sum_256(float v) {
    __shared__ float sh[8];
    int lane = threadIdx.x & 31, w = threadIdx.x >> 5;
#pragma unroll
    for (int o = 16; o; o >>= 1) v += __shfl_xor_sync(0xffffffffu, v, o);
    if (lane == 0) sh[w] = v;
    __syncthreads();
    float r = (lane < 8) ? sh[lane] : 0.f;
    if (w == 0) {
#pragma unroll
        for (int o = 4; o; o >>= 1) r += __shfl_xor_sync(0xffffffffu, r, o);
        if (lane == 0) sh[0] = r;
    }
    __syncthreads();
    float out = sh[0];
    __syncthreads();
    return out;
}

__device__ __forceinline__ uint32_t smem_u32(const void* p) {
    return (uint32_t)__cvta_generic_to_shared(p);
}
__device__ __forceinline__ void cp16(uint32_t dst, const void* src) {
    asm volatile("cp.async.cg.shared.global [%0], [%1], 16;" :: "r"(dst), "l"(src));
}
__device__ __forceinline__ void cp_commit() { asm volatile("cp.async.commit_group;"); }
template <int N>
__device__ __forceinline__ void cp_wait() { asm volatile("cp.async.wait_group %0;" :: "n"(N)); }

#define MMA_F16(d, a0, a1, a2, a3, b0, b1) \
    asm volatile( \
        "mma.sync.aligned.m16n8k16.row.col.f32.f16.f16.f32 " \
        "{%0,%1,%2,%3}, {%4,%5,%6,%7}, {%8,%9}, {%0,%1,%2,%3};" \
        : "+f"((d)[0]), "+f"((d)[1]), "+f"((d)[2]), "+f"((d)[3]) \
        : "r"(a0), "r"(a1), "r"(a2), "r"(a3), "r"(b0), "r"(b1))

// ============================================================
// BIG fp16 GEMM: 128 x BN CTA tile, 8 warps, 4-stage pipeline, 1 sync/iter.
// OMODE: 1 fp16 kperm'd, 2 fp16 plain, 3 fp32 split-K partial,
//        4 overlap: col pairs (re,im) -> ov = re^2+im^2, fp16 kperm'd on s,
//        5 attn-affine: alpha_row*acc + beta_row*S_col + bias_col, fp16 plain.
// SUMSQ: per-row sum of (vx^2+vy^2) partials -> rowss[bx*NTOK+row].
// ============================================================
template <int BN>
__device__ __forceinline__ void load_slab_h(char* smem, int stage,
                                            const __half* gA, const __half* gB,
                                            int k0, int K, int tid) {
    constexpr int STAGE = (128 + BN) * 64;
    uint32_t base = smem_u32(smem) + stage * STAGE;
#pragma unroll
    for (int i = 0; i < 2; i++) {
        int idx = tid + i * 256;
        int row = idx >> 2, c = idx & 3;
        cp16(base + (uint32_t)(row * 64 + c * 16),
             gA + (size_t)row * K + k0 + c * 8);
    }
    uint32_t bb = base + 128 * 64;
#pragma unroll
    for (int i = 0; i < BN / 64; i++) {
        int idx = tid + i * 256;
        int row = idx >> 2, c = idx & 3;
        cp16(bb + (uint32_t)(row * 64 + c * 16),
             gB + (size_t)row * K + k0 + c * 8);
    }
}

template <int BN, bool GELU, int OMODE, bool SUMSQ>
__global__ __launch_bounds__(256, 1) void hgemm_big(
    const __half* __restrict__ A, const __half* __restrict__ B,
    const float* __restrict__ bias, void* __restrict__ Cv,
    float* __restrict__ rowss,
    const float* __restrict__ rowalpha, const float* __restrict__ rowbeta,
    const float* __restrict__ colS,
    int K, int Ntot, size_t zstride)
{
    extern __shared__ char smem[];
    constexpr int STAGE = (128 + BN) * 64;
    constexpr int NI = BN / 32;

    const int tid = threadIdx.x, wid = tid >> 5, lane = tid & 31;
    const int warp_m = (wid & 1) * 64;
    const int warp_n = (wid >> 1) * (BN / 4);
    const int g = lane >> 2, tg = lane & 3;

    const int kchunk = K / gridDim.z;
    const __half* gA = A + (size_t)blockIdx.y * 128 * K + blockIdx.z * kchunk;
    const __half* gB = B + (size_t)blockIdx.x * BN * K + blockIdx.z * kchunk;
    const int NS = kchunk >> 5;

    float acc[4][NI][4] = {};

    load_slab_h<BN>(smem, 0, gA, gB, 0, K, tid);  cp_commit();
    load_slab_h<BN>(smem, 1, gA, gB, 32, K, tid); cp_commit();

    for (int ks = 0; ks < NS; ks++) {
        if (ks + 2 < NS) {
            load_slab_h<BN>(smem, (ks + 2) & 3, gA, gB, (ks + 2) * 32, K, tid);
            cp_commit();
        }
        int rem = NS - 1 - ks;
        if (rem >= 2) cp_wait<2>();
        else if (rem == 1) cp_wait<1>();
        else cp_wait<0>();
        __syncthreads();

        const __half* As = (const __half*)(smem + (size_t)(ks & 3) * STAGE);
        const __half* Bs = As + 128 * 32;

        uint4 aq[4][2];
#pragma unroll
        for (int mi = 0; mi < 4; mi++) {
            aq[mi][0] = *(const uint4*)(As + (warp_m + mi * 16 + g) * 32 + 8 * tg);
            aq[mi][1] = *(const uint4*)(As + (warp_m + mi * 16 + 8 + g) * 32 + 8 * tg);
        }
        uint4 bq[NI];
#pragma unroll
        for (int ni = 0; ni < NI; ni++)
            bq[ni] = *(const uint4*)(Bs + (warp_n + ni * 8 + g) * 32 + 8 * tg);

#pragma unroll
        for (int mi = 0; mi < 4; mi++) {
#pragma unroll
            for (int ni = 0; ni < NI; ni++) {
                MMA_F16(acc[mi][ni], aq[mi][0].x, aq[mi][1].x, aq[mi][0].y, aq[mi][1].y,
                        bq[ni].x, bq[ni].y);
                MMA_F16(acc[mi][ni], aq[mi][0].z, aq[mi][1].z, aq[mi][0].w, aq[mi][1].w,
                        bq[ni].z, bq[ni].w);
            }
        }
        // no trailing sync (4-stage, prefetch distance 2)
    }
    __syncthreads();

    float ss[4][2];
    if (SUMSQ) {
#pragma unroll
        for (int mi = 0; mi < 4; mi++) { ss[mi][0] = 0.f; ss[mi][1] = 0.f; }
    }

#pragma unroll
    for (int mi = 0; mi < 4; mi++) {
        int r0 = blockIdx.y * 128 + warp_m + mi * 16 + g;
#pragma unroll
        for (int ni = 0; ni < NI; ni++) {
            int col = blockIdx.x * BN + warp_n + ni * 8 + 2 * tg;
            float bx = 0.f, by = 0.f;
            if ((OMODE == 1 || OMODE == 2 || OMODE == 5) && bias) {
                bx = bias[col]; by = bias[col + 1];
            }
#pragma unroll
            for (int half = 0; half < 2; half++) {
                int row = r0 + half * 8;
                float vx = acc[mi][ni][half * 2 + 0];
                float vy = acc[mi][ni][half * 2 + 1];
                if (OMODE == 4) {
                    float ov = vx * vx + vy * vy;
                    if (SUMSQ) ss[mi][half] += ov;
                    int s = col >> 1;
                    ((__half*)Cv)[(size_t)row * Ntot + kperm(s)] = __float2half_rn(ov);
                    continue;
                }
                if (OMODE == 5) {
                    float al = rowalpha[row], be = rowbeta[row];
                    vx = al * vx + be * colS[col] + bx;
                    vy = al * vy + be * colS[col + 1] + by;
                } else {
                    vx += bx; vy += by;
                }
                if (GELU) { vx = gelu_exact(vx); vy = gelu_exact(vy); }
                if (SUMSQ) ss[mi][half] += vx * vx + vy * vy;
                if (OMODE == 1) {
                    *(__half2*)((__half*)Cv + (size_t)row * Ntot + kperm(col)) =
                        __floats2half2_rn(vx, vy);
                } else if (OMODE == 2 || OMODE == 5) {
                    *(__half2*)((__half*)Cv + (size_t)row * Ntot + col) =
                        __floats2half2_rn(vx, vy);
                } else if (OMODE == 3) {
                    *(float2*)((float*)Cv + blockIdx.z * zstride + (size_t)row * Ntot + col) =
                        make_float2(vx, vy);
                }
            }
        }
    }

    if (SUMSQ) {
        float* red = (float*)smem;   // [128][4]
#pragma unroll
        for (int mi = 0; mi < 4; mi++) {
#pragma unroll
            for (int half = 0; half < 2; half++) {
                float v = ss[mi][half];
                v += __shfl_xor_sync(0xffffffffu, v, 1);
                v += __shfl_xor_sync(0xffffffffu, v, 2);
                if (tg == 0) {
                    int rl = warp_m + mi * 16 + half * 8 + g;
                    red[rl * 4 + (wid >> 1)] = v;
                }
            }
        }
        __syncthreads();
        if (tid < 128) {
            float tot = red[tid * 4] + red[tid * 4 + 1] + red[tid * 4 + 2] + red[tid * 4 + 3];
            rowss[blockIdx.x * NTOK + blockIdx.y * 128 + tid] = tot;
        }
    }
}

// ============================================================
// Gate GEMM (N = 32) with FUSED finish, 6-stage pipeline.
// ============================================================
__device__ __forceinline__ void load_slab_h32(char* smem, int stage,
                                              const __half* gA, const __half* gB,
                                              int k0, int K, int tid) {
    constexpr int STAGE = (128 + 32) * 64;
    uint32_t base = smem_u32(smem) + stage * STAGE;
#pragma unroll
    for (int i = 0; i < 2; i++) {
        int idx = tid + i * 256;
        int row = idx >> 2, c = idx & 3;
        cp16(base + (uint32_t)(row * 64 + c * 16),
             gA + (size_t)row * K + k0 + c * 8);
    }
    uint32_t bb = base + 128 * 64;
    if (tid < 128) {
        int row = tid >> 2, c = tid & 3;
        cp16(bb + (uint32_t)(row * 64 + c * 16),
             gB + (size_t)row * K + k0 + c * 8);
    }
}

__global__ __launch_bounds__(256) void hgemm_gate(
    const __half* __restrict__ A, const __half* __restrict__ B,
    const float* __restrict__ b1, const float* __restrict__ gain,
    const float* __restrict__ beta, const float* __restrict__ w2,
    const float* __restrict__ b2, float* __restrict__ pinit,
    float scale, int K)
{
    extern __shared__ char smem[];
    constexpr int STAGE = (128 + 32) * 64;

    const int tid = threadIdx.x, wid = tid >> 5, lane = tid & 31;
    const int warp_m = wid * 16;
    const int gg2 = lane >> 2, tg = lane & 3;

    const __half* gA = A + (size_t)blockIdx.y * 128 * K;
    const __half* gB = B;
    const int NS = K >> 5;

    float acc[4][4] = {};

#pragma unroll
    for (int s = 0; s < 5; s++) {
        load_slab_h32(smem, s, gA, gB, s * 32, K, tid);
        cp_commit();
    }

    for (int ks = 0; ks < NS; ks++) {
        if (ks + 5 < NS) {
            load_slab_h32(smem, (ks + 5) % 6, gA, gB, (ks + 5) * 32, K, tid);
            cp_commit();
        }
        int rem = NS - 1 - ks;
        if (rem >= 5) cp_wait<5>();
        else if (rem == 4) cp_wait<4>();
        else if (rem == 3) cp_wait<3>();
        else if (rem == 2) cp_wait<2>();
        else if (rem == 1) cp_wait<1>();
        else cp_wait<0>();
        __syncthreads();

        const __half* As = (const __half*)(smem + (size_t)(ks % 6) * STAGE);
        const __half* Bs = As + 128 * 32;

        uint4 alo = *(const uint4*)(As + (warp_m + gg2) * 32 + 8 * tg);
        uint4 ahi = *(const uint4*)(As + (warp_m + 8 + gg2) * 32 + 8 * tg);
        uint4 bq[4];
#pragma unroll
        for (int ni = 0; ni < 4; ni++)
            bq[ni] = *(const uint4*)(Bs + (ni * 8 + gg2) * 32 + 8 * tg);
#pragma unroll
        for (int ni = 0; ni < 4; ni++) {
            MMA_F16(acc[ni], alo.x, ahi.x, alo.y, ahi.y, bq[ni].x, bq[ni].y);
            MMA_F16(acc[ni], alo.z, ahi.z, alo.w, ahi.w, bq[ni].z, bq[ni].w);
        }
        __syncthreads();
    }

#pragma unroll
    for (int half = 0; half < 2; half++) {
        float vv[8];
        float sum = 0.f;
#pragma unroll
        for (int ni = 0; ni < 4; ni++) {
#pragma unroll
            for (int j = 0; j < 2; j++) {
                int col = ni * 8 + 2 * tg + j;
                float v = acc[ni][half * 2 + j] + b1[col];
                vv[ni * 2 + j] = v;
                sum += v;
            }
        }
        sum += __shfl_xor_sync(0xffffffffu, sum, 1);
        sum += __shfl_xor_sync(0xffffffffu, sum, 2);
        float m = sum * (1.f / 32.f);
        float s2 = 0.f;
#pragma unroll
        for (int q = 0; q < 8; q++) { float d = vv[q] - m; s2 += d * d; }
        s2 += __shfl_xor_sync(0xffffffffu, s2, 1);
        s2 += __shfl_xor_sync(0xffffffffu, s2, 2);
        float inv = rsqrtf(s2 * (1.f / 32.f) + 1e-5f);
        float p = 0.f;
#pragma unroll
        for (int ni = 0; ni < 4; ni++) {
#pragma unroll
            for (int j = 0; j < 2; j++) {
                int col = ni * 8 + 2 * tg + j;
                float tn = (vv[ni * 2 + j] - m) * inv * gain[col] + beta[col];
                float si = tn / (1.f + expf(-tn));
                p += si * w2[col];
            }
        }
        p += __shfl_xor_sync(0xffffffffu, p, 1);
        p += __shfl_xor_sync(0xffffffffu, p, 2);
        if (tg == 0) {
            int row = blockIdx.y * 128 + warp_m + half * 8 + gg2;
            pinit[row] = scale / (1.f + expf(-(p + b2[0])));
        }
    }
}

// ============================================================
// PREP megakernel (job table). All blocks 256 threads.
// ============================================================
__device__ __forceinline__ void transpose_tile(const float* in, __half* out,
                                               int R, int C, int lb, int tid) {
    __shared__ float t[32][33];
    int nbx = C >> 5;
    int bx = lb % nbx, by = lb / nbx;
    int c0 = bx * 32, r0 = by * 32;
    int x = tid & 31, y = tid >> 5;
#pragma unroll
    for (int dy = 0; dy < 32; dy += 8)
        t[y + dy][x] = in[(size_t)(r0 + y + dy) * C + c0 + x];
    __syncthreads();
#pragma unroll
    for (int dy = 0; dy < 32; dy += 8)
        out[(size_t)(c0 + y + dy) * R + kperm(r0 + x)] = __float2half_rn(t[x][y + dy]);
}

__global__ void prep_kernel(
    const float* __restrict__ Wr, const float* __restrict__ Wi,
    const float* __restrict__ uw1, const float* __restrict__ ow,
    const float* __restrict__ fw1, const float* __restrict__ fw2,
    const float* __restrict__ values,
    const float* __restrict__ mr, const float* __restrict__ mi,
    const float* __restrict__ br, const float* __restrict__ bi,
    __half* __restrict__ WT16, __half* __restrict__ uw1T16,
    __half* __restrict__ owT16, __half* __restrict__ fw1T16,
    __half* __restrict__ fw2T16, __half* __restrict__ val16,
    __half* __restrict__ Mp16, float* __restrict__ bc)
{
    int b = blockIdx.x, tid = threadIdx.x;
    if (b < 256) { transpose_tile(Wr, WT16, DIM, DH, b, tid); return; }
    b -= 256;
    if (b < 256) { transpose_tile(Wi, WT16 + 256 * DIM, DIM, DH, b, tid); return; }
    b -= 256;
    if (b < 32)  { transpose_tile(uw1, uw1T16, DIM, HIDN, b, tid); return; }
    b -= 32;
    if (b < 1024){ transpose_tile(ow, owT16, DIM, DIM, b, tid); return; }
    b -= 1024;
    if (b < 4096){ transpose_tile(fw1, fw1T16, DIM, DFF, b, tid); return; }
    b -= 4096;
    if (b < 4096){ transpose_tile(fw2, fw2T16, DFF, DIM, b, tid); return; }
    b -= 4096;
    if (b < 256) {
        int i = (b * 256 + tid) * 4;
        float4 v = *(const float4*)(values + i);
        int p0 = kperm(i);
        *(__half2*)(val16 + p0) = __floats2half2_rn(v.x, v.y);
        *(__half2*)(val16 + p0 + 8) = __floats2half2_rn(v.z, v.w);
        return;
    }
    b -= 256;
    if (b < 256) {
        // memnorm -> INTERLEAVED Mp: row 2s = [Mr|Mi], row 2s+1 = [Mi|-Mr]
        int s = b, d = tid;
        float a = mr[s * DH + d], bb2 = mi[s * DH + d];
        float tot = block_sum_256(a * a + bb2 * bb2);
        float inv = 1.f / fmaxf(sqrtf(tot), 1e-12f);
        float ra = a * inv, rb = bb2 * inv;
        Mp16[(size_t)(2 * s) * 512 + kperm(d)] = __float2half_rn(ra);
        Mp16[(size_t)(2 * s) * 512 + kperm(256 + d)] = __float2half_rn(rb);
        Mp16[(size_t)(2 * s + 1) * 512 + kperm(d)] = __float2half_rn(rb);
        Mp16[(size_t)(2 * s + 1) * 512 + kperm(256 + d)] = __float2half_rn(-ra);
        return;
    }
    {
        bc[tid] = br[tid];
        bc[256 + tid] = bi[tid];
    }
}
#define PREP_BLOCKS (256 + 256 + 32 + 1024 + 4096 + 4096 + 256 + 256 + 1)

// ---------------- elementwise kernels ----------------
// ctx partials (32-row chunks) + h -> h16 (kperm'd), vectorized.
__global__ void ctx_partial_cvt_kernel(const float* __restrict__ h,
                                       float* __restrict__ part,
                                       __half* __restrict__ h16) {
    int tid = threadIdx.x;
    int d0 = tid * 4;
    int b = blockIdx.y, c = blockIdx.z;
    int p0 = kperm(d0);
    size_t row0 = (size_t)b * NSEQ + c * 32;
    const float* base = h + row0 * DIM;
    float s0 = 0.f, s1 = 0.f, s2 = 0.f, s3 = 0.f;
#pragma unroll 4
    for (int n = 0; n < 32; n++) {
        float4 v = *(const float4*)(base + (size_t)n * DIM + d0);
        s0 += v.x; s1 += v.y; s2 += v.z; s3 += v.w;
        __half* hr = h16 + (row0 + n) * DIM;
        *(__half2*)(hr + p0) = __floats2half2_rn(v.x, v.y);
        *(__half2*)(hr + p0 + 8) = __floats2half2_rn(v.z, v.w);
    }
    *(float4*)(part + (size_t)(b * 128 + c) * DIM + d0) = make_float4(s0, s1, s2, s3);
}

// fused: ctx mean + full gamma gate. grid = BB, block = 1024.
__global__ __launch_bounds__(1024) void ctxgate_kernel(
    const float* __restrict__ part,
    const float* __restrict__ w1, const float* __restrict__ b1,
    const float* __restrict__ gain, const float* __restrict__ beta,
    const float* __restrict__ w2, const float* __restrict__ b2,
    float* __restrict__ gamma)
{
    __shared__ float cs[DIM];
    __shared__ float tj[HIDN];
    int b = blockIdx.x, tid = threadIdx.x;
    int w = tid >> 5, l = tid & 31;

    float s = 0.f;
#pragma unroll
    for (int c = 0; c < 128; c++) s += part[(size_t)(b * 128 + c) * DIM + tid];
    cs[tid] = s * (1.f / (float)NSEQ);
    __syncthreads();

    float acc = 0.f;
#pragma unroll 8
    for (int it = 0; it < DIM / 32; it++) {
        int d = l + it * 32;
        acc += cs[d] * w1[d * HIDN + w];
    }
#pragma unroll
    for (int o = 16; o; o >>= 1) acc += __shfl_xor_sync(0xffffffffu, acc, o);
    if (l == 0) tj[w] = acc + b1[w];
    __syncthreads();

    if (tid < HIDN) {
        float v = tj[tid];
        float m = v;
#pragma unroll
        for (int o = 16; o; o >>= 1) m += __shfl_xor_sync(0xffffffffu, m, o);
        m *= (1.f / 32.f);
        float d = v - m;
        float var = d * d;
#pragma unroll
        for (int o = 16; o; o >>= 1) var += __shfl_xor_sync(0xffffffffu, var, o);
        var *= (1.f / 32.f);
        float tn = d * rsqrtf(var + 1e-5f) * gain[tid] + beta[tid];
        float si = tn / (1.f + expf(-tn));
        float p = si * w2[tid];
#pragma unroll
        for (int o = 16; o; o >>= 1) p += __shfl_xor_sync(0xffffffffu, p, o);
        if (tid == 0) gamma[b] = 1.f / (1.f + expf(-(p + b2[0])));
    }
}

// combine 4 split-K partials -> fp16 kperm'd VOT
__global__ void cvt_vot_kernel(const float* __restrict__ part, __half* __restrict__ out) {
    int i = (blockIdx.x * 256 + threadIdx.x) * 4;
    const int SZ = DIM * SS;
    float4 a = *(const float4*)(part + i);
    float4 b = *(const float4*)(part + SZ + i);
    float4 c = *(const float4*)(part + 2 * SZ + i);
    float4 d = *(const float4*)(part + 3 * SZ + i);
    float x = a.x + b.x + c.x + d.x;
    float y = a.y + b.y + c.y + d.y;
    float z = a.z + b.z + c.z + d.z;
    float w = a.w + b.w + c.w + d.w;
    int p0 = kperm(i);
    *(__half2*)(out + p0) = __floats2half2_rn(x, y);
    *(__half2*)(out + p0 + 8) = __floats2half2_rn(z, w);
}

// colsum of VOT: S[d] = sum_s VOT[d,s] (perm-invariant). grid 4 x 256.
__global__ void votsum_kernel(const __half* __restrict__ VOT16, float* __restrict__ S) {
    int d = blockIdx.x * 256 + threadIdx.x;
    const __half2* r = (const __half2*)(VOT16 + (size_t)d * SS);
    float s = 0.f;
#pragma unroll 8
    for (int i = 0; i < SS / 2; i++) {
        float2 v = __half22float2(r[i]);
        s += v.x + v.y;
    }
    S[d] = s;
}

// per-row attention affine factors: alpha = c1/D, beta = c0/D
__global__ void rowfac_kernel(const float* __restrict__ pinit, const float* __restrict__ gamma,
                              const float* __restrict__ rowssp, const float* __restrict__ ovsump,
                              float* __restrict__ alpha, float* __restrict__ beta) {
    int row = blockIdx.x * 256 + threadIdx.x;
    int b = row >> 12;
    float p = pinit[row] * (1.f - gamma[b]);
    float n2 = fmaxf(rowssp[row] + rowssp[NTOK + row], 1e-24f);
    float ovs = ovsump[row] + ovsump[NTOK + row];
    float c1 = (1.f - p) / n2;
    float c0 = p * (1.f / (float)DH);
    float D = c1 * ovs + (float)SS * c0 + 1e-8f;
    alpha[row] = c1 / D;
    beta[row] = c0 / D;
}

// mid LN: h1 = LN(h16 + ao16); writes ONLY fp16 kperm'd copy
__global__ void ln_add_mid_kernel(const __half* __restrict__ a, const __half* __restrict__ bsrc,
                                  const float* __restrict__ g, const float* __restrict__ beta,
                                  __half* __restrict__ outr) {
    size_t off = (size_t)blockIdx.x * DIM;
    int tid = threadIdx.x;
    float v[4];
    float s = 0.f;
#pragma unroll
    for (int q = 0; q < 4; q++) {
        int i = tid + q * 256;
        v[q] = __half2float(a[off + kperm(i)]) + __half2float(bsrc[off + i]);
        s += v[q];
    }
    float mu = block_sum_256(s) * (1.f / (float)DIM);
    float s2 = 0.f;
#pragma unroll
    for (int q = 0; q < 4; q++) {
        float d = v[q] - mu;
        s2 += d * d;
    }
    float var = block_sum_256(s2) * (1.f / (float)DIM);
    float inv = rsqrtf(var + 1e-5f);
#pragma unroll
    for (int q = 0; q < 4; q++) {
        int i = tid + q * 256;
        float o = (v[q] - mu) * inv * g[i] + beta[i];
        outr[off + kperm(i)] = __float2half_rn(o);
    }
}

// final LN: out = LN(h1r16[kperm] + ff216)
__global__ void ln_add_final_kernel(const __half* __restrict__ a, const __half* __restrict__ bsrc,
                                    const float* __restrict__ g, const float* __restrict__ beta,
                                    float* __restrict__ out) {
    size_t off = (size_t)blockIdx.x * DIM;
    int tid = threadIdx.x;
    float v[4];
    float s = 0.f;
#pragma unroll
    for (int q = 0; q < 4; q++) {
        int i = tid + q * 256;
        v[q] = __half2float(a[off + kperm(i)]) + __half2float(bsrc[off + i]);
        s += v[q];
    }
    float mu = block_sum_256(s) * (1.f / (float)DIM);
    float s2 = 0.f;
#pragma unroll
    for (int q = 0; q < 4; q++) {
        float d = v[q] - mu;
        s2 += d * d;
    }
    float var = block_sum_256(s2) * (1.f / (float)DIM);
    float inv = rsqrtf(var + 1e-5f);
#pragma unroll
    for (int q = 0; q < 4; q++) {
        int i = tid + q * 256;
        out[off + i] = (v[q] - mu) * inv * g[i] + beta[i];
    }
}

// ---------------- launch ----------------
static inline void* symv(const void* s) {
    void* p = nullptr;
    cudaGetSymbolAddress(&p, s);
    return p;
}

extern "C" void kernel_launch(void* const* d_in, const int* in_sizes, int n_in,
                              void* d_out, int out_size) {
    const float* h     = (const float*)d_in[0];
    const float* Wr    = (const float*)d_in[1];
    const float* br    = (const float*)d_in[2];
    const float* Wi    = (const float*)d_in[3];
    const float* bi    = (const float*)d_in[4];
    const float* uw1   = (const float*)d_in[5];
    const float* ub1   = (const float*)d_in[6];
    const float* ug    = (const float*)d_in[7];
    const float* ubeta = (const float*)d_in[8];
    const float* uw2   = (const float*)d_in[9];
    const float* ub2   = (const float*)d_in[10];
    const float* gw1   = (const float*)d_in[11];
    const float* gb1   = (const float*)d_in[12];
    const float* gg    = (const float*)d_in[13];
    const float* gbeta = (const float*)d_in[14];
    const float* gw2   = (const float*)d_in[15];
    const float* gb2   = (const float*)d_in[16];
    const float* m_real= (const float*)d_in[17];
    const float* m_imag= (const float*)d_in[18];
    const float* values= (const float*)d_in[19];
    const float* ow    = (const float*)d_in[20];
    const float* ob    = (const float*)d_in[21];
    const float* n1g   = (const float*)d_in[22];
    const float* n1b   = (const float*)d_in[23];
    const float* n2g   = (const float*)d_in[24];
    const float* n2b   = (const float*)d_in[25];
    const float* fw1   = (const float*)d_in[26];
    const float* fb1   = (const float*)d_in[27];
    const float* fw2   = (const float*)d_in[28];
    const float* fb2   = (const float*)d_in[29];
    float* out = (float*)d_out;

    float* pinit = (float*)symv(g_pinit);
    float* gam   = (float*)symv(g_gamma);
    float* ctxp  = (float*)symv(g_ctxpart);
    float* rowssp= (float*)symv(g_rowsspart);
    float* ovsump= (float*)symv(g_ovsump);
    float* alpha = (float*)symv(g_alpha);
    float* beta  = (float*)symv(g_beta);
    float* votS  = (float*)symv(g_votS);
    float* bc    = (float*)symv(g_bc);
    float* VOTp  = (float*)symv(g_VOTpart);
    __half* h16    = (__half*)symv(g_h16);
    __half* psi16  = (__half*)symv(g_psi16);
    __half* ov16   = (__half*)symv(g_ov16);
    __half* h1r16  = (__half*)symv(g_h1r16);
    __half* ff116  = (__half*)symv(g_ff116);
    __half* ao16   = (__half*)symv(g_ao16);
    __half* ff216  = (__half*)symv(g_ff216);
    __half* WT16   = (__half*)symv(g_WT16);
    __half* uw1T16 = (__half*)symv(g_uw1T16);
    __half* Mp16   = (__half*)symv(g_Mp16);
    __half* owT16  = (__half*)symv(g_owT16);
    __half* val16  = (__half*)symv(g_val16);
    __half* VOT16  = (__half*)symv(g_VOT16);
    __half* fw1T16 = (__half*)symv(g_fw1T16);
    __half* fw2T16 = (__half*)symv(g_fw2T16);

    const int smBIG  = (128 + 256) * 64 * 4;   // 98304
    const int smBIG1 = (128 + 128) * 64 * 4;   // 65536
    const int smGATE = (128 + 32) * 64 * 6;    // 61440
    cudaFuncSetAttribute(hgemm_big<256, false, 1, true >, cudaFuncAttributeMaxDynamicSharedMemorySize, smBIG);
    cudaFuncSetAttribute(hgemm_big<256, false, 3, false>, cudaFuncAttributeMaxDynamicSharedMemorySize, smBIG);
    cudaFuncSetAttribute(hgemm_big<256, false, 4, true >, cudaFuncAttributeMaxDynamicSharedMemorySize, smBIG);
    cudaFuncSetAttribute(hgemm_big<256, false, 5, false>, cudaFuncAttributeMaxDynamicSharedMemorySize, smBIG);
    cudaFuncSetAttribute(hgemm_big<256, true,  1, false>, cudaFuncAttributeMaxDynamicSharedMemorySize, smBIG);
    cudaFuncSetAttribute(hgemm_big<128, false, 2, false>, cudaFuncAttributeMaxDynamicSharedMemorySize, smBIG1);
    cudaFuncSetAttribute(hgemm_gate, cudaFuncAttributeMaxDynamicSharedMemorySize, smGATE);

    // fork-join streams/events (created once, outside capture on first call)
    static cudaStream_t s1 = nullptr, s2 = nullptr;
    static cudaEvent_t evEntry = nullptr, evPrep = nullptr, evCtx = nullptr,
                       evGate = nullptr, evVot = nullptr;
    if (!s1) {
        cudaStreamCreateWithFlags(&s1, cudaStreamNonBlocking);
        cudaStreamCreateWithFlags(&s2, cudaStreamNonBlocking);
        cudaEventCreateWithFlags(&evEntry, cudaEventDisableTiming);
        cudaEventCreateWithFlags(&evPrep, cudaEventDisableTiming);
        cudaEventCreateWithFlags(&evCtx, cudaEventDisableTiming);
        cudaEventCreateWithFlags(&evGate, cudaEventDisableTiming);
        cudaEventCreateWithFlags(&evVot, cudaEventDisableTiming);
    }

    dim3 thr(256);

    // fork s2: weight prep + VOT chain + colsum
    cudaEventRecord(evEntry, 0);
    cudaStreamWaitEvent(s2, evEntry, 0);
    prep_kernel<<<PREP_BLOCKS, thr, 0, s2>>>(Wr, Wi, uw1, ow, fw1, fw2, values,
                                             m_real, m_imag, br, bi,
                                             WT16, uw1T16, owT16, fw1T16, fw2T16,
                                             val16, Mp16, bc);
    cudaEventRecord(evPrep, s2);
    hgemm_big<256, false, 3, false><<<dim3(1, 8, 4), thr, smBIG, s2>>>(
        owT16, val16, nullptr, VOTp, nullptr, nullptr, nullptr, nullptr,
        DIM, SS, (size_t)DIM * SS);
    cvt_vot_kernel<<<DIM * SS / 1024, thr, 0, s2>>>(VOTp, VOT16);
    votsum_kernel<<<DIM / 256, thr, 0, s2>>>(VOT16, votS);
    cudaEventRecord(evVot, s2);

    // main: ctx partials + h -> h16 (overlaps prep)
    ctx_partial_cvt_kernel<<<dim3(1, BB, 128), thr>>>(h, ctxp, h16);
    cudaEventRecord(evCtx, 0);

    // s1: gamma gate + uncertainty gate (overlap psi/reim on main)
    cudaStreamWaitEvent(s1, evCtx, 0);
    cudaStreamWaitEvent(s1, evPrep, 0);
    ctxgate_kernel<<<BB, 1024, 0, s1>>>(ctxp, gw1, gb1, gg, gbeta, gw2, gb2, gam);
    hgemm_gate<<<dim3(1, 128), thr, smGATE, s1>>>(h16, uw1T16, ub1, ug, ubeta, uw2, ub2,
                                                  pinit, 0.95f, DIM);
    cudaEventRecord(evGate, s1);

    // main: psi (kperm'd + rowss partials) -> ov (overlap + ovsum partials)
    cudaStreamWaitEvent(0, evPrep, 0);
    hgemm_big<256, false, 1, true><<<dim3(2, 128), thr, smBIG>>>(
        h16, WT16, bc, psi16, rowssp, nullptr, nullptr, nullptr, DIM, 512, 0);
    hgemm_big<256, false, 4, true><<<dim3(2, 128), thr, smBIG>>>(
        psi16, Mp16, nullptr, ov16, ovsump, nullptr, nullptr, nullptr, 512, SS, 0);

    // join gate, then per-row attention factors
    cudaStreamWaitEvent(0, evGate, 0);
    rowfac_kernel<<<NTOK / 256, thr>>>(pinit, gam, rowssp, ovsump, alpha, beta);

    // join VOT, then ao = alpha*(ov @ VOT^T) + beta*S + ob   (fp16 plain)
    cudaStreamWaitEvent(0, evVot, 0);
    hgemm_big<256, false, 5, false><<<dim3(4, 128), thr, smBIG>>>(
        ov16, VOT16, ob, ao16, nullptr, alpha, beta, votS, SS, DIM, 0);

    // h1 = LN(h16 + ao16) -> fp16 kperm'd only
    ln_add_mid_kernel<<<NTOK, 256>>>(h16, ao16, n1g, n1b, h1r16);

    // FFN
    hgemm_big<256, true, 1, false><<<dim3(16, 128), thr, smBIG>>>(
        h1r16, fw1T16, fb1, ff116, nullptr, nullptr, nullptr, nullptr, DIM, DFF, 0);
    hgemm_big<128, false, 2, false><<<dim3(8, 128), thr, smBIG1>>>(
        ff116, fw2T16, fb2, ff216, nullptr, nullptr, nullptr, nullptr, DFF, DIM, 0);

    // out = LN(h1 + ff2)
    ln_add_final_kernel<<<NTOK, 256>>>(h1r16, ff216, n2g, n2b, out);
}